// round 10
// baseline (speedup 1.0000x reference)
#include <cuda_runtime.h>
#include <cuda_bf16.h>
#include <math.h>
#include <stdint.h>

#define NBATCH 2
#define SEQ 2048
#define EMBD 1024
#define NHEAD 16
#define HDIM 64
#define ATT_SCALE 0.03125f
#define SKW 72                    // bf16 smem row stride: 16B-aligned, ldmatrix conflict-free

// scratch
__device__ float g_v[(size_t)NBATCH * NHEAD * SEQ * HDIM];            // fp32 V (colsum source)
__device__ float g_sv4[(size_t)NBATCH * NHEAD * 4 * HDIM];            // partial masked colsums
__device__ float g_mcnt[(size_t)NBATCH * NHEAD * 4];                  // partial mask counts
__device__ __nv_bfloat16 g_qbf[(size_t)NBATCH * NHEAD * SEQ * HDIM];  // pre-scaled by 1/32
__device__ __nv_bfloat16 g_kbf[(size_t)NBATCH * NHEAD * SEQ * HDIM];  // pre-masked (k * mask)
__device__ __nv_bfloat16 g_vbf[(size_t)NBATCH * NHEAD * SEQ * HDIM];
__device__ __nv_bfloat16 g_ahi[(size_t)NBATCH * SEQ * EMBD];
__device__ __nv_bfloat16 g_alo[(size_t)NBATCH * SEQ * EMBD];
__device__ __nv_bfloat16 g_whi[(size_t)EMBD * EMBD];
__device__ __nv_bfloat16 g_wlo[(size_t)EMBD * EMBD];

// ===================== helpers =====================
__device__ __forceinline__ uint32_t smem_u32(const void* p) {
    uint32_t a;
    asm("{ .reg .u64 t; cvta.to.shared.u64 t, %1; cvt.u32.u64 %0, t; }" : "=r"(a) : "l"(p));
    return a;
}
__device__ __forceinline__ void cp16(uint32_t s, const void* g) {
    asm volatile("cp.async.ca.shared.global [%0], [%1], 16;" :: "r"(s), "l"(g));
}
#define CP_COMMIT() asm volatile("cp.async.commit_group;" ::: "memory")
#define CP_WAIT(n)  asm volatile("cp.async.wait_group %0;" :: "n"(n) : "memory")

__device__ __forceinline__ void mma_bf16(float* c, uint32_t a0, uint32_t a1, uint32_t a2, uint32_t a3,
                                         uint32_t b0, uint32_t b1) {
    asm volatile("mma.sync.aligned.m16n8k16.row.col.f32.bf16.bf16.f32 "
                 "{%0,%1,%2,%3}, {%4,%5,%6,%7}, {%8,%9}, {%0,%1,%2,%3};"
                 : "+f"(c[0]), "+f"(c[1]), "+f"(c[2]), "+f"(c[3])
                 : "r"(a0), "r"(a1), "r"(a2), "r"(a3), "r"(b0), "r"(b1));
}
__device__ __forceinline__ void ldm4(uint32_t& r0, uint32_t& r1, uint32_t& r2, uint32_t& r3, uint32_t a) {
    asm volatile("ldmatrix.sync.aligned.m8n8.x4.shared.b16 {%0,%1,%2,%3}, [%4];"
                 : "=r"(r0), "=r"(r1), "=r"(r2), "=r"(r3) : "r"(a));
}
__device__ __forceinline__ void ldm4t(uint32_t& r0, uint32_t& r1, uint32_t& r2, uint32_t& r3, uint32_t a) {
    asm volatile("ldmatrix.sync.aligned.m8n8.x4.trans.shared.b16 {%0,%1,%2,%3}, [%4];"
                 : "=r"(r0), "=r"(r1), "=r"(r2), "=r"(r3) : "r"(a));
}
__device__ __forceinline__ uint32_t f2bf2(float lo, float hi) {
    uint32_t u;
    asm("cvt.rn.bf16x2.f32 %0, %1, %2;" : "=r"(u) : "f"(hi), "f"(lo));
    return u;
}

// ---------------------------------------------------------------------------
// Kernel 1: projections via HMMA (3-way bf16 split). 128 rows x one head/block.
// k output is pre-multiplied by the attention mask (masked keys -> 0 -> delta 0).
// ---------------------------------------------------------------------------
#define P_XH 0
#define P_XL 18432
#define P_WH 36864
#define P_WL 46080
#define P_TOTAL 55296

__device__ __forceinline__ void proj_load_x(char* smc, const float* __restrict__ x, int t) {
    for (int i = t; i < 2048; i += 256) {
        int r = i >> 4, c4 = (i & 15) * 4;
        float4 v = *(const float4*)(x + (size_t)r * EMBD + c4);
        uint32_t h01 = f2bf2(v.x, v.y), h23 = f2bf2(v.z, v.w);
        float r0 = v.x - __uint_as_float(h01 << 16);
        float r1 = v.y - __uint_as_float(h01 & 0xffff0000u);
        float r2 = v.z - __uint_as_float(h23 << 16);
        float r3 = v.w - __uint_as_float(h23 & 0xffff0000u);
        uint32_t so = (uint32_t)((r * SKW + c4) * 2);
        *(uint2*)(smc + P_XH + so) = make_uint2(h01, h23);
        *(uint2*)(smc + P_XL + so) = make_uint2(f2bf2(r0, r1), f2bf2(r2, r3));
    }
}
__device__ __forceinline__ void proj_load_w(char* smc, const float* __restrict__ W, int t) {
    for (int i = t; i < 1024; i += 256) {
        int r = i >> 4, c4 = (i & 15) * 4;
        float4 v = *(const float4*)(W + r * 64 + c4);
        uint32_t h01 = f2bf2(v.x, v.y), h23 = f2bf2(v.z, v.w);
        float r0 = v.x - __uint_as_float(h01 << 16);
        float r1 = v.y - __uint_as_float(h01 & 0xffff0000u);
        float r2 = v.z - __uint_as_float(h23 << 16);
        float r3 = v.w - __uint_as_float(h23 & 0xffff0000u);
        uint32_t so = (uint32_t)((r * SKW + c4) * 2);
        *(uint2*)(smc + P_WH + so) = make_uint2(h01, h23);
        *(uint2*)(smc + P_WL + so) = make_uint2(f2bf2(r0, r1), f2bf2(r2, r3));
    }
}
__device__ __forceinline__ void proj_mm(uint32_t sb, int wr, int lane, float (&c)[8][4]) {
    const uint32_t arow = (uint32_t)(wr + (lane & 7) + ((lane & 8) ? 8 : 0));
    const uint32_t acs = (lane & 16) ? 8u : 0u;
    const uint32_t brow = (uint32_t)(((lane & 16) ? 8 : 0) + (lane & 7));
    const uint32_t bcs = (lane & 8) ? 8u : 0u;
    #pragma unroll
    for (int kk = 0; kk < 4; kk++) {
        uint32_t xh[4], xl[4];
        ldm4(xh[0], xh[1], xh[2], xh[3], sb + P_XH + (arow * SKW + kk * 16 + acs) * 2);
        ldm4(xl[0], xl[1], xl[2], xl[3], sb + P_XL + (arow * SKW + kk * 16 + acs) * 2);
        #pragma unroll
        for (int p = 0; p < 4; p++) {
            uint32_t off = ((p * 16 + brow) * SKW + kk * 16 + bcs) * 2;
            uint32_t bh0, bh1, bh2, bh3, bl0, bl1, bl2, bl3;
            ldm4(bh0, bh1, bh2, bh3, sb + P_WH + off);
            ldm4(bl0, bl1, bl2, bl3, sb + P_WL + off);
            mma_bf16(c[2 * p],     xh[0], xh[1], xh[2], xh[3], bh0, bh1);
            mma_bf16(c[2 * p],     xh[0], xh[1], xh[2], xh[3], bl0, bl1);
            mma_bf16(c[2 * p],     xl[0], xl[1], xl[2], xl[3], bh0, bh1);
            mma_bf16(c[2 * p + 1], xh[0], xh[1], xh[2], xh[3], bh2, bh3);
            mma_bf16(c[2 * p + 1], xh[0], xh[1], xh[2], xh[3], bl2, bl3);
            mma_bf16(c[2 * p + 1], xl[0], xl[1], xl[2], xl[3], bh2, bh3);
        }
    }
}
__device__ __forceinline__ void proj_mm_regA(uint32_t sb, int lane,
                                             const uint32_t (&ah)[4][4], const uint32_t (&al)[4][4],
                                             float (&c)[8][4]) {
    const uint32_t brow = (uint32_t)(((lane & 16) ? 8 : 0) + (lane & 7));
    const uint32_t bcs = (lane & 8) ? 8u : 0u;
    #pragma unroll
    for (int kk = 0; kk < 4; kk++) {
        #pragma unroll
        for (int p = 0; p < 4; p++) {
            uint32_t off = ((p * 16 + brow) * SKW + kk * 16 + bcs) * 2;
            uint32_t bh0, bh1, bh2, bh3, bl0, bl1, bl2, bl3;
            ldm4(bh0, bh1, bh2, bh3, sb + P_WH + off);
            ldm4(bl0, bl1, bl2, bl3, sb + P_WL + off);
            mma_bf16(c[2 * p],     ah[kk][0], ah[kk][1], ah[kk][2], ah[kk][3], bh0, bh1);
            mma_bf16(c[2 * p],     ah[kk][0], ah[kk][1], ah[kk][2], ah[kk][3], bl0, bl1);
            mma_bf16(c[2 * p],     al[kk][0], al[kk][1], al[kk][2], al[kk][3], bh0, bh1);
            mma_bf16(c[2 * p + 1], ah[kk][0], ah[kk][1], ah[kk][2], ah[kk][3], bh2, bh3);
            mma_bf16(c[2 * p + 1], ah[kk][0], ah[kk][1], ah[kk][2], ah[kk][3], bl2, bl3);
            mma_bf16(c[2 * p + 1], al[kk][0], al[kk][1], al[kk][2], al[kk][3], bh2, bh3);
        }
    }
}

__global__ __launch_bounds__(256, 2) void proj_hmma(
    const float* __restrict__ keys, const float* __restrict__ queries,
    const float* __restrict__ Wk, const float* __restrict__ Wq, const float* __restrict__ Wv,
    const int* __restrict__ mask)
{
    extern __shared__ char smc[];
    const uint32_t sb = smem_u32(smc);
    const int t = threadIdx.x, w = t >> 5, lane = t & 31;
    const int grow = lane >> 2, qr = lane & 3;
    const int wr = w * 16;
    const int n = blockIdx.z, h = blockIdx.y, l0 = blockIdx.x * 128;
    const size_t hb = ((size_t)(n * NHEAD + h) * SEQ + l0) * HDIM;
    const float* xq = queries + ((size_t)n * SEQ + l0) * EMBD + h * HDIM;
    const float* xk = keys    + ((size_t)n * SEQ + l0) * EMBD + h * HDIM;

    // ---- q ----
    proj_load_x(smc, xq, t);
    proj_load_w(smc, Wq, t);
    __syncthreads();
    float c[8][4];
    #pragma unroll
    for (int i = 0; i < 8; i++)
        #pragma unroll
        for (int j = 0; j < 4; j++) c[i][j] = 0.0f;
    proj_mm(sb, wr, lane, c);
    __syncthreads();

    uint32_t qh[4][4], ql[4][4];
    #pragma unroll
    for (int nt = 0; nt < 8; nt++) {
        uint32_t h0 = f2bf2(c[nt][0], c[nt][1]);
        uint32_t h1 = f2bf2(c[nt][2], c[nt][3]);
        float r0 = c[nt][0] - __uint_as_float(h0 << 16);
        float r1 = c[nt][1] - __uint_as_float(h0 & 0xffff0000u);
        float r2 = c[nt][2] - __uint_as_float(h1 << 16);
        float r3 = c[nt][3] - __uint_as_float(h1 & 0xffff0000u);
        qh[nt >> 1][(nt & 1) * 2 + 0] = h0;
        qh[nt >> 1][(nt & 1) * 2 + 1] = h1;
        ql[nt >> 1][(nt & 1) * 2 + 0] = f2bf2(r0, r1);
        ql[nt >> 1][(nt & 1) * 2 + 1] = f2bf2(r2, r3);
        int col = nt * 8 + qr * 2;
        *(uint32_t*)(g_qbf + hb + (size_t)(wr + grow) * HDIM + col) =
            f2bf2(c[nt][0] * ATT_SCALE, c[nt][1] * ATT_SCALE);
        *(uint32_t*)(g_qbf + hb + (size_t)(wr + grow + 8) * HDIM + col) =
            f2bf2(c[nt][2] * ATT_SCALE, c[nt][3] * ATT_SCALE);
    }

    // ---- k (pre-masked) ----
    proj_load_x(smc, xk, t);
    proj_load_w(smc, Wk, t);
    __syncthreads();
    #pragma unroll
    for (int i = 0; i < 8; i++)
        #pragma unroll
        for (int j = 0; j < 4; j++) c[i][j] = 0.0f;
    proj_mm(sb, wr, lane, c);
    __syncthreads();
    {
        const int* mrow = mask + n * SEQ + l0;
        const float mk0 = (float)mrow[wr + grow];
        const float mk1 = (float)mrow[wr + grow + 8];
        #pragma unroll
        for (int nt = 0; nt < 8; nt++) {
            int col = nt * 8 + qr * 2;
            *(uint32_t*)(g_kbf + hb + (size_t)(wr + grow) * HDIM + col) =
                f2bf2(c[nt][0] * mk0, c[nt][1] * mk0);
            *(uint32_t*)(g_kbf + hb + (size_t)(wr + grow + 8) * HDIM + col) =
                f2bf2(c[nt][2] * mk1, c[nt][3] * mk1);
        }
    }

    // ---- v = q Wv^T ----
    proj_load_w(smc, Wv, t);
    __syncthreads();
    #pragma unroll
    for (int i = 0; i < 8; i++)
        #pragma unroll
        for (int j = 0; j < 4; j++) c[i][j] = 0.0f;
    proj_mm_regA(sb, lane, qh, ql, c);
    #pragma unroll
    for (int nt = 0; nt < 8; nt++) {
        int col = nt * 8 + qr * 2;
        *(uint32_t*)(g_vbf + hb + (size_t)(wr + grow) * HDIM + col) = f2bf2(c[nt][0], c[nt][1]);
        *(uint32_t*)(g_vbf + hb + (size_t)(wr + grow + 8) * HDIM + col) = f2bf2(c[nt][2], c[nt][3]);
        *(float2*)(g_v + hb + (size_t)(wr + grow) * HDIM + col) = make_float2(c[nt][0], c[nt][1]);
        *(float2*)(g_v + hb + (size_t)(wr + grow + 8) * HDIM + col) = make_float2(c[nt][2], c[nt][3]);
    }
}

// ---------------------------------------------------------------------------
// Kernel 1b: masked V column sums + mask counts (once per (n,h))
// ---------------------------------------------------------------------------
__global__ __launch_bounds__(256) void colsum_kernel(const int* __restrict__ mask)
{
    const int bid = blockIdx.x, y = blockIdx.y;
    const float* V = g_v + (size_t)bid * SEQ * HDIM + (size_t)y * 512 * HDIM;
    const int* mg = mask + (bid >> 4) * SEQ + y * 512;
    const int d = threadIdx.x & 63, grp = threadIdx.x >> 6;
    float s = 0.0f;
    int scnt = 0;
    const float* vp = V + (size_t)grp * 128 * HDIM + d;
    const int* mp = mg + grp * 128;
    #pragma unroll 8
    for (int cc = 0; cc < 128; cc++) {
        int m = mp[cc];
        s = fmaf((float)m, vp[(size_t)cc * HDIM], s);
        scnt += m;
    }
    __shared__ float red[256];
    __shared__ int redc[4];
    red[threadIdx.x] = s;
    if (d == 0) redc[grp] = scnt;
    __syncthreads();
    if (threadIdx.x < 64)
        g_sv4[((size_t)bid * 4 + y) * HDIM + threadIdx.x] =
            red[threadIdx.x] + red[64 + threadIdx.x] + red[128 + threadIdx.x] + red[192 + threadIdx.x];
    if (threadIdx.x == 0)
        g_mcnt[bid * 4 + y] = (float)(redc[0] + redc[1] + redc[2] + redc[3]);
}

// ---------------------------------------------------------------------------
// Kernel 2: HMMA flash attention. 4 warps x 32 query rows (M=32/warp):
// K/V B-fragments amortized over 2x MMAs -> halved LDSM traffic (was the
// binding L1/smem constraint at 63%).
// ---------------------------------------------------------------------------
#define A_QS 0
#define A_KS0 18432
#define A_KS1 36864
#define A_VS0 55296
#define A_VS1 73728
#define A_SVR 92160
#define A_CNT 92416
#define A_TOTAL 92432

__global__ __launch_bounds__(128, 2) void attn_hmma()
{
    extern __shared__ char smc[];
    const uint32_t sb = smem_u32(smc);
    const int t = threadIdx.x;
    const int w = t >> 5, lane = t & 31;
    const int grow = lane >> 2, qr = lane & 3;
    const int wr = w * 32;                      // 32 query rows per warp
    const int n = blockIdx.z, h = blockIdx.y, q0 = blockIdx.x * 128;
    const size_t hb = (size_t)(n * NHEAD + h) * SEQ;
    const __nv_bfloat16* Qg = g_qbf + (hb + q0) * HDIM;
    const __nv_bfloat16* Kg = g_kbf + hb * HDIM;
    const __nv_bfloat16* Vg = g_vbf + hb * HDIM;

    for (int i = t; i < 1024; i += 128) {
        int r = i >> 3, ch = i & 7;
        uint32_t so = (uint32_t)((r * SKW + ch * 8) * 2);
        cp16(sb + A_QS + so, Qg + r * 64 + ch * 8);
        cp16(sb + A_KS0 + so, Kg + r * 64 + ch * 8);
        cp16(sb + A_VS0 + so, Vg + r * 64 + ch * 8);
    }
    if (t < 64) {
        const float* s4 = g_sv4 + (size_t)(n * NHEAD + h) * 4 * HDIM;
        ((float*)(smc + A_SVR))[t] = s4[t] + s4[64 + t] + s4[128 + t] + s4[192 + t];
    }
    if (t < 4) ((float*)(smc + A_CNT))[t] = g_mcnt[(n * NHEAD + h) * 4 + t];
    CP_COMMIT();
    CP_WAIT(0);
    __syncthreads();

    // preload Q A-fragments: two m16 tiles (wr, wr+16) x 4 k-steps
    uint32_t qf0[4][4], qf1[4][4];
    {
        uint32_t qrow = (uint32_t)(wr + (lane & 7) + ((lane & 8) ? 8 : 0));
        uint32_t qcs = (lane & 16) ? 8u : 0u;
        #pragma unroll
        for (int kk = 0; kk < 4; kk++) {
            ldm4(qf0[kk][0], qf0[kk][1], qf0[kk][2], qf0[kk][3],
                 sb + A_QS + (qrow * SKW + kk * 16 + qcs) * 2);
            ldm4(qf1[kk][0], qf1[kk][1], qf1[kk][2], qf1[kk][3],
                 sb + A_QS + ((qrow + 16) * SKW + kk * 16 + qcs) * 2);
        }
    }

    float of0[9][4], of1[9][4];
    #pragma unroll
    for (int i = 0; i < 9; i++)
        #pragma unroll
        for (int j = 0; j < 4; j++) { of0[i][j] = 0.0f; of1[i][j] = 0.0f; }

    const uint32_t krow_b = (uint32_t)(lane & 7);
    const uint32_t ke = ((uint32_t)(lane >> 3)) * 8;
    const uint32_t vrow_b = (uint32_t)(((lane & 8) ? 8 : 0) + (lane & 7));
    const uint32_t vcs = (lane & 16) ? 8u : 0u;
    const uint32_t bones = (lane < 4) ? 0x3F803F80u : 0u;

    const __nv_bfloat162 C24 = __float2bfloat162_rn(4.1666667e-2f);
    const __nv_bfloat162 C6  = __float2bfloat162_rn(1.6666667e-1f);
    const __nv_bfloat162 C2  = __float2bfloat162_rn(0.5f);
    const __nv_bfloat162 C1  = __float2bfloat162_rn(1.0f);

    for (int tile = 0; tile < 16; tile++) {
        if (tile) __syncthreads();

        if (tile < 15) {
            const int kn = tile * 128 + 128;
            const __nv_bfloat16* ks = Kg + (size_t)kn * HDIM;
            const __nv_bfloat16* vs = Vg + (size_t)kn * HDIM;
            uint32_t kb = sb + ((tile + 1) & 1 ? A_KS1 : A_KS0);
            uint32_t vb = sb + ((tile + 1) & 1 ? A_VS1 : A_VS0);
            for (int i = t; i < 1024; i += 128) {
                int r = i >> 3, ch = i & 7;
                uint32_t so = (uint32_t)((r * SKW + ch * 8) * 2);
                cp16(kb + so, ks + r * 64 + ch * 8);
                cp16(vb + so, vs + r * 64 + ch * 8);
            }
            CP_COMMIT();
            CP_WAIT(1);
        } else {
            CP_WAIT(0);
        }
        __syncthreads();

        const uint32_t kb = sb + (tile & 1 ? A_KS1 : A_KS0);
        const uint32_t vb = sb + (tile & 1 ? A_VS1 : A_VS0);

        // S for both m16 tiles -> packed delta -> P fragments (pf0, pf1)
        uint32_t pf0[8][4], pf1[8][4];
        #pragma unroll
        for (int ct = 0; ct < 16; ct++) {
            float sa0[4] = {0.0f, 0.0f, 0.0f, 0.0f};
            float sa1[4] = {0.0f, 0.0f, 0.0f, 0.0f};
            uint32_t base = kb + ((ct * 8 + krow_b) * SKW + ke) * 2;
            uint32_t b0, b1, b2, b3, b4, b5, b6, b7;
            ldm4(b0, b1, b2, b3, base);
            ldm4(b4, b5, b6, b7, base + 64);
            mma_bf16(sa0, qf0[0][0], qf0[0][1], qf0[0][2], qf0[0][3], b0, b1);
            mma_bf16(sa1, qf1[0][0], qf1[0][1], qf1[0][2], qf1[0][3], b0, b1);
            mma_bf16(sa0, qf0[1][0], qf0[1][1], qf0[1][2], qf0[1][3], b2, b3);
            mma_bf16(sa1, qf1[1][0], qf1[1][1], qf1[1][2], qf1[1][3], b2, b3);
            mma_bf16(sa0, qf0[2][0], qf0[2][1], qf0[2][2], qf0[2][3], b4, b5);
            mma_bf16(sa1, qf1[2][0], qf1[2][1], qf1[2][2], qf1[2][3], b4, b5);
            mma_bf16(sa0, qf0[3][0], qf0[3][1], qf0[3][2], qf0[3][3], b6, b7);
            mma_bf16(sa1, qf1[3][0], qf1[3][1], qf1[3][2], qf1[3][3], b6, b7);

            __nv_bfloat162 x01, x23, y01, y23;
            *(uint32_t*)&x01 = f2bf2(sa0[0], sa0[1]);
            *(uint32_t*)&x23 = f2bf2(sa0[2], sa0[3]);
            *(uint32_t*)&y01 = f2bf2(sa1[0], sa1[1]);
            *(uint32_t*)&y23 = f2bf2(sa1[2], sa1[3]);
            __nv_bfloat162 d01 = __hmul2(x01, __hfma2(x01, __hfma2(x01, __hfma2(x01, C24, C6), C2), C1));
            __nv_bfloat162 d23 = __hmul2(x23, __hfma2(x23, __hfma2(x23, __hfma2(x23, C24, C6), C2), C1));
            __nv_bfloat162 e01 = __hmul2(y01, __hfma2(y01, __hfma2(y01, __hfma2(y01, C24, C6), C2), C1));
            __nv_bfloat162 e23 = __hmul2(y23, __hfma2(y23, __hfma2(y23, __hfma2(y23, C24, C6), C2), C1));
            pf0[ct >> 1][(ct & 1) * 2 + 0] = *(uint32_t*)&d01;
            pf0[ct >> 1][(ct & 1) * 2 + 1] = *(uint32_t*)&d23;
            pf1[ct >> 1][(ct & 1) * 2 + 0] = *(uint32_t*)&e01;
            pf1[ct >> 1][(ct & 1) * 2 + 1] = *(uint32_t*)&e23;
        }

        // O += deltaP * V for both m16 tiles; shared V fragments
        #pragma unroll
        for (int kk = 0; kk < 8; kk++) {
            uint32_t rbase = vb + ((kk * 16 + vrow_b) * SKW + vcs) * 2;
            #pragma unroll
            for (int dg = 0; dg < 4; dg++) {
                uint32_t v0, v1, v2, v3;
                ldm4t(v0, v1, v2, v3, rbase + dg * 32);
                mma_bf16(of0[2 * dg],     pf0[kk][0], pf0[kk][1], pf0[kk][2], pf0[kk][3], v0, v1);
                mma_bf16(of1[2 * dg],     pf1[kk][0], pf1[kk][1], pf1[kk][2], pf1[kk][3], v0, v1);
                mma_bf16(of0[2 * dg + 1], pf0[kk][0], pf0[kk][1], pf0[kk][2], pf0[kk][3], v2, v3);
                mma_bf16(of1[2 * dg + 1], pf1[kk][0], pf1[kk][1], pf1[kk][2], pf1[kk][3], v2, v3);
            }
            mma_bf16(of0[8], pf0[kk][0], pf0[kk][1], pf0[kk][2], pf0[kk][3], bones, bones);
            mma_bf16(of1[8], pf1[kk][0], pf1[kk][1], pf1[kk][2], pf1[kk][3], bones, bones);
        }
    }

    const float* c4 = (const float*)(smc + A_CNT);
    const float cnt = c4[0] + c4[1] + c4[2] + c4[3];
    float sd00 = __shfl_sync(0xffffffffu, of0[8][0], lane & 28);
    float sd01 = __shfl_sync(0xffffffffu, of0[8][2], lane & 28);
    float sd10 = __shfl_sync(0xffffffffu, of1[8][0], lane & 28);
    float sd11 = __shfl_sync(0xffffffffu, of1[8][2], lane & 28);
    const float i00 = 1.0f / (cnt + sd00), i01 = 1.0f / (cnt + sd01);
    const float i10 = 1.0f / (cnt + sd10), i11 = 1.0f / (cnt + sd11);

    const float* sv = (const float*)(smc + A_SVR);
    const size_t rb = ((size_t)n * SEQ + q0 + wr + grow) * EMBD + h * HDIM;
    #pragma unroll
    for (int half = 0; half < 2; half++) {
        const float (*ofp)[4] = half ? of1 : of0;
        const float inv0 = half ? i10 : i00;
        const float inv1 = half ? i11 : i01;
        const size_t base0 = rb + (size_t)(half * 16) * EMBD;
        const size_t base1 = base0 + (size_t)8 * EMBD;
        #pragma unroll
        for (int dt = 0; dt < 8; dt++) {
            int j0 = dt * 8 + qr * 2;
            float o00 = (ofp[dt][0] + sv[j0]) * inv0;
            float o01 = (ofp[dt][1] + sv[j0 + 1]) * inv0;
            float o10 = (ofp[dt][2] + sv[j0]) * inv1;
            float o11 = (ofp[dt][3] + sv[j0 + 1]) * inv1;
            uint32_t h0 = f2bf2(o00, o01);
            uint32_t h1 = f2bf2(o10, o11);
            float r00 = o00 - __uint_as_float(h0 << 16);
            float r01 = o01 - __uint_as_float(h0 & 0xffff0000u);
            float r10 = o10 - __uint_as_float(h1 << 16);
            float r11 = o11 - __uint_as_float(h1 & 0xffff0000u);
            *(uint32_t*)(g_ahi + base0 + j0) = h0;
            *(uint32_t*)(g_ahi + base1 + j0) = h1;
            *(uint32_t*)(g_alo + base0 + j0) = f2bf2(r00, r01);
            *(uint32_t*)(g_alo + base1 + j0) = f2bf2(r10, r11);
        }
    }
}

// ---------------------------------------------------------------------------
// Kernel 3a: Wo -> hi/lo bf16 split
// ---------------------------------------------------------------------------
__global__ __launch_bounds__(256) void wo_prep(const float* __restrict__ Wo)
{
    int i = blockIdx.x * 256 + threadIdx.x;
    float wv = Wo[i];
    __nv_bfloat16 hi = __float2bfloat16(wv);
    g_whi[i] = hi;
    g_wlo[i] = __float2bfloat16(wv - __bfloat162float(hi));
}

// ---------------------------------------------------------------------------
// Kernel 3b: out = attn @ Wo^T + bo (HMMA 3-way split, cp.async double buffer)
// ---------------------------------------------------------------------------
#define O_STAGE 73728
#define O_AH 0
#define O_AL 18432
#define O_WH 36864
#define O_WL 55296
#define O_TOTAL (2 * O_STAGE)

__global__ __launch_bounds__(256, 1) void out_hmma(const float* __restrict__ bo, float* __restrict__ out)
{
    extern __shared__ char smc[];
    const uint32_t sb = smem_u32(smc);
    const int t = threadIdx.x;
    const int w = t >> 5, lane = t & 31;
    const int grow = lane >> 2, qr = lane & 3;
    const int o0 = blockIdx.x * 128, m0 = blockIdx.y * 128;
    const int my = (w >> 2) * 64, ox = (w & 3) * 32;

    const __nv_bfloat16* AHg = g_ahi + (size_t)m0 * EMBD;
    const __nv_bfloat16* ALg = g_alo + (size_t)m0 * EMBD;
    const __nv_bfloat16* WHg = g_whi + (size_t)o0 * EMBD;
    const __nv_bfloat16* WLg = g_wlo + (size_t)o0 * EMBD;

    for (int i = t; i < 1024; i += 256) {
        int r = i >> 3, ch = i & 7;
        uint32_t so = (uint32_t)((r * SKW + ch * 8) * 2);
        size_t go = (size_t)r * EMBD + ch * 8;
        cp16(sb + O_AH + so, AHg + go);
        cp16(sb + O_AL + so, ALg + go);
        cp16(sb + O_WH + so, WHg + go);
        cp16(sb + O_WL + so, WLg + go);
    }
    CP_COMMIT();

    float cf[4][4][4];
    #pragma unroll
    for (int i = 0; i < 4; i++)
        #pragma unroll
        for (int j = 0; j < 4; j++)
            #pragma unroll
            for (int k = 0; k < 4; k++) cf[i][j][k] = 0.0f;

    const uint32_t arow = (uint32_t)(my + (lane & 7) + ((lane & 8) ? 8 : 0));
    const uint32_t acs = (lane & 16) ? 8u : 0u;
    const uint32_t brow = (uint32_t)(ox + ((lane & 16) ? 8 : 0) + (lane & 7));
    const uint32_t bcs = (lane & 8) ? 8u : 0u;

    for (int ec = 0; ec < 16; ec++) {
        if (ec) __syncthreads();

        if (ec < 15) {
            uint32_t stage = sb + ((ec + 1) & 1) * O_STAGE;
            size_t gb = (size_t)(ec + 1) * 64;
            for (int i = t; i < 1024; i += 256) {
                int r = i >> 3, ch = i & 7;
                uint32_t so = (uint32_t)((r * SKW + ch * 8) * 2);
                size_t go = (size_t)r * EMBD + gb + ch * 8;
                cp16(stage + O_AH + so, AHg + go);
                cp16(stage + O_AL + so, ALg + go);
                cp16(stage + O_WH + so, WHg + go);
                cp16(stage + O_WL + so, WLg + go);
            }
            CP_COMMIT();
            CP_WAIT(1);
        } else {
            CP_WAIT(0);
        }
        __syncthreads();

        const uint32_t st = sb + (ec & 1) * O_STAGE;
        #pragma unroll
        for (int kk = 0; kk < 4; kk++) {
            uint32_t ah[4][4], al[4][4], bh[4][2], bl[4][2];
            #pragma unroll
            for (int mt = 0; mt < 4; mt++) {
                uint32_t off = (((arow + mt * 16) * SKW) + kk * 16 + acs) * 2;
                ldm4(ah[mt][0], ah[mt][1], ah[mt][2], ah[mt][3], st + O_AH + off);
                ldm4(al[mt][0], al[mt][1], al[mt][2], al[mt][3], st + O_AL + off);
            }
            #pragma unroll
            for (int p = 0; p < 2; p++) {
                uint32_t off = (((brow + p * 16) * SKW) + kk * 16 + bcs) * 2;
                ldm4(bh[2 * p][0], bh[2 * p][1], bh[2 * p + 1][0], bh[2 * p + 1][1], st + O_WH + off);
                ldm4(bl[2 * p][0], bl[2 * p][1], bl[2 * p + 1][0], bl[2 * p + 1][1], st + O_WL + off);
            }
            #pragma unroll
            for (int mt = 0; mt < 4; mt++)
                #pragma unroll
                for (int nt = 0; nt < 4; nt++) {
                    mma_bf16(cf[mt][nt], ah[mt][0], ah[mt][1], ah[mt][2], ah[mt][3], bh[nt][0], bh[nt][1]);
                    mma_bf16(cf[mt][nt], ah[mt][0], ah[mt][1], ah[mt][2], ah[mt][3], bl[nt][0], bl[nt][1]);
                    mma_bf16(cf[mt][nt], al[mt][0], al[mt][1], al[mt][2], al[mt][3], bh[nt][0], bh[nt][1]);
                }
        }
    }

    #pragma unroll
    for (int mt = 0; mt < 4; mt++) {
        int row = m0 + my + mt * 16 + grow;
        #pragma unroll
        for (int nt = 0; nt < 4; nt++) {
            int col = o0 + ox + nt * 8 + qr * 2;
            float b0 = bo[col], b1 = bo[col + 1];
            *(float2*)(out + (size_t)row * EMBD + col) =
                make_float2(cf[mt][nt][0] + b0, cf[mt][nt][1] + b1);
            *(float2*)(out + (size_t)(row + 8) * EMBD + col) =
                make_float2(cf[mt][nt][2] + b0, cf[mt][nt][3] + b1);
        }
    }
}

// ---------------------------------------------------------------------------
extern "C" void kernel_launch(void* const* d_in, const int* in_sizes, int n_in,
                              void* d_out, int out_size)
{
    const float* keys    = (const float*)d_in[0];
    const float* queries = (const float*)d_in[1];
    const int*   mask    = (const int*)d_in[3];
    const float* Wk      = (const float*)d_in[4];
    const float* Wq      = (const float*)d_in[5];
    const float* Wv      = (const float*)d_in[6];
    const float* Wo      = (const float*)d_in[7];
    const float* bo      = (const float*)d_in[8];
    float* out = (float*)d_out;

    cudaFuncSetAttribute(proj_hmma, cudaFuncAttributeMaxDynamicSharedMemorySize, P_TOTAL);
    cudaFuncSetAttribute(attn_hmma, cudaFuncAttributeMaxDynamicSharedMemorySize, A_TOTAL);
    cudaFuncSetAttribute(out_hmma, cudaFuncAttributeMaxDynamicSharedMemorySize, O_TOTAL);

    dim3 gp(SEQ / 128, NHEAD, NBATCH);
    proj_hmma<<<gp, 256, P_TOTAL>>>(keys, queries, Wk, Wq, Wv, mask);
    dim3 gc(NBATCH * NHEAD, 4);
    colsum_kernel<<<gc, 256>>>(mask);
    wo_prep<<<(EMBD * EMBD) / 256, 256>>>(Wo);
    dim3 ga(SEQ / 128, NHEAD, NBATCH);
    attn_hmma<<<ga, 128, A_TOTAL>>>();
    dim3 go(EMBD / 128, NBATCH * SEQ / 128);
    out_hmma<<<go, 256, O_TOTAL>>>(bo, out);
}

// round 11
// speedup vs baseline: 1.4832x; 1.4832x over previous
#include <cuda_runtime.h>
#include <cuda_bf16.h>
#include <math.h>
#include <stdint.h>

#define NBATCH 2
#define SEQ 2048
#define EMBD 1024
#define NHEAD 16
#define HDIM 64
#define ATT_SCALE 0.03125f
#define SKW 72                    // bf16 smem row stride: 16B-aligned, ldmatrix conflict-free

// scratch
__device__ float g_v[(size_t)NBATCH * NHEAD * SEQ * HDIM];            // fp32 V (colsum source)
__device__ float g_sv4[(size_t)NBATCH * NHEAD * 4 * HDIM];            // partial masked colsums
__device__ float g_mcnt[(size_t)NBATCH * NHEAD * 4];                  // partial mask counts
__device__ __nv_bfloat16 g_qbf[(size_t)NBATCH * NHEAD * SEQ * HDIM];  // pre-scaled by 1/32
__device__ __nv_bfloat16 g_kbf[(size_t)NBATCH * NHEAD * SEQ * HDIM];  // pre-masked (k * mask)
__device__ __nv_bfloat16 g_vbf[(size_t)NBATCH * NHEAD * SEQ * HDIM];
__device__ __nv_bfloat16 g_ahi[(size_t)NBATCH * SEQ * EMBD];
__device__ __nv_bfloat16 g_alo[(size_t)NBATCH * SEQ * EMBD];
__device__ __nv_bfloat16 g_whi[(size_t)EMBD * EMBD];
__device__ __nv_bfloat16 g_wlo[(size_t)EMBD * EMBD];

// ===================== helpers =====================
__device__ __forceinline__ uint32_t smem_u32(const void* p) {
    uint32_t a;
    asm("{ .reg .u64 t; cvta.to.shared.u64 t, %1; cvt.u32.u64 %0, t; }" : "=r"(a) : "l"(p));
    return a;
}
__device__ __forceinline__ void cp16(uint32_t s, const void* g) {
    asm volatile("cp.async.ca.shared.global [%0], [%1], 16;" :: "r"(s), "l"(g));
}
#define CP_COMMIT() asm volatile("cp.async.commit_group;" ::: "memory")
#define CP_WAIT(n)  asm volatile("cp.async.wait_group %0;" :: "n"(n) : "memory")

__device__ __forceinline__ void mma_bf16(float* c, uint32_t a0, uint32_t a1, uint32_t a2, uint32_t a3,
                                         uint32_t b0, uint32_t b1) {
    asm volatile("mma.sync.aligned.m16n8k16.row.col.f32.bf16.bf16.f32 "
                 "{%0,%1,%2,%3}, {%4,%5,%6,%7}, {%8,%9}, {%0,%1,%2,%3};"
                 : "+f"(c[0]), "+f"(c[1]), "+f"(c[2]), "+f"(c[3])
                 : "r"(a0), "r"(a1), "r"(a2), "r"(a3), "r"(b0), "r"(b1));
}
__device__ __forceinline__ void ldm4(uint32_t& r0, uint32_t& r1, uint32_t& r2, uint32_t& r3, uint32_t a) {
    asm volatile("ldmatrix.sync.aligned.m8n8.x4.shared.b16 {%0,%1,%2,%3}, [%4];"
                 : "=r"(r0), "=r"(r1), "=r"(r2), "=r"(r3) : "r"(a));
}
__device__ __forceinline__ void ldm4t(uint32_t& r0, uint32_t& r1, uint32_t& r2, uint32_t& r3, uint32_t a) {
    asm volatile("ldmatrix.sync.aligned.m8n8.x4.trans.shared.b16 {%0,%1,%2,%3}, [%4];"
                 : "=r"(r0), "=r"(r1), "=r"(r2), "=r"(r3) : "r"(a));
}
__device__ __forceinline__ uint32_t f2bf2(float lo, float hi) {
    uint32_t u;
    asm("cvt.rn.bf16x2.f32 %0, %1, %2;" : "=r"(u) : "f"(hi), "f"(lo));
    return u;
}

// ---------------------------------------------------------------------------
// Kernel 1: projections via HMMA (3-way bf16 split). 128 rows x one head/block.
// k output is pre-multiplied by the attention mask (masked keys -> 0 -> delta 0).
// ---------------------------------------------------------------------------
#define P_XH 0
#define P_XL 18432
#define P_WH 36864
#define P_WL 46080
#define P_TOTAL 55296

__device__ __forceinline__ void proj_load_x(char* smc, const float* __restrict__ x, int t) {
    for (int i = t; i < 2048; i += 256) {
        int r = i >> 4, c4 = (i & 15) * 4;
        float4 v = *(const float4*)(x + (size_t)r * EMBD + c4);
        uint32_t h01 = f2bf2(v.x, v.y), h23 = f2bf2(v.z, v.w);
        float r0 = v.x - __uint_as_float(h01 << 16);
        float r1 = v.y - __uint_as_float(h01 & 0xffff0000u);
        float r2 = v.z - __uint_as_float(h23 << 16);
        float r3 = v.w - __uint_as_float(h23 & 0xffff0000u);
        uint32_t so = (uint32_t)((r * SKW + c4) * 2);
        *(uint2*)(smc + P_XH + so) = make_uint2(h01, h23);
        *(uint2*)(smc + P_XL + so) = make_uint2(f2bf2(r0, r1), f2bf2(r2, r3));
    }
}
__device__ __forceinline__ void proj_load_w(char* smc, const float* __restrict__ W, int t) {
    for (int i = t; i < 1024; i += 256) {
        int r = i >> 4, c4 = (i & 15) * 4;
        float4 v = *(const float4*)(W + r * 64 + c4);
        uint32_t h01 = f2bf2(v.x, v.y), h23 = f2bf2(v.z, v.w);
        float r0 = v.x - __uint_as_float(h01 << 16);
        float r1 = v.y - __uint_as_float(h01 & 0xffff0000u);
        float r2 = v.z - __uint_as_float(h23 << 16);
        float r3 = v.w - __uint_as_float(h23 & 0xffff0000u);
        uint32_t so = (uint32_t)((r * SKW + c4) * 2);
        *(uint2*)(smc + P_WH + so) = make_uint2(h01, h23);
        *(uint2*)(smc + P_WL + so) = make_uint2(f2bf2(r0, r1), f2bf2(r2, r3));
    }
}
__device__ __forceinline__ void proj_mm(uint32_t sb, int wr, int lane, float (&c)[8][4]) {
    const uint32_t arow = (uint32_t)(wr + (lane & 7) + ((lane & 8) ? 8 : 0));
    const uint32_t acs = (lane & 16) ? 8u : 0u;
    const uint32_t brow = (uint32_t)(((lane & 16) ? 8 : 0) + (lane & 7));
    const uint32_t bcs = (lane & 8) ? 8u : 0u;
    #pragma unroll
    for (int kk = 0; kk < 4; kk++) {
        uint32_t xh[4], xl[4];
        ldm4(xh[0], xh[1], xh[2], xh[3], sb + P_XH + (arow * SKW + kk * 16 + acs) * 2);
        ldm4(xl[0], xl[1], xl[2], xl[3], sb + P_XL + (arow * SKW + kk * 16 + acs) * 2);
        #pragma unroll
        for (int p = 0; p < 4; p++) {
            uint32_t off = ((p * 16 + brow) * SKW + kk * 16 + bcs) * 2;
            uint32_t bh0, bh1, bh2, bh3, bl0, bl1, bl2, bl3;
            ldm4(bh0, bh1, bh2, bh3, sb + P_WH + off);
            ldm4(bl0, bl1, bl2, bl3, sb + P_WL + off);
            mma_bf16(c[2 * p],     xh[0], xh[1], xh[2], xh[3], bh0, bh1);
            mma_bf16(c[2 * p],     xh[0], xh[1], xh[2], xh[3], bl0, bl1);
            mma_bf16(c[2 * p],     xl[0], xl[1], xl[2], xl[3], bh0, bh1);
            mma_bf16(c[2 * p + 1], xh[0], xh[1], xh[2], xh[3], bh2, bh3);
            mma_bf16(c[2 * p + 1], xh[0], xh[1], xh[2], xh[3], bl2, bl3);
            mma_bf16(c[2 * p + 1], xl[0], xl[1], xl[2], xl[3], bh2, bh3);
        }
    }
}
__device__ __forceinline__ void proj_mm_regA(uint32_t sb, int lane,
                                             const uint32_t (&ah)[4][4], const uint32_t (&al)[4][4],
                                             float (&c)[8][4]) {
    const uint32_t brow = (uint32_t)(((lane & 16) ? 8 : 0) + (lane & 7));
    const uint32_t bcs = (lane & 8) ? 8u : 0u;
    #pragma unroll
    for (int kk = 0; kk < 4; kk++) {
        #pragma unroll
        for (int p = 0; p < 4; p++) {
            uint32_t off = ((p * 16 + brow) * SKW + kk * 16 + bcs) * 2;
            uint32_t bh0, bh1, bh2, bh3, bl0, bl1, bl2, bl3;
            ldm4(bh0, bh1, bh2, bh3, sb + P_WH + off);
            ldm4(bl0, bl1, bl2, bl3, sb + P_WL + off);
            mma_bf16(c[2 * p],     ah[kk][0], ah[kk][1], ah[kk][2], ah[kk][3], bh0, bh1);
            mma_bf16(c[2 * p],     ah[kk][0], ah[kk][1], ah[kk][2], ah[kk][3], bl0, bl1);
            mma_bf16(c[2 * p],     al[kk][0], al[kk][1], al[kk][2], al[kk][3], bh0, bh1);
            mma_bf16(c[2 * p + 1], ah[kk][0], ah[kk][1], ah[kk][2], ah[kk][3], bh2, bh3);
            mma_bf16(c[2 * p + 1], ah[kk][0], ah[kk][1], ah[kk][2], ah[kk][3], bl2, bl3);
            mma_bf16(c[2 * p + 1], al[kk][0], al[kk][1], al[kk][2], al[kk][3], bh2, bh3);
        }
    }
}

__global__ __launch_bounds__(256, 2) void proj_hmma(
    const float* __restrict__ keys, const float* __restrict__ queries,
    const float* __restrict__ Wk, const float* __restrict__ Wq, const float* __restrict__ Wv,
    const int* __restrict__ mask)
{
    extern __shared__ char smc[];
    const uint32_t sb = smem_u32(smc);
    const int t = threadIdx.x, w = t >> 5, lane = t & 31;
    const int grow = lane >> 2, qr = lane & 3;
    const int wr = w * 16;
    const int n = blockIdx.z, h = blockIdx.y, l0 = blockIdx.x * 128;
    const size_t hb = ((size_t)(n * NHEAD + h) * SEQ + l0) * HDIM;
    const float* xq = queries + ((size_t)n * SEQ + l0) * EMBD + h * HDIM;
    const float* xk = keys    + ((size_t)n * SEQ + l0) * EMBD + h * HDIM;

    // ---- q ----
    proj_load_x(smc, xq, t);
    proj_load_w(smc, Wq, t);
    __syncthreads();
    float c[8][4];
    #pragma unroll
    for (int i = 0; i < 8; i++)
        #pragma unroll
        for (int j = 0; j < 4; j++) c[i][j] = 0.0f;
    proj_mm(sb, wr, lane, c);
    __syncthreads();

    uint32_t qh[4][4], ql[4][4];
    #pragma unroll
    for (int nt = 0; nt < 8; nt++) {
        uint32_t h0 = f2bf2(c[nt][0], c[nt][1]);
        uint32_t h1 = f2bf2(c[nt][2], c[nt][3]);
        float r0 = c[nt][0] - __uint_as_float(h0 << 16);
        float r1 = c[nt][1] - __uint_as_float(h0 & 0xffff0000u);
        float r2 = c[nt][2] - __uint_as_float(h1 << 16);
        float r3 = c[nt][3] - __uint_as_float(h1 & 0xffff0000u);
        qh[nt >> 1][(nt & 1) * 2 + 0] = h0;
        qh[nt >> 1][(nt & 1) * 2 + 1] = h1;
        ql[nt >> 1][(nt & 1) * 2 + 0] = f2bf2(r0, r1);
        ql[nt >> 1][(nt & 1) * 2 + 1] = f2bf2(r2, r3);
        int col = nt * 8 + qr * 2;
        *(uint32_t*)(g_qbf + hb + (size_t)(wr + grow) * HDIM + col) =
            f2bf2(c[nt][0] * ATT_SCALE, c[nt][1] * ATT_SCALE);
        *(uint32_t*)(g_qbf + hb + (size_t)(wr + grow + 8) * HDIM + col) =
            f2bf2(c[nt][2] * ATT_SCALE, c[nt][3] * ATT_SCALE);
    }

    // ---- k (pre-masked) ----
    proj_load_x(smc, xk, t);
    proj_load_w(smc, Wk, t);
    __syncthreads();
    #pragma unroll
    for (int i = 0; i < 8; i++)
        #pragma unroll
        for (int j = 0; j < 4; j++) c[i][j] = 0.0f;
    proj_mm(sb, wr, lane, c);
    __syncthreads();
    {
        const int* mrow = mask + n * SEQ + l0;
        const float mk0 = (float)mrow[wr + grow];
        const float mk1 = (float)mrow[wr + grow + 8];
        #pragma unroll
        for (int nt = 0; nt < 8; nt++) {
            int col = nt * 8 + qr * 2;
            *(uint32_t*)(g_kbf + hb + (size_t)(wr + grow) * HDIM + col) =
                f2bf2(c[nt][0] * mk0, c[nt][1] * mk0);
            *(uint32_t*)(g_kbf + hb + (size_t)(wr + grow + 8) * HDIM + col) =
                f2bf2(c[nt][2] * mk1, c[nt][3] * mk1);
        }
    }

    // ---- v = q Wv^T ----
    proj_load_w(smc, Wv, t);
    __syncthreads();
    #pragma unroll
    for (int i = 0; i < 8; i++)
        #pragma unroll
        for (int j = 0; j < 4; j++) c[i][j] = 0.0f;
    proj_mm_regA(sb, lane, qh, ql, c);
    #pragma unroll
    for (int nt = 0; nt < 8; nt++) {
        int col = nt * 8 + qr * 2;
        *(uint32_t*)(g_vbf + hb + (size_t)(wr + grow) * HDIM + col) = f2bf2(c[nt][0], c[nt][1]);
        *(uint32_t*)(g_vbf + hb + (size_t)(wr + grow + 8) * HDIM + col) = f2bf2(c[nt][2], c[nt][3]);
        *(float2*)(g_v + hb + (size_t)(wr + grow) * HDIM + col) = make_float2(c[nt][0], c[nt][1]);
        *(float2*)(g_v + hb + (size_t)(wr + grow + 8) * HDIM + col) = make_float2(c[nt][2], c[nt][3]);
    }
}

// ---------------------------------------------------------------------------
// Kernel 1b: masked V column sums + mask counts (once per (n,h))
// ---------------------------------------------------------------------------
__global__ __launch_bounds__(256) void colsum_kernel(const int* __restrict__ mask)
{
    const int bid = blockIdx.x, y = blockIdx.y;
    const float* V = g_v + (size_t)bid * SEQ * HDIM + (size_t)y * 512 * HDIM;
    const int* mg = mask + (bid >> 4) * SEQ + y * 512;
    const int d = threadIdx.x & 63, grp = threadIdx.x >> 6;
    float s = 0.0f;
    int scnt = 0;
    const float* vp = V + (size_t)grp * 128 * HDIM + d;
    const int* mp = mg + grp * 128;
    #pragma unroll 8
    for (int cc = 0; cc < 128; cc++) {
        int m = mp[cc];
        s = fmaf((float)m, vp[(size_t)cc * HDIM], s);
        scnt += m;
    }
    __shared__ float red[256];
    __shared__ int redc[4];
    red[threadIdx.x] = s;
    if (d == 0) redc[grp] = scnt;
    __syncthreads();
    if (threadIdx.x < 64)
        g_sv4[((size_t)bid * 4 + y) * HDIM + threadIdx.x] =
            red[threadIdx.x] + red[64 + threadIdx.x] + red[128 + threadIdx.x] + red[192 + threadIdx.x];
    if (threadIdx.x == 0)
        g_mcnt[bid * 4 + y] = (float)(redc[0] + redc[1] + redc[2] + redc[3]);
}

// ---------------------------------------------------------------------------
// Kernel 2: HMMA flash attention. 4 warps x 32 query rows, FUSED per-kk
// S -> delta-softmax -> PV: P-fragment liveness is 16 regs (vs 64 in R10),
// no spills; K/V B-fragments amortized over 2x MMAs -> halved LDSM traffic.
// ---------------------------------------------------------------------------
#define A_QS 0
#define A_KS0 18432
#define A_KS1 36864
#define A_VS0 55296
#define A_VS1 73728
#define A_SVR 92160
#define A_CNT 92416
#define A_TOTAL 92432

__global__ __launch_bounds__(128, 2) void attn_hmma()
{
    extern __shared__ char smc[];
    const uint32_t sb = smem_u32(smc);
    const int t = threadIdx.x;
    const int w = t >> 5, lane = t & 31;
    const int grow = lane >> 2, qr = lane & 3;
    const int wr = w * 32;                      // 32 query rows per warp
    const int n = blockIdx.z, h = blockIdx.y, q0 = blockIdx.x * 128;
    const size_t hb = (size_t)(n * NHEAD + h) * SEQ;
    const __nv_bfloat16* Qg = g_qbf + (hb + q0) * HDIM;
    const __nv_bfloat16* Kg = g_kbf + hb * HDIM;
    const __nv_bfloat16* Vg = g_vbf + hb * HDIM;

    for (int i = t; i < 1024; i += 128) {
        int r = i >> 3, ch = i & 7;
        uint32_t so = (uint32_t)((r * SKW + ch * 8) * 2);
        cp16(sb + A_QS + so, Qg + r * 64 + ch * 8);
        cp16(sb + A_KS0 + so, Kg + r * 64 + ch * 8);
        cp16(sb + A_VS0 + so, Vg + r * 64 + ch * 8);
    }
    if (t < 64) {
        const float* s4 = g_sv4 + (size_t)(n * NHEAD + h) * 4 * HDIM;
        ((float*)(smc + A_SVR))[t] = s4[t] + s4[64 + t] + s4[128 + t] + s4[192 + t];
    }
    if (t < 4) ((float*)(smc + A_CNT))[t] = g_mcnt[(n * NHEAD + h) * 4 + t];
    CP_COMMIT();
    CP_WAIT(0);
    __syncthreads();

    // preload Q A-fragments: two m16 tiles (wr, wr+16) x 4 k-steps
    uint32_t qf0[4][4], qf1[4][4];
    {
        uint32_t qrow = (uint32_t)(wr + (lane & 7) + ((lane & 8) ? 8 : 0));
        uint32_t qcs = (lane & 16) ? 8u : 0u;
        #pragma unroll
        for (int kk = 0; kk < 4; kk++) {
            ldm4(qf0[kk][0], qf0[kk][1], qf0[kk][2], qf0[kk][3],
                 sb + A_QS + (qrow * SKW + kk * 16 + qcs) * 2);
            ldm4(qf1[kk][0], qf1[kk][1], qf1[kk][2], qf1[kk][3],
                 sb + A_QS + ((qrow + 16) * SKW + kk * 16 + qcs) * 2);
        }
    }

    float of0[9][4], of1[9][4];
    #pragma unroll
    for (int i = 0; i < 9; i++)
        #pragma unroll
        for (int j = 0; j < 4; j++) { of0[i][j] = 0.0f; of1[i][j] = 0.0f; }

    const uint32_t krow_b = (uint32_t)(lane & 7);
    const uint32_t ke = ((uint32_t)(lane >> 3)) * 8;
    const uint32_t vrow_b = (uint32_t)(((lane & 8) ? 8 : 0) + (lane & 7));
    const uint32_t vcs = (lane & 16) ? 8u : 0u;
    const uint32_t bones = (lane < 4) ? 0x3F803F80u : 0u;

    const __nv_bfloat162 C24 = __float2bfloat162_rn(4.1666667e-2f);
    const __nv_bfloat162 C6  = __float2bfloat162_rn(1.6666667e-1f);
    const __nv_bfloat162 C2  = __float2bfloat162_rn(0.5f);
    const __nv_bfloat162 C1  = __float2bfloat162_rn(1.0f);

    for (int tile = 0; tile < 16; tile++) {
        if (tile) __syncthreads();

        if (tile < 15) {
            const int kn = tile * 128 + 128;
            const __nv_bfloat16* ks = Kg + (size_t)kn * HDIM;
            const __nv_bfloat16* vs = Vg + (size_t)kn * HDIM;
            uint32_t kbn = sb + ((tile + 1) & 1 ? A_KS1 : A_KS0);
            uint32_t vbn = sb + ((tile + 1) & 1 ? A_VS1 : A_VS0);
            for (int i = t; i < 1024; i += 128) {
                int r = i >> 3, ch = i & 7;
                uint32_t so = (uint32_t)((r * SKW + ch * 8) * 2);
                cp16(kbn + so, ks + r * 64 + ch * 8);
                cp16(vbn + so, vs + r * 64 + ch * 8);
            }
            CP_COMMIT();
            CP_WAIT(1);
        } else {
            CP_WAIT(0);
        }
        __syncthreads();

        const uint32_t kb = sb + (tile & 1 ? A_KS1 : A_KS0);
        const uint32_t vb = sb + (tile & 1 ? A_VS1 : A_VS0);

        // fused: per 16-key chunk kk, S (2 col-tiles) -> delta -> PV
        #pragma unroll
        for (int kk = 0; kk < 8; kk++) {
            uint32_t p0[4], p1[4];
            #pragma unroll
            for (int half = 0; half < 2; half++) {
                const int ct = 2 * kk + half;
                float sa0[4] = {0.0f, 0.0f, 0.0f, 0.0f};
                float sa1[4] = {0.0f, 0.0f, 0.0f, 0.0f};
                uint32_t base = kb + ((ct * 8 + krow_b) * SKW + ke) * 2;
                uint32_t b0, b1, b2, b3, b4, b5, b6, b7;
                ldm4(b0, b1, b2, b3, base);
                ldm4(b4, b5, b6, b7, base + 64);
                mma_bf16(sa0, qf0[0][0], qf0[0][1], qf0[0][2], qf0[0][3], b0, b1);
                mma_bf16(sa1, qf1[0][0], qf1[0][1], qf1[0][2], qf1[0][3], b0, b1);
                mma_bf16(sa0, qf0[1][0], qf0[1][1], qf0[1][2], qf0[1][3], b2, b3);
                mma_bf16(sa1, qf1[1][0], qf1[1][1], qf1[1][2], qf1[1][3], b2, b3);
                mma_bf16(sa0, qf0[2][0], qf0[2][1], qf0[2][2], qf0[2][3], b4, b5);
                mma_bf16(sa1, qf1[2][0], qf1[2][1], qf1[2][2], qf1[2][3], b4, b5);
                mma_bf16(sa0, qf0[3][0], qf0[3][1], qf0[3][2], qf0[3][3], b6, b7);
                mma_bf16(sa1, qf1[3][0], qf1[3][1], qf1[3][2], qf1[3][3], b6, b7);

                __nv_bfloat162 x01, x23, y01, y23;
                *(uint32_t*)&x01 = f2bf2(sa0[0], sa0[1]);
                *(uint32_t*)&x23 = f2bf2(sa0[2], sa0[3]);
                *(uint32_t*)&y01 = f2bf2(sa1[0], sa1[1]);
                *(uint32_t*)&y23 = f2bf2(sa1[2], sa1[3]);
                __nv_bfloat162 d01 = __hmul2(x01, __hfma2(x01, __hfma2(x01, __hfma2(x01, C24, C6), C2), C1));
                __nv_bfloat162 d23 = __hmul2(x23, __hfma2(x23, __hfma2(x23, __hfma2(x23, C24, C6), C2), C1));
                __nv_bfloat162 e01 = __hmul2(y01, __hfma2(y01, __hfma2(y01, __hfma2(y01, C24, C6), C2), C1));
                __nv_bfloat162 e23 = __hmul2(y23, __hfma2(y23, __hfma2(y23, __hfma2(y23, C24, C6), C2), C1));
                p0[half * 2 + 0] = *(uint32_t*)&d01;
                p0[half * 2 + 1] = *(uint32_t*)&d23;
                p1[half * 2 + 0] = *(uint32_t*)&e01;
                p1[half * 2 + 1] = *(uint32_t*)&e23;
            }

            uint32_t rbase = vb + ((kk * 16 + vrow_b) * SKW + vcs) * 2;
            #pragma unroll
            for (int dg = 0; dg < 4; dg++) {
                uint32_t v0, v1, v2, v3;
                ldm4t(v0, v1, v2, v3, rbase + dg * 32);
                mma_bf16(of0[2 * dg],     p0[0], p0[1], p0[2], p0[3], v0, v1);
                mma_bf16(of1[2 * dg],     p1[0], p1[1], p1[2], p1[3], v0, v1);
                mma_bf16(of0[2 * dg + 1], p0[0], p0[1], p0[2], p0[3], v2, v3);
                mma_bf16(of1[2 * dg + 1], p1[0], p1[1], p1[2], p1[3], v2, v3);
            }
            mma_bf16(of0[8], p0[0], p0[1], p0[2], p0[3], bones, bones);
            mma_bf16(of1[8], p1[0], p1[1], p1[2], p1[3], bones, bones);
        }
    }

    const float* c4 = (const float*)(smc + A_CNT);
    const float cnt = c4[0] + c4[1] + c4[2] + c4[3];
    float sd00 = __shfl_sync(0xffffffffu, of0[8][0], lane & 28);
    float sd01 = __shfl_sync(0xffffffffu, of0[8][2], lane & 28);
    float sd10 = __shfl_sync(0xffffffffu, of1[8][0], lane & 28);
    float sd11 = __shfl_sync(0xffffffffu, of1[8][2], lane & 28);
    const float i00 = 1.0f / (cnt + sd00), i01 = 1.0f / (cnt + sd01);
    const float i10 = 1.0f / (cnt + sd10), i11 = 1.0f / (cnt + sd11);

    const float* sv = (const float*)(smc + A_SVR);
    const size_t rb = ((size_t)n * SEQ + q0 + wr + grow) * EMBD + h * HDIM;
    #pragma unroll
    for (int half = 0; half < 2; half++) {
        const float (*ofp)[4] = half ? of1 : of0;
        const float inv0 = half ? i10 : i00;
        const float inv1 = half ? i11 : i01;
        const size_t base0 = rb + (size_t)(half * 16) * EMBD;
        const size_t base1 = base0 + (size_t)8 * EMBD;
        #pragma unroll
        for (int dt = 0; dt < 8; dt++) {
            int j0 = dt * 8 + qr * 2;
            float o00 = (ofp[dt][0] + sv[j0]) * inv0;
            float o01 = (ofp[dt][1] + sv[j0 + 1]) * inv0;
            float o10 = (ofp[dt][2] + sv[j0]) * inv1;
            float o11 = (ofp[dt][3] + sv[j0 + 1]) * inv1;
            uint32_t h0 = f2bf2(o00, o01);
            uint32_t h1 = f2bf2(o10, o11);
            float r00 = o00 - __uint_as_float(h0 << 16);
            float r01 = o01 - __uint_as_float(h0 & 0xffff0000u);
            float r10 = o10 - __uint_as_float(h1 << 16);
            float r11 = o11 - __uint_as_float(h1 & 0xffff0000u);
            *(uint32_t*)(g_ahi + base0 + j0) = h0;
            *(uint32_t*)(g_ahi + base1 + j0) = h1;
            *(uint32_t*)(g_alo + base0 + j0) = f2bf2(r00, r01);
            *(uint32_t*)(g_alo + base1 + j0) = f2bf2(r10, r11);
        }
    }
}

// ---------------------------------------------------------------------------
// Kernel 3a: Wo -> hi/lo bf16 split
// ---------------------------------------------------------------------------
__global__ __launch_bounds__(256) void wo_prep(const float* __restrict__ Wo)
{
    int i = blockIdx.x * 256 + threadIdx.x;
    float wv = Wo[i];
    __nv_bfloat16 hi = __float2bfloat16(wv);
    g_whi[i] = hi;
    g_wlo[i] = __float2bfloat16(wv - __bfloat162float(hi));
}

// ---------------------------------------------------------------------------
// Kernel 3b: out = attn @ Wo^T + bo (HMMA 3-way split, cp.async double buffer)
// ---------------------------------------------------------------------------
#define O_STAGE 73728
#define O_AH 0
#define O_AL 18432
#define O_WH 36864
#define O_WL 55296
#define O_TOTAL (2 * O_STAGE)

__global__ __launch_bounds__(256, 1) void out_hmma(const float* __restrict__ bo, float* __restrict__ out)
{
    extern __shared__ char smc[];
    const uint32_t sb = smem_u32(smc);
    const int t = threadIdx.x;
    const int w = t >> 5, lane = t & 31;
    const int grow = lane >> 2, qr = lane & 3;
    const int o0 = blockIdx.x * 128, m0 = blockIdx.y * 128;
    const int my = (w >> 2) * 64, ox = (w & 3) * 32;

    const __nv_bfloat16* AHg = g_ahi + (size_t)m0 * EMBD;
    const __nv_bfloat16* ALg = g_alo + (size_t)m0 * EMBD;
    const __nv_bfloat16* WHg = g_whi + (size_t)o0 * EMBD;
    const __nv_bfloat16* WLg = g_wlo + (size_t)o0 * EMBD;

    for (int i = t; i < 1024; i += 256) {
        int r = i >> 3, ch = i & 7;
        uint32_t so = (uint32_t)((r * SKW + ch * 8) * 2);
        size_t go = (size_t)r * EMBD + ch * 8;
        cp16(sb + O_AH + so, AHg + go);
        cp16(sb + O_AL + so, ALg + go);
        cp16(sb + O_WH + so, WHg + go);
        cp16(sb + O_WL + so, WLg + go);
    }
    CP_COMMIT();

    float cf[4][4][4];
    #pragma unroll
    for (int i = 0; i < 4; i++)
        #pragma unroll
        for (int j = 0; j < 4; j++)
            #pragma unroll
            for (int k = 0; k < 4; k++) cf[i][j][k] = 0.0f;

    const uint32_t arow = (uint32_t)(my + (lane & 7) + ((lane & 8) ? 8 : 0));
    const uint32_t acs = (lane & 16) ? 8u : 0u;
    const uint32_t brow = (uint32_t)(ox + ((lane & 16) ? 8 : 0) + (lane & 7));
    const uint32_t bcs = (lane & 8) ? 8u : 0u;

    for (int ec = 0; ec < 16; ec++) {
        if (ec) __syncthreads();

        if (ec < 15) {
            uint32_t stage = sb + ((ec + 1) & 1) * O_STAGE;
            size_t gb = (size_t)(ec + 1) * 64;
            for (int i = t; i < 1024; i += 256) {
                int r = i >> 3, ch = i & 7;
                uint32_t so = (uint32_t)((r * SKW + ch * 8) * 2);
                size_t go = (size_t)r * EMBD + gb + ch * 8;
                cp16(stage + O_AH + so, AHg + go);
                cp16(stage + O_AL + so, ALg + go);
                cp16(stage + O_WH + so, WHg + go);
                cp16(stage + O_WL + so, WLg + go);
            }
            CP_COMMIT();
            CP_WAIT(1);
        } else {
            CP_WAIT(0);
        }
        __syncthreads();

        const uint32_t st = sb + (ec & 1) * O_STAGE;
        #pragma unroll
        for (int kk = 0; kk < 4; kk++) {
            uint32_t ah[4][4], al[4][4], bh[4][2], bl[4][2];
            #pragma unroll
            for (int mt = 0; mt < 4; mt++) {
                uint32_t off = (((arow + mt * 16) * SKW) + kk * 16 + acs) * 2;
                ldm4(ah[mt][0], ah[mt][1], ah[mt][2], ah[mt][3], st + O_AH + off);
                ldm4(al[mt][0], al[mt][1], al[mt][2], al[mt][3], st + O_AL + off);
            }
            #pragma unroll
            for (int p = 0; p < 2; p++) {
                uint32_t off = (((brow + p * 16) * SKW) + kk * 16 + bcs) * 2;
                ldm4(bh[2 * p][0], bh[2 * p][1], bh[2 * p + 1][0], bh[2 * p + 1][1], st + O_WH + off);
                ldm4(bl[2 * p][0], bl[2 * p][1], bl[2 * p + 1][0], bl[2 * p + 1][1], st + O_WL + off);
            }
            #pragma unroll
            for (int mt = 0; mt < 4; mt++)
                #pragma unroll
                for (int nt = 0; nt < 4; nt++) {
                    mma_bf16(cf[mt][nt], ah[mt][0], ah[mt][1], ah[mt][2], ah[mt][3], bh[nt][0], bh[nt][1]);
                    mma_bf16(cf[mt][nt], ah[mt][0], ah[mt][1], ah[mt][2], ah[mt][3], bl[nt][0], bl[nt][1]);
                    mma_bf16(cf[mt][nt], al[mt][0], al[mt][1], al[mt][2], al[mt][3], bh[nt][0], bh[nt][1]);
                }
        }
    }

    #pragma unroll
    for (int mt = 0; mt < 4; mt++) {
        int row = m0 + my + mt * 16 + grow;
        #pragma unroll
        for (int nt = 0; nt < 4; nt++) {
            int col = o0 + ox + nt * 8 + qr * 2;
            float b0 = bo[col], b1 = bo[col + 1];
            *(float2*)(out + (size_t)row * EMBD + col) =
                make_float2(cf[mt][nt][0] + b0, cf[mt][nt][1] + b1);
            *(float2*)(out + (size_t)(row + 8) * EMBD + col) =
                make_float2(cf[mt][nt][2] + b0, cf[mt][nt][3] + b1);
        }
    }
}

// ---------------------------------------------------------------------------
extern "C" void kernel_launch(void* const* d_in, const int* in_sizes, int n_in,
                              void* d_out, int out_size)
{
    const float* keys    = (const float*)d_in[0];
    const float* queries = (const float*)d_in[1];
    const int*   mask    = (const int*)d_in[3];
    const float* Wk      = (const float*)d_in[4];
    const float* Wq      = (const float*)d_in[5];
    const float* Wv      = (const float*)d_in[6];
    const float* Wo      = (const float*)d_in[7];
    const float* bo      = (const float*)d_in[8];
    float* out = (float*)d_out;

    cudaFuncSetAttribute(proj_hmma, cudaFuncAttributeMaxDynamicSharedMemorySize, P_TOTAL);
    cudaFuncSetAttribute(attn_hmma, cudaFuncAttributeMaxDynamicSharedMemorySize, A_TOTAL);
    cudaFuncSetAttribute(out_hmma, cudaFuncAttributeMaxDynamicSharedMemorySize, O_TOTAL);

    dim3 gp(SEQ / 128, NHEAD, NBATCH);
    proj_hmma<<<gp, 256, P_TOTAL>>>(keys, queries, Wk, Wq, Wv, mask);
    dim3 gc(NBATCH * NHEAD, 4);
    colsum_kernel<<<gc, 256>>>(mask);
    wo_prep<<<(EMBD * EMBD) / 256, 256>>>(Wo);
    dim3 ga(SEQ / 128, NHEAD, NBATCH);
    attn_hmma<<<ga, 128, A_TOTAL>>>();
    dim3 go(EMBD / 128, NBATCH * SEQ / 128);
    out_hmma<<<go, 256, O_TOTAL>>>(bo, out);
}

// round 12
// speedup vs baseline: 1.5345x; 1.0346x over previous
#include <cuda_runtime.h>
#include <cuda_bf16.h>
#include <math.h>
#include <stdint.h>

#define NBATCH 2
#define SEQ 2048
#define EMBD 1024
#define NHEAD 16
#define HDIM 64
#define ATT_SCALE 0.03125f
#define SKW 72                    // bf16 smem row stride: 16B-aligned, ldmatrix conflict-free

// scratch
__device__ float g_v[(size_t)NBATCH * NHEAD * SEQ * HDIM];            // fp32 V (colsum source)
__device__ float g_sv4[(size_t)NBATCH * NHEAD * 4 * HDIM];            // partial masked colsums
__device__ float g_mcnt[(size_t)NBATCH * NHEAD * 4];                  // partial mask counts
__device__ __nv_bfloat16 g_qbf[(size_t)NBATCH * NHEAD * SEQ * HDIM];  // pre-scaled by 1/32
__device__ __nv_bfloat16 g_kbf[(size_t)NBATCH * NHEAD * SEQ * HDIM];  // pre-masked (k * mask)
__device__ __nv_bfloat16 g_vbf[(size_t)NBATCH * NHEAD * SEQ * HDIM];
__device__ __nv_bfloat16 g_ahi[(size_t)NBATCH * SEQ * EMBD];
__device__ __nv_bfloat16 g_alo[(size_t)NBATCH * SEQ * EMBD];
__device__ __nv_bfloat16 g_whi[(size_t)EMBD * EMBD];
__device__ __nv_bfloat16 g_wlo[(size_t)EMBD * EMBD];

// ===================== helpers =====================
__device__ __forceinline__ uint32_t smem_u32(const void* p) {
    uint32_t a;
    asm("{ .reg .u64 t; cvta.to.shared.u64 t, %1; cvt.u32.u64 %0, t; }" : "=r"(a) : "l"(p));
    return a;
}
__device__ __forceinline__ void cp16(uint32_t s, const void* g) {
    asm volatile("cp.async.ca.shared.global [%0], [%1], 16;" :: "r"(s), "l"(g));
}
#define CP_COMMIT() asm volatile("cp.async.commit_group;" ::: "memory")
#define CP_WAIT(n)  asm volatile("cp.async.wait_group %0;" :: "n"(n) : "memory")

__device__ __forceinline__ void mma_bf16(float* c, uint32_t a0, uint32_t a1, uint32_t a2, uint32_t a3,
                                         uint32_t b0, uint32_t b1) {
    asm volatile("mma.sync.aligned.m16n8k16.row.col.f32.bf16.bf16.f32 "
                 "{%0,%1,%2,%3}, {%4,%5,%6,%7}, {%8,%9}, {%0,%1,%2,%3};"
                 : "+f"(c[0]), "+f"(c[1]), "+f"(c[2]), "+f"(c[3])
                 : "r"(a0), "r"(a1), "r"(a2), "r"(a3), "r"(b0), "r"(b1));
}
__device__ __forceinline__ void ldm4(uint32_t& r0, uint32_t& r1, uint32_t& r2, uint32_t& r3, uint32_t a) {
    asm volatile("ldmatrix.sync.aligned.m8n8.x4.shared.b16 {%0,%1,%2,%3}, [%4];"
                 : "=r"(r0), "=r"(r1), "=r"(r2), "=r"(r3) : "r"(a));
}
__device__ __forceinline__ void ldm4t(uint32_t& r0, uint32_t& r1, uint32_t& r2, uint32_t& r3, uint32_t a) {
    asm volatile("ldmatrix.sync.aligned.m8n8.x4.trans.shared.b16 {%0,%1,%2,%3}, [%4];"
                 : "=r"(r0), "=r"(r1), "=r"(r2), "=r"(r3) : "r"(a));
}
__device__ __forceinline__ uint32_t f2bf2(float lo, float hi) {
    uint32_t u;
    asm("cvt.rn.bf16x2.f32 %0, %1, %2;" : "=r"(u) : "f"(hi), "f"(lo));
    return u;
}

// ---------------------------------------------------------------------------
// Kernel 1: projections via HMMA (3-way bf16 split). 128 rows x one head/block.
// k output is pre-multiplied by the attention mask (masked keys -> 0 -> delta 0).
// ---------------------------------------------------------------------------
#define P_XH 0
#define P_XL 18432
#define P_WH 36864
#define P_WL 46080
#define P_TOTAL 55296

__device__ __forceinline__ void proj_load_x(char* smc, const float* __restrict__ x, int t) {
    for (int i = t; i < 2048; i += 256) {
        int r = i >> 4, c4 = (i & 15) * 4;
        float4 v = *(const float4*)(x + (size_t)r * EMBD + c4);
        uint32_t h01 = f2bf2(v.x, v.y), h23 = f2bf2(v.z, v.w);
        float r0 = v.x - __uint_as_float(h01 << 16);
        float r1 = v.y - __uint_as_float(h01 & 0xffff0000u);
        float r2 = v.z - __uint_as_float(h23 << 16);
        float r3 = v.w - __uint_as_float(h23 & 0xffff0000u);
        uint32_t so = (uint32_t)((r * SKW + c4) * 2);
        *(uint2*)(smc + P_XH + so) = make_uint2(h01, h23);
        *(uint2*)(smc + P_XL + so) = make_uint2(f2bf2(r0, r1), f2bf2(r2, r3));
    }
}
__device__ __forceinline__ void proj_load_w(char* smc, const float* __restrict__ W, int t) {
    for (int i = t; i < 1024; i += 256) {
        int r = i >> 4, c4 = (i & 15) * 4;
        float4 v = *(const float4*)(W + r * 64 + c4);
        uint32_t h01 = f2bf2(v.x, v.y), h23 = f2bf2(v.z, v.w);
        float r0 = v.x - __uint_as_float(h01 << 16);
        float r1 = v.y - __uint_as_float(h01 & 0xffff0000u);
        float r2 = v.z - __uint_as_float(h23 << 16);
        float r3 = v.w - __uint_as_float(h23 & 0xffff0000u);
        uint32_t so = (uint32_t)((r * SKW + c4) * 2);
        *(uint2*)(smc + P_WH + so) = make_uint2(h01, h23);
        *(uint2*)(smc + P_WL + so) = make_uint2(f2bf2(r0, r1), f2bf2(r2, r3));
    }
}
__device__ __forceinline__ void proj_mm(uint32_t sb, int wr, int lane, float (&c)[8][4]) {
    const uint32_t arow = (uint32_t)(wr + (lane & 7) + ((lane & 8) ? 8 : 0));
    const uint32_t acs = (lane & 16) ? 8u : 0u;
    const uint32_t brow = (uint32_t)(((lane & 16) ? 8 : 0) + (lane & 7));
    const uint32_t bcs = (lane & 8) ? 8u : 0u;
    #pragma unroll
    for (int kk = 0; kk < 4; kk++) {
        uint32_t xh[4], xl[4];
        ldm4(xh[0], xh[1], xh[2], xh[3], sb + P_XH + (arow * SKW + kk * 16 + acs) * 2);
        ldm4(xl[0], xl[1], xl[2], xl[3], sb + P_XL + (arow * SKW + kk * 16 + acs) * 2);
        #pragma unroll
        for (int p = 0; p < 4; p++) {
            uint32_t off = ((p * 16 + brow) * SKW + kk * 16 + bcs) * 2;
            uint32_t bh0, bh1, bh2, bh3, bl0, bl1, bl2, bl3;
            ldm4(bh0, bh1, bh2, bh3, sb + P_WH + off);
            ldm4(bl0, bl1, bl2, bl3, sb + P_WL + off);
            mma_bf16(c[2 * p],     xh[0], xh[1], xh[2], xh[3], bh0, bh1);
            mma_bf16(c[2 * p],     xh[0], xh[1], xh[2], xh[3], bl0, bl1);
            mma_bf16(c[2 * p],     xl[0], xl[1], xl[2], xl[3], bh0, bh1);
            mma_bf16(c[2 * p + 1], xh[0], xh[1], xh[2], xh[3], bh2, bh3);
            mma_bf16(c[2 * p + 1], xh[0], xh[1], xh[2], xh[3], bl2, bl3);
            mma_bf16(c[2 * p + 1], xl[0], xl[1], xl[2], xl[3], bh2, bh3);
        }
    }
}
__device__ __forceinline__ void proj_mm_regA(uint32_t sb, int lane,
                                             const uint32_t (&ah)[4][4], const uint32_t (&al)[4][4],
                                             float (&c)[8][4]) {
    const uint32_t brow = (uint32_t)(((lane & 16) ? 8 : 0) + (lane & 7));
    const uint32_t bcs = (lane & 8) ? 8u : 0u;
    #pragma unroll
    for (int kk = 0; kk < 4; kk++) {
        #pragma unroll
        for (int p = 0; p < 4; p++) {
            uint32_t off = ((p * 16 + brow) * SKW + kk * 16 + bcs) * 2;
            uint32_t bh0, bh1, bh2, bh3, bl0, bl1, bl2, bl3;
            ldm4(bh0, bh1, bh2, bh3, sb + P_WH + off);
            ldm4(bl0, bl1, bl2, bl3, sb + P_WL + off);
            mma_bf16(c[2 * p],     ah[kk][0], ah[kk][1], ah[kk][2], ah[kk][3], bh0, bh1);
            mma_bf16(c[2 * p],     ah[kk][0], ah[kk][1], ah[kk][2], ah[kk][3], bl0, bl1);
            mma_bf16(c[2 * p],     al[kk][0], al[kk][1], al[kk][2], al[kk][3], bh0, bh1);
            mma_bf16(c[2 * p + 1], ah[kk][0], ah[kk][1], ah[kk][2], ah[kk][3], bh2, bh3);
            mma_bf16(c[2 * p + 1], ah[kk][0], ah[kk][1], ah[kk][2], ah[kk][3], bl2, bl3);
            mma_bf16(c[2 * p + 1], al[kk][0], al[kk][1], al[kk][2], al[kk][3], bh2, bh3);
        }
    }
}

__global__ __launch_bounds__(256, 2) void proj_hmma(
    const float* __restrict__ keys, const float* __restrict__ queries,
    const float* __restrict__ Wk, const float* __restrict__ Wq, const float* __restrict__ Wv,
    const int* __restrict__ mask)
{
    extern __shared__ char smc[];
    const uint32_t sb = smem_u32(smc);
    const int t = threadIdx.x, w = t >> 5, lane = t & 31;
    const int grow = lane >> 2, qr = lane & 3;
    const int wr = w * 16;
    const int n = blockIdx.z, h = blockIdx.y, l0 = blockIdx.x * 128;
    const size_t hb = ((size_t)(n * NHEAD + h) * SEQ + l0) * HDIM;
    const float* xq = queries + ((size_t)n * SEQ + l0) * EMBD + h * HDIM;
    const float* xk = keys    + ((size_t)n * SEQ + l0) * EMBD + h * HDIM;

    // ---- q ----
    proj_load_x(smc, xq, t);
    proj_load_w(smc, Wq, t);
    __syncthreads();
    float c[8][4];
    #pragma unroll
    for (int i = 0; i < 8; i++)
        #pragma unroll
        for (int j = 0; j < 4; j++) c[i][j] = 0.0f;
    proj_mm(sb, wr, lane, c);
    __syncthreads();

    uint32_t qh[4][4], ql[4][4];
    #pragma unroll
    for (int nt = 0; nt < 8; nt++) {
        uint32_t h0 = f2bf2(c[nt][0], c[nt][1]);
        uint32_t h1 = f2bf2(c[nt][2], c[nt][3]);
        float r0 = c[nt][0] - __uint_as_float(h0 << 16);
        float r1 = c[nt][1] - __uint_as_float(h0 & 0xffff0000u);
        float r2 = c[nt][2] - __uint_as_float(h1 << 16);
        float r3 = c[nt][3] - __uint_as_float(h1 & 0xffff0000u);
        qh[nt >> 1][(nt & 1) * 2 + 0] = h0;
        qh[nt >> 1][(nt & 1) * 2 + 1] = h1;
        ql[nt >> 1][(nt & 1) * 2 + 0] = f2bf2(r0, r1);
        ql[nt >> 1][(nt & 1) * 2 + 1] = f2bf2(r2, r3);
        int col = nt * 8 + qr * 2;
        *(uint32_t*)(g_qbf + hb + (size_t)(wr + grow) * HDIM + col) =
            f2bf2(c[nt][0] * ATT_SCALE, c[nt][1] * ATT_SCALE);
        *(uint32_t*)(g_qbf + hb + (size_t)(wr + grow + 8) * HDIM + col) =
            f2bf2(c[nt][2] * ATT_SCALE, c[nt][3] * ATT_SCALE);
    }

    // ---- k (pre-masked) ----
    proj_load_x(smc, xk, t);
    proj_load_w(smc, Wk, t);
    __syncthreads();
    #pragma unroll
    for (int i = 0; i < 8; i++)
        #pragma unroll
        for (int j = 0; j < 4; j++) c[i][j] = 0.0f;
    proj_mm(sb, wr, lane, c);
    __syncthreads();
    {
        const int* mrow = mask + n * SEQ + l0;
        const float mk0 = (float)mrow[wr + grow];
        const float mk1 = (float)mrow[wr + grow + 8];
        #pragma unroll
        for (int nt = 0; nt < 8; nt++) {
            int col = nt * 8 + qr * 2;
            *(uint32_t*)(g_kbf + hb + (size_t)(wr + grow) * HDIM + col) =
                f2bf2(c[nt][0] * mk0, c[nt][1] * mk0);
            *(uint32_t*)(g_kbf + hb + (size_t)(wr + grow + 8) * HDIM + col) =
                f2bf2(c[nt][2] * mk1, c[nt][3] * mk1);
        }
    }

    // ---- v = q Wv^T ----
    proj_load_w(smc, Wv, t);
    __syncthreads();
    #pragma unroll
    for (int i = 0; i < 8; i++)
        #pragma unroll
        for (int j = 0; j < 4; j++) c[i][j] = 0.0f;
    proj_mm_regA(sb, lane, qh, ql, c);
    #pragma unroll
    for (int nt = 0; nt < 8; nt++) {
        int col = nt * 8 + qr * 2;
        *(uint32_t*)(g_vbf + hb + (size_t)(wr + grow) * HDIM + col) = f2bf2(c[nt][0], c[nt][1]);
        *(uint32_t*)(g_vbf + hb + (size_t)(wr + grow + 8) * HDIM + col) = f2bf2(c[nt][2], c[nt][3]);
        *(float2*)(g_v + hb + (size_t)(wr + grow) * HDIM + col) = make_float2(c[nt][0], c[nt][1]);
        *(float2*)(g_v + hb + (size_t)(wr + grow + 8) * HDIM + col) = make_float2(c[nt][2], c[nt][3]);
    }
}

// ---------------------------------------------------------------------------
// Kernel 1b: masked V column sums + mask counts (once per (n,h))
// ---------------------------------------------------------------------------
__global__ __launch_bounds__(256) void colsum_kernel(const int* __restrict__ mask)
{
    const int bid = blockIdx.x, y = blockIdx.y;
    const float* V = g_v + (size_t)bid * SEQ * HDIM + (size_t)y * 512 * HDIM;
    const int* mg = mask + (bid >> 4) * SEQ + y * 512;
    const int d = threadIdx.x & 63, grp = threadIdx.x >> 6;
    float s = 0.0f;
    int scnt = 0;
    const float* vp = V + (size_t)grp * 128 * HDIM + d;
    const int* mp = mg + grp * 128;
    #pragma unroll 8
    for (int cc = 0; cc < 128; cc++) {
        int m = mp[cc];
        s = fmaf((float)m, vp[(size_t)cc * HDIM], s);
        scnt += m;
    }
    __shared__ float red[256];
    __shared__ int redc[4];
    red[threadIdx.x] = s;
    if (d == 0) redc[grp] = scnt;
    __syncthreads();
    if (threadIdx.x < 64)
        g_sv4[((size_t)bid * 4 + y) * HDIM + threadIdx.x] =
            red[threadIdx.x] + red[64 + threadIdx.x] + red[128 + threadIdx.x] + red[192 + threadIdx.x];
    if (threadIdx.x == 0)
        g_mcnt[bid * 4 + y] = (float)(redc[0] + redc[1] + redc[2] + redc[3]);
}

// ---------------------------------------------------------------------------
// Kernel 2: HMMA flash attention. 4 warps x 32 query rows, fused per-kk
// S -> delta -> PV. Q smem ALIASED into KS1 (dead after fragment preload)
// -> 74KB smem, and __launch_bounds__(128,3) -> 3 CTAs/SM = 12 warps/SM.
// ---------------------------------------------------------------------------
#define A_KS0 0
#define A_KS1 18432
#define A_VS0 36864
#define A_VS1 55296
#define A_SVR 73728
#define A_CNT 73984
#define A_TOTAL 74048

__global__ __launch_bounds__(128, 3) void attn_hmma()
{
    extern __shared__ char smc[];
    const uint32_t sb = smem_u32(smc);
    const int t = threadIdx.x;
    const int w = t >> 5, lane = t & 31;
    const int grow = lane >> 2, qr = lane & 3;
    const int wr = w * 32;                      // 32 query rows per warp
    const int n = blockIdx.z, h = blockIdx.y, q0 = blockIdx.x * 128;
    const size_t hb = (size_t)(n * NHEAD + h) * SEQ;
    const __nv_bfloat16* Qg = g_qbf + (hb + q0) * HDIM;
    const __nv_bfloat16* Kg = g_kbf + hb * HDIM;
    const __nv_bfloat16* Vg = g_vbf + hb * HDIM;

    // prologue: Q staged into KS1 (freed after fragment preload), K0/V0 tiles
    for (int i = t; i < 1024; i += 128) {
        int r = i >> 3, ch = i & 7;
        uint32_t so = (uint32_t)((r * SKW + ch * 8) * 2);
        cp16(sb + A_KS1 + so, Qg + r * 64 + ch * 8);
        cp16(sb + A_KS0 + so, Kg + r * 64 + ch * 8);
        cp16(sb + A_VS0 + so, Vg + r * 64 + ch * 8);
    }
    if (t < 64) {
        const float* s4 = g_sv4 + (size_t)(n * NHEAD + h) * 4 * HDIM;
        ((float*)(smc + A_SVR))[t] = s4[t] + s4[64 + t] + s4[128 + t] + s4[192 + t];
    }
    if (t < 4) ((float*)(smc + A_CNT))[t] = g_mcnt[(n * NHEAD + h) * 4 + t];
    CP_COMMIT();
    CP_WAIT(0);
    __syncthreads();

    // preload Q A-fragments from KS1: two m16 tiles (wr, wr+16) x 4 k-steps
    uint32_t qf0[4][4], qf1[4][4];
    {
        uint32_t qrow = (uint32_t)(wr + (lane & 7) + ((lane & 8) ? 8 : 0));
        uint32_t qcs = (lane & 16) ? 8u : 0u;
        #pragma unroll
        for (int kk = 0; kk < 4; kk++) {
            ldm4(qf0[kk][0], qf0[kk][1], qf0[kk][2], qf0[kk][3],
                 sb + A_KS1 + (qrow * SKW + kk * 16 + qcs) * 2);
            ldm4(qf1[kk][0], qf1[kk][1], qf1[kk][2], qf1[kk][3],
                 sb + A_KS1 + ((qrow + 16) * SKW + kk * 16 + qcs) * 2);
        }
    }
    __syncthreads();                            // Q reads done before KS1 reuse

    float of0[9][4], of1[9][4];
    #pragma unroll
    for (int i = 0; i < 9; i++)
        #pragma unroll
        for (int j = 0; j < 4; j++) { of0[i][j] = 0.0f; of1[i][j] = 0.0f; }

    const uint32_t krow_b = (uint32_t)(lane & 7);
    const uint32_t ke = ((uint32_t)(lane >> 3)) * 8;
    const uint32_t vrow_b = (uint32_t)(((lane & 8) ? 8 : 0) + (lane & 7));
    const uint32_t vcs = (lane & 16) ? 8u : 0u;
    const uint32_t bones = (lane < 4) ? 0x3F803F80u : 0u;

    const __nv_bfloat162 C24 = __float2bfloat162_rn(4.1666667e-2f);
    const __nv_bfloat162 C6  = __float2bfloat162_rn(1.6666667e-1f);
    const __nv_bfloat162 C2  = __float2bfloat162_rn(0.5f);
    const __nv_bfloat162 C1  = __float2bfloat162_rn(1.0f);

    for (int tile = 0; tile < 16; tile++) {
        if (tile) __syncthreads();

        if (tile < 15) {
            const int kn = tile * 128 + 128;
            const __nv_bfloat16* ks = Kg + (size_t)kn * HDIM;
            const __nv_bfloat16* vs = Vg + (size_t)kn * HDIM;
            uint32_t kbn = sb + ((tile + 1) & 1 ? A_KS1 : A_KS0);
            uint32_t vbn = sb + ((tile + 1) & 1 ? A_VS1 : A_VS0);
            for (int i = t; i < 1024; i += 128) {
                int r = i >> 3, ch = i & 7;
                uint32_t so = (uint32_t)((r * SKW + ch * 8) * 2);
                cp16(kbn + so, ks + r * 64 + ch * 8);
                cp16(vbn + so, vs + r * 64 + ch * 8);
            }
            CP_COMMIT();
            CP_WAIT(1);
        } else {
            CP_WAIT(0);
        }
        __syncthreads();

        const uint32_t kb = sb + (tile & 1 ? A_KS1 : A_KS0);
        const uint32_t vb = sb + (tile & 1 ? A_VS1 : A_VS0);

        // fused: per 16-key chunk kk, S (2 col-tiles) -> delta -> PV
        #pragma unroll
        for (int kk = 0; kk < 8; kk++) {
            uint32_t p0[4], p1[4];
            #pragma unroll
            for (int half = 0; half < 2; half++) {
                const int ct = 2 * kk + half;
                float sa0[4] = {0.0f, 0.0f, 0.0f, 0.0f};
                float sa1[4] = {0.0f, 0.0f, 0.0f, 0.0f};
                uint32_t base = kb + ((ct * 8 + krow_b) * SKW + ke) * 2;
                uint32_t b0, b1, b2, b3, b4, b5, b6, b7;
                ldm4(b0, b1, b2, b3, base);
                ldm4(b4, b5, b6, b7, base + 64);
                mma_bf16(sa0, qf0[0][0], qf0[0][1], qf0[0][2], qf0[0][3], b0, b1);
                mma_bf16(sa1, qf1[0][0], qf1[0][1], qf1[0][2], qf1[0][3], b0, b1);
                mma_bf16(sa0, qf0[1][0], qf0[1][1], qf0[1][2], qf0[1][3], b2, b3);
                mma_bf16(sa1, qf1[1][0], qf1[1][1], qf1[1][2], qf1[1][3], b2, b3);
                mma_bf16(sa0, qf0[2][0], qf0[2][1], qf0[2][2], qf0[2][3], b4, b5);
                mma_bf16(sa1, qf1[2][0], qf1[2][1], qf1[2][2], qf1[2][3], b4, b5);
                mma_bf16(sa0, qf0[3][0], qf0[3][1], qf0[3][2], qf0[3][3], b6, b7);
                mma_bf16(sa1, qf1[3][0], qf1[3][1], qf1[3][2], qf1[3][3], b6, b7);

                __nv_bfloat162 x01, x23, y01, y23;
                *(uint32_t*)&x01 = f2bf2(sa0[0], sa0[1]);
                *(uint32_t*)&x23 = f2bf2(sa0[2], sa0[3]);
                *(uint32_t*)&y01 = f2bf2(sa1[0], sa1[1]);
                *(uint32_t*)&y23 = f2bf2(sa1[2], sa1[3]);
                __nv_bfloat162 d01 = __hmul2(x01, __hfma2(x01, __hfma2(x01, __hfma2(x01, C24, C6), C2), C1));
                __nv_bfloat162 d23 = __hmul2(x23, __hfma2(x23, __hfma2(x23, __hfma2(x23, C24, C6), C2), C1));
                __nv_bfloat162 e01 = __hmul2(y01, __hfma2(y01, __hfma2(y01, __hfma2(y01, C24, C6), C2), C1));
                __nv_bfloat162 e23 = __hmul2(y23, __hfma2(y23, __hfma2(y23, __hfma2(y23, C24, C6), C2), C1));
                p0[half * 2 + 0] = *(uint32_t*)&d01;
                p0[half * 2 + 1] = *(uint32_t*)&d23;
                p1[half * 2 + 0] = *(uint32_t*)&e01;
                p1[half * 2 + 1] = *(uint32_t*)&e23;
            }

            uint32_t rbase = vb + ((kk * 16 + vrow_b) * SKW + vcs) * 2;
            #pragma unroll
            for (int dg = 0; dg < 4; dg++) {
                uint32_t v0, v1, v2, v3;
                ldm4t(v0, v1, v2, v3, rbase + dg * 32);
                mma_bf16(of0[2 * dg],     p0[0], p0[1], p0[2], p0[3], v0, v1);
                mma_bf16(of1[2 * dg],     p1[0], p1[1], p1[2], p1[3], v0, v1);
                mma_bf16(of0[2 * dg + 1], p0[0], p0[1], p0[2], p0[3], v2, v3);
                mma_bf16(of1[2 * dg + 1], p1[0], p1[1], p1[2], p1[3], v2, v3);
            }
            mma_bf16(of0[8], p0[0], p0[1], p0[2], p0[3], bones, bones);
            mma_bf16(of1[8], p1[0], p1[1], p1[2], p1[3], bones, bones);
        }
    }

    const float* c4 = (const float*)(smc + A_CNT);
    const float cnt = c4[0] + c4[1] + c4[2] + c4[3];
    float sd00 = __shfl_sync(0xffffffffu, of0[8][0], lane & 28);
    float sd01 = __shfl_sync(0xffffffffu, of0[8][2], lane & 28);
    float sd10 = __shfl_sync(0xffffffffu, of1[8][0], lane & 28);
    float sd11 = __shfl_sync(0xffffffffu, of1[8][2], lane & 28);
    const float i00 = 1.0f / (cnt + sd00), i01 = 1.0f / (cnt + sd01);
    const float i10 = 1.0f / (cnt + sd10), i11 = 1.0f / (cnt + sd11);

    const float* sv = (const float*)(smc + A_SVR);
    const size_t rb = ((size_t)n * SEQ + q0 + wr + grow) * EMBD + h * HDIM;
    #pragma unroll
    for (int half = 0; half < 2; half++) {
        const float (*ofp)[4] = half ? of1 : of0;
        const float inv0 = half ? i10 : i00;
        const float inv1 = half ? i11 : i01;
        const size_t base0 = rb + (size_t)(half * 16) * EMBD;
        const size_t base1 = base0 + (size_t)8 * EMBD;
        #pragma unroll
        for (int dt = 0; dt < 8; dt++) {
            int j0 = dt * 8 + qr * 2;
            float o00 = (ofp[dt][0] + sv[j0]) * inv0;
            float o01 = (ofp[dt][1] + sv[j0 + 1]) * inv0;
            float o10 = (ofp[dt][2] + sv[j0]) * inv1;
            float o11 = (ofp[dt][3] + sv[j0 + 1]) * inv1;
            uint32_t h0 = f2bf2(o00, o01);
            uint32_t h1 = f2bf2(o10, o11);
            float r00 = o00 - __uint_as_float(h0 << 16);
            float r01 = o01 - __uint_as_float(h0 & 0xffff0000u);
            float r10 = o10 - __uint_as_float(h1 << 16);
            float r11 = o11 - __uint_as_float(h1 & 0xffff0000u);
            *(uint32_t*)(g_ahi + base0 + j0) = h0;
            *(uint32_t*)(g_ahi + base1 + j0) = h1;
            *(uint32_t*)(g_alo + base0 + j0) = f2bf2(r00, r01);
            *(uint32_t*)(g_alo + base1 + j0) = f2bf2(r10, r11);
        }
    }
}

// ---------------------------------------------------------------------------
// Kernel 3a: Wo -> hi/lo bf16 split
// ---------------------------------------------------------------------------
__global__ __launch_bounds__(256) void wo_prep(const float* __restrict__ Wo)
{
    int i = blockIdx.x * 256 + threadIdx.x;
    float wv = Wo[i];
    __nv_bfloat16 hi = __float2bfloat16(wv);
    g_whi[i] = hi;
    g_wlo[i] = __float2bfloat16(wv - __bfloat162float(hi));
}

// ---------------------------------------------------------------------------
// Kernel 3b: out = attn @ Wo^T + bo (HMMA 3-way split, cp.async double buffer)
// ---------------------------------------------------------------------------
#define O_STAGE 73728
#define O_AH 0
#define O_AL 18432
#define O_WH 36864
#define O_WL 55296
#define O_TOTAL (2 * O_STAGE)

__global__ __launch_bounds__(256, 1) void out_hmma(const float* __restrict__ bo, float* __restrict__ out)
{
    extern __shared__ char smc[];
    const uint32_t sb = smem_u32(smc);
    const int t = threadIdx.x;
    const int w = t >> 5, lane = t & 31;
    const int grow = lane >> 2, qr = lane & 3;
    const int o0 = blockIdx.x * 128, m0 = blockIdx.y * 128;
    const int my = (w >> 2) * 64, ox = (w & 3) * 32;

    const __nv_bfloat16* AHg = g_ahi + (size_t)m0 * EMBD;
    const __nv_bfloat16* ALg = g_alo + (size_t)m0 * EMBD;
    const __nv_bfloat16* WHg = g_whi + (size_t)o0 * EMBD;
    const __nv_bfloat16* WLg = g_wlo + (size_t)o0 * EMBD;

    for (int i = t; i < 1024; i += 256) {
        int r = i >> 3, ch = i & 7;
        uint32_t so = (uint32_t)((r * SKW + ch * 8) * 2);
        size_t go = (size_t)r * EMBD + ch * 8;
        cp16(sb + O_AH + so, AHg + go);
        cp16(sb + O_AL + so, ALg + go);
        cp16(sb + O_WH + so, WHg + go);
        cp16(sb + O_WL + so, WLg + go);
    }
    CP_COMMIT();

    float cf[4][4][4];
    #pragma unroll
    for (int i = 0; i < 4; i++)
        #pragma unroll
        for (int j = 0; j < 4; j++)
            #pragma unroll
            for (int k = 0; k < 4; k++) cf[i][j][k] = 0.0f;

    const uint32_t arow = (uint32_t)(my + (lane & 7) + ((lane & 8) ? 8 : 0));
    const uint32_t acs = (lane & 16) ? 8u : 0u;
    const uint32_t brow = (uint32_t)(ox + ((lane & 16) ? 8 : 0) + (lane & 7));
    const uint32_t bcs = (lane & 8) ? 8u : 0u;

    for (int ec = 0; ec < 16; ec++) {
        if (ec) __syncthreads();

        if (ec < 15) {
            uint32_t stage = sb + ((ec + 1) & 1) * O_STAGE;
            size_t gb = (size_t)(ec + 1) * 64;
            for (int i = t; i < 1024; i += 256) {
                int r = i >> 3, ch = i & 7;
                uint32_t so = (uint32_t)((r * SKW + ch * 8) * 2);
                size_t go = (size_t)r * EMBD + gb + ch * 8;
                cp16(stage + O_AH + so, AHg + go);
                cp16(stage + O_AL + so, ALg + go);
                cp16(stage + O_WH + so, WHg + go);
                cp16(stage + O_WL + so, WLg + go);
            }
            CP_COMMIT();
            CP_WAIT(1);
        } else {
            CP_WAIT(0);
        }
        __syncthreads();

        const uint32_t st = sb + (ec & 1) * O_STAGE;
        #pragma unroll
        for (int kk = 0; kk < 4; kk++) {
            uint32_t ah[4][4], al[4][4], bh[4][2], bl[4][2];
            #pragma unroll
            for (int mt = 0; mt < 4; mt++) {
                uint32_t off = (((arow + mt * 16) * SKW) + kk * 16 + acs) * 2;
                ldm4(ah[mt][0], ah[mt][1], ah[mt][2], ah[mt][3], st + O_AH + off);
                ldm4(al[mt][0], al[mt][1], al[mt][2], al[mt][3], st + O_AL + off);
            }
            #pragma unroll
            for (int p = 0; p < 2; p++) {
                uint32_t off = (((brow + p * 16) * SKW) + kk * 16 + bcs) * 2;
                ldm4(bh[2 * p][0], bh[2 * p][1], bh[2 * p + 1][0], bh[2 * p + 1][1], st + O_WH + off);
                ldm4(bl[2 * p][0], bl[2 * p][1], bl[2 * p + 1][0], bl[2 * p + 1][1], st + O_WL + off);
            }
            #pragma unroll
            for (int mt = 0; mt < 4; mt++)
                #pragma unroll
                for (int nt = 0; nt < 4; nt++) {
                    mma_bf16(cf[mt][nt], ah[mt][0], ah[mt][1], ah[mt][2], ah[mt][3], bh[nt][0], bh[nt][1]);
                    mma_bf16(cf[mt][nt], ah[mt][0], ah[mt][1], ah[mt][2], ah[mt][3], bl[nt][0], bl[nt][1]);
                    mma_bf16(cf[mt][nt], al[mt][0], al[mt][1], al[mt][2], al[mt][3], bh[nt][0], bh[nt][1]);
                }
        }
    }

    #pragma unroll
    for (int mt = 0; mt < 4; mt++) {
        int row = m0 + my + mt * 16 + grow;
        #pragma unroll
        for (int nt = 0; nt < 4; nt++) {
            int col = o0 + ox + nt * 8 + qr * 2;
            float b0 = bo[col], b1 = bo[col + 1];
            *(float2*)(out + (size_t)row * EMBD + col) =
                make_float2(cf[mt][nt][0] + b0, cf[mt][nt][1] + b1);
            *(float2*)(out + (size_t)(row + 8) * EMBD + col) =
                make_float2(cf[mt][nt][2] + b0, cf[mt][nt][3] + b1);
        }
    }
}

// ---------------------------------------------------------------------------
extern "C" void kernel_launch(void* const* d_in, const int* in_sizes, int n_in,
                              void* d_out, int out_size)
{
    const float* keys    = (const float*)d_in[0];
    const float* queries = (const float*)d_in[1];
    const int*   mask    = (const int*)d_in[3];
    const float* Wk      = (const float*)d_in[4];
    const float* Wq      = (const float*)d_in[5];
    const float* Wv      = (const float*)d_in[6];
    const float* Wo      = (const float*)d_in[7];
    const float* bo      = (const float*)d_in[8];
    float* out = (float*)d_out;

    cudaFuncSetAttribute(proj_hmma, cudaFuncAttributeMaxDynamicSharedMemorySize, P_TOTAL);
    cudaFuncSetAttribute(attn_hmma, cudaFuncAttributeMaxDynamicSharedMemorySize, A_TOTAL);
    cudaFuncSetAttribute(out_hmma, cudaFuncAttributeMaxDynamicSharedMemorySize, O_TOTAL);

    dim3 gp(SEQ / 128, NHEAD, NBATCH);
    proj_hmma<<<gp, 256, P_TOTAL>>>(keys, queries, Wk, Wq, Wv, mask);
    dim3 gc(NBATCH * NHEAD, 4);
    colsum_kernel<<<gc, 256>>>(mask);
    wo_prep<<<(EMBD * EMBD) / 256, 256>>>(Wo);
    dim3 ga(SEQ / 128, NHEAD, NBATCH);
    attn_hmma<<<ga, 128, A_TOTAL>>>();
    dim3 go(EMBD / 128, NBATCH * SEQ / 128);
    out_hmma<<<go, 256, O_TOTAL>>>(bo, out);
}

// round 13
// speedup vs baseline: 1.8757x; 1.2224x over previous
#include <cuda_runtime.h>
#include <cuda_bf16.h>
#include <cuda_fp16.h>
#include <math.h>
#include <stdint.h>

#define NBATCH 2
#define SEQ 2048
#define EMBD 1024
#define NHEAD 16
#define HDIM 64
#define ATT_SCALE 0.03125f
#define SKW 72                    // 16-bit smem row stride: 16B-aligned, ldmatrix conflict-free

// scratch
__device__ float g_v[(size_t)NBATCH * NHEAD * SEQ * HDIM];            // fp32 V (colsum source)
__device__ float g_sv4[(size_t)NBATCH * NHEAD * 4 * HDIM];            // partial masked colsums
__device__ float g_mcnt[(size_t)NBATCH * NHEAD * 4];                  // partial mask counts
__device__ __nv_bfloat16 g_qbf[(size_t)NBATCH * NHEAD * SEQ * HDIM];  // pre-scaled by 1/32
__device__ __nv_bfloat16 g_kbf[(size_t)NBATCH * NHEAD * SEQ * HDIM];  // pre-masked (k * mask)
__device__ __nv_bfloat16 g_vbf[(size_t)NBATCH * NHEAD * SEQ * HDIM];
__device__ __half g_a16[(size_t)NBATCH * SEQ * EMBD];                 // attn output, fp16
__device__ __half g_w16[(size_t)EMBD * EMBD];                         // Wo, fp16

// ===================== helpers =====================
__device__ __forceinline__ uint32_t smem_u32(const void* p) {
    uint32_t a;
    asm("{ .reg .u64 t; cvta.to.shared.u64 t, %1; cvt.u32.u64 %0, t; }" : "=r"(a) : "l"(p));
    return a;
}
__device__ __forceinline__ void cp16(uint32_t s, const void* g) {
    asm volatile("cp.async.ca.shared.global [%0], [%1], 16;" :: "r"(s), "l"(g));
}
#define CP_COMMIT() asm volatile("cp.async.commit_group;" ::: "memory")
#define CP_WAIT(n)  asm volatile("cp.async.wait_group %0;" :: "n"(n) : "memory")

__device__ __forceinline__ void mma_bf16(float* c, uint32_t a0, uint32_t a1, uint32_t a2, uint32_t a3,
                                         uint32_t b0, uint32_t b1) {
    asm volatile("mma.sync.aligned.m16n8k16.row.col.f32.bf16.bf16.f32 "
                 "{%0,%1,%2,%3}, {%4,%5,%6,%7}, {%8,%9}, {%0,%1,%2,%3};"
                 : "+f"(c[0]), "+f"(c[1]), "+f"(c[2]), "+f"(c[3])
                 : "r"(a0), "r"(a1), "r"(a2), "r"(a3), "r"(b0), "r"(b1));
}
__device__ __forceinline__ void mma_fp16(float* c, uint32_t a0, uint32_t a1, uint32_t a2, uint32_t a3,
                                         uint32_t b0, uint32_t b1) {
    asm volatile("mma.sync.aligned.m16n8k16.row.col.f32.f16.f16.f32 "
                 "{%0,%1,%2,%3}, {%4,%5,%6,%7}, {%8,%9}, {%0,%1,%2,%3};"
                 : "+f"(c[0]), "+f"(c[1]), "+f"(c[2]), "+f"(c[3])
                 : "r"(a0), "r"(a1), "r"(a2), "r"(a3), "r"(b0), "r"(b1));
}
__device__ __forceinline__ void ldm4(uint32_t& r0, uint32_t& r1, uint32_t& r2, uint32_t& r3, uint32_t a) {
    asm volatile("ldmatrix.sync.aligned.m8n8.x4.shared.b16 {%0,%1,%2,%3}, [%4];"
                 : "=r"(r0), "=r"(r1), "=r"(r2), "=r"(r3) : "r"(a));
}
__device__ __forceinline__ void ldm4t(uint32_t& r0, uint32_t& r1, uint32_t& r2, uint32_t& r3, uint32_t a) {
    asm volatile("ldmatrix.sync.aligned.m8n8.x4.trans.shared.b16 {%0,%1,%2,%3}, [%4];"
                 : "=r"(r0), "=r"(r1), "=r"(r2), "=r"(r3) : "r"(a));
}
__device__ __forceinline__ uint32_t f2bf2(float lo, float hi) {
    uint32_t u;
    asm("cvt.rn.bf16x2.f32 %0, %1, %2;" : "=r"(u) : "f"(hi), "f"(lo));
    return u;
}
__device__ __forceinline__ uint32_t f2h2(float lo, float hi) {
    uint32_t u;
    asm("cvt.rn.f16x2.f32 %0, %1, %2;" : "=r"(u) : "f"(hi), "f"(lo));
    return u;
}

// ---------------------------------------------------------------------------
// Kernel 1: projections via HMMA (3-way bf16 split). 128 rows x one head/block.
// k output is pre-multiplied by the attention mask (masked keys -> 0 -> delta 0).
// ---------------------------------------------------------------------------
#define P_XH 0
#define P_XL 18432
#define P_WH 36864
#define P_WL 46080
#define P_TOTAL 55296

__device__ __forceinline__ void proj_load_x(char* smc, const float* __restrict__ x, int t) {
    for (int i = t; i < 2048; i += 256) {
        int r = i >> 4, c4 = (i & 15) * 4;
        float4 v = *(const float4*)(x + (size_t)r * EMBD + c4);
        uint32_t h01 = f2bf2(v.x, v.y), h23 = f2bf2(v.z, v.w);
        float r0 = v.x - __uint_as_float(h01 << 16);
        float r1 = v.y - __uint_as_float(h01 & 0xffff0000u);
        float r2 = v.z - __uint_as_float(h23 << 16);
        float r3 = v.w - __uint_as_float(h23 & 0xffff0000u);
        uint32_t so = (uint32_t)((r * SKW + c4) * 2);
        *(uint2*)(smc + P_XH + so) = make_uint2(h01, h23);
        *(uint2*)(smc + P_XL + so) = make_uint2(f2bf2(r0, r1), f2bf2(r2, r3));
    }
}
__device__ __forceinline__ void proj_load_w(char* smc, const float* __restrict__ W, int t) {
    for (int i = t; i < 1024; i += 256) {
        int r = i >> 4, c4 = (i & 15) * 4;
        float4 v = *(const float4*)(W + r * 64 + c4);
        uint32_t h01 = f2bf2(v.x, v.y), h23 = f2bf2(v.z, v.w);
        float r0 = v.x - __uint_as_float(h01 << 16);
        float r1 = v.y - __uint_as_float(h01 & 0xffff0000u);
        float r2 = v.z - __uint_as_float(h23 << 16);
        float r3 = v.w - __uint_as_float(h23 & 0xffff0000u);
        uint32_t so = (uint32_t)((r * SKW + c4) * 2);
        *(uint2*)(smc + P_WH + so) = make_uint2(h01, h23);
        *(uint2*)(smc + P_WL + so) = make_uint2(f2bf2(r0, r1), f2bf2(r2, r3));
    }
}
__device__ __forceinline__ void proj_mm(uint32_t sb, int wr, int lane, float (&c)[8][4]) {
    const uint32_t arow = (uint32_t)(wr + (lane & 7) + ((lane & 8) ? 8 : 0));
    const uint32_t acs = (lane & 16) ? 8u : 0u;
    const uint32_t brow = (uint32_t)(((lane & 16) ? 8 : 0) + (lane & 7));
    const uint32_t bcs = (lane & 8) ? 8u : 0u;
    #pragma unroll
    for (int kk = 0; kk < 4; kk++) {
        uint32_t xh[4], xl[4];
        ldm4(xh[0], xh[1], xh[2], xh[3], sb + P_XH + (arow * SKW + kk * 16 + acs) * 2);
        ldm4(xl[0], xl[1], xl[2], xl[3], sb + P_XL + (arow * SKW + kk * 16 + acs) * 2);
        #pragma unroll
        for (int p = 0; p < 4; p++) {
            uint32_t off = ((p * 16 + brow) * SKW + kk * 16 + bcs) * 2;
            uint32_t bh0, bh1, bh2, bh3, bl0, bl1, bl2, bl3;
            ldm4(bh0, bh1, bh2, bh3, sb + P_WH + off);
            ldm4(bl0, bl1, bl2, bl3, sb + P_WL + off);
            mma_bf16(c[2 * p],     xh[0], xh[1], xh[2], xh[3], bh0, bh1);
            mma_bf16(c[2 * p],     xh[0], xh[1], xh[2], xh[3], bl0, bl1);
            mma_bf16(c[2 * p],     xl[0], xl[1], xl[2], xl[3], bh0, bh1);
            mma_bf16(c[2 * p + 1], xh[0], xh[1], xh[2], xh[3], bh2, bh3);
            mma_bf16(c[2 * p + 1], xh[0], xh[1], xh[2], xh[3], bl2, bl3);
            mma_bf16(c[2 * p + 1], xl[0], xl[1], xl[2], xl[3], bh2, bh3);
        }
    }
}
__device__ __forceinline__ void proj_mm_regA(uint32_t sb, int lane,
                                             const uint32_t (&ah)[4][4], const uint32_t (&al)[4][4],
                                             float (&c)[8][4]) {
    const uint32_t brow = (uint32_t)(((lane & 16) ? 8 : 0) + (lane & 7));
    const uint32_t bcs = (lane & 8) ? 8u : 0u;
    #pragma unroll
    for (int kk = 0; kk < 4; kk++) {
        #pragma unroll
        for (int p = 0; p < 4; p++) {
            uint32_t off = ((p * 16 + brow) * SKW + kk * 16 + bcs) * 2;
            uint32_t bh0, bh1, bh2, bh3, bl0, bl1, bl2, bl3;
            ldm4(bh0, bh1, bh2, bh3, sb + P_WH + off);
            ldm4(bl0, bl1, bl2, bl3, sb + P_WL + off);
            mma_bf16(c[2 * p],     ah[kk][0], ah[kk][1], ah[kk][2], ah[kk][3], bh0, bh1);
            mma_bf16(c[2 * p],     ah[kk][0], ah[kk][1], ah[kk][2], ah[kk][3], bl0, bl1);
            mma_bf16(c[2 * p],     al[kk][0], al[kk][1], al[kk][2], al[kk][3], bh0, bh1);
            mma_bf16(c[2 * p + 1], ah[kk][0], ah[kk][1], ah[kk][2], ah[kk][3], bh2, bh3);
            mma_bf16(c[2 * p + 1], ah[kk][0], ah[kk][1], ah[kk][2], ah[kk][3], bl2, bl3);
            mma_bf16(c[2 * p + 1], al[kk][0], al[kk][1], al[kk][2], al[kk][3], bh2, bh3);
        }
    }
}

__global__ __launch_bounds__(256, 2) void proj_hmma(
    const float* __restrict__ keys, const float* __restrict__ queries,
    const float* __restrict__ Wk, const float* __restrict__ Wq, const float* __restrict__ Wv,
    const int* __restrict__ mask)
{
    extern __shared__ char smc[];
    const uint32_t sb = smem_u32(smc);
    const int t = threadIdx.x, w = t >> 5, lane = t & 31;
    const int grow = lane >> 2, qr = lane & 3;
    const int wr = w * 16;
    const int n = blockIdx.z, h = blockIdx.y, l0 = blockIdx.x * 128;
    const size_t hb = ((size_t)(n * NHEAD + h) * SEQ + l0) * HDIM;
    const float* xq = queries + ((size_t)n * SEQ + l0) * EMBD + h * HDIM;
    const float* xk = keys    + ((size_t)n * SEQ + l0) * EMBD + h * HDIM;

    // ---- q ----
    proj_load_x(smc, xq, t);
    proj_load_w(smc, Wq, t);
    __syncthreads();
    float c[8][4];
    #pragma unroll
    for (int i = 0; i < 8; i++)
        #pragma unroll
        for (int j = 0; j < 4; j++) c[i][j] = 0.0f;
    proj_mm(sb, wr, lane, c);
    __syncthreads();

    uint32_t qh[4][4], ql[4][4];
    #pragma unroll
    for (int nt = 0; nt < 8; nt++) {
        uint32_t h0 = f2bf2(c[nt][0], c[nt][1]);
        uint32_t h1 = f2bf2(c[nt][2], c[nt][3]);
        float r0 = c[nt][0] - __uint_as_float(h0 << 16);
        float r1 = c[nt][1] - __uint_as_float(h0 & 0xffff0000u);
        float r2 = c[nt][2] - __uint_as_float(h1 << 16);
        float r3 = c[nt][3] - __uint_as_float(h1 & 0xffff0000u);
        qh[nt >> 1][(nt & 1) * 2 + 0] = h0;
        qh[nt >> 1][(nt & 1) * 2 + 1] = h1;
        ql[nt >> 1][(nt & 1) * 2 + 0] = f2bf2(r0, r1);
        ql[nt >> 1][(nt & 1) * 2 + 1] = f2bf2(r2, r3);
        int col = nt * 8 + qr * 2;
        *(uint32_t*)(g_qbf + hb + (size_t)(wr + grow) * HDIM + col) =
            f2bf2(c[nt][0] * ATT_SCALE, c[nt][1] * ATT_SCALE);
        *(uint32_t*)(g_qbf + hb + (size_t)(wr + grow + 8) * HDIM + col) =
            f2bf2(c[nt][2] * ATT_SCALE, c[nt][3] * ATT_SCALE);
    }

    // ---- k (pre-masked) ----
    proj_load_x(smc, xk, t);
    proj_load_w(smc, Wk, t);
    __syncthreads();
    #pragma unroll
    for (int i = 0; i < 8; i++)
        #pragma unroll
        for (int j = 0; j < 4; j++) c[i][j] = 0.0f;
    proj_mm(sb, wr, lane, c);
    __syncthreads();
    {
        const int* mrow = mask + n * SEQ + l0;
        const float mk0 = (float)mrow[wr + grow];
        const float mk1 = (float)mrow[wr + grow + 8];
        #pragma unroll
        for (int nt = 0; nt < 8; nt++) {
            int col = nt * 8 + qr * 2;
            *(uint32_t*)(g_kbf + hb + (size_t)(wr + grow) * HDIM + col) =
                f2bf2(c[nt][0] * mk0, c[nt][1] * mk0);
            *(uint32_t*)(g_kbf + hb + (size_t)(wr + grow + 8) * HDIM + col) =
                f2bf2(c[nt][2] * mk1, c[nt][3] * mk1);
        }
    }

    // ---- v = q Wv^T ----
    proj_load_w(smc, Wv, t);
    __syncthreads();
    #pragma unroll
    for (int i = 0; i < 8; i++)
        #pragma unroll
        for (int j = 0; j < 4; j++) c[i][j] = 0.0f;
    proj_mm_regA(sb, lane, qh, ql, c);
    #pragma unroll
    for (int nt = 0; nt < 8; nt++) {
        int col = nt * 8 + qr * 2;
        *(uint32_t*)(g_vbf + hb + (size_t)(wr + grow) * HDIM + col) = f2bf2(c[nt][0], c[nt][1]);
        *(uint32_t*)(g_vbf + hb + (size_t)(wr + grow + 8) * HDIM + col) = f2bf2(c[nt][2], c[nt][3]);
        *(float2*)(g_v + hb + (size_t)(wr + grow) * HDIM + col) = make_float2(c[nt][0], c[nt][1]);
        *(float2*)(g_v + hb + (size_t)(wr + grow + 8) * HDIM + col) = make_float2(c[nt][2], c[nt][3]);
    }
}

// ---------------------------------------------------------------------------
// Kernel 1b: masked V column sums + mask counts (once per (n,h))
// ---------------------------------------------------------------------------
__global__ __launch_bounds__(256) void colsum_kernel(const int* __restrict__ mask)
{
    const int bid = blockIdx.x, y = blockIdx.y;
    const float* V = g_v + (size_t)bid * SEQ * HDIM + (size_t)y * 512 * HDIM;
    const int* mg = mask + (bid >> 4) * SEQ + y * 512;
    const int d = threadIdx.x & 63, grp = threadIdx.x >> 6;
    float s = 0.0f;
    int scnt = 0;
    const float* vp = V + (size_t)grp * 128 * HDIM + d;
    const int* mp = mg + grp * 128;
    #pragma unroll 8
    for (int cc = 0; cc < 128; cc++) {
        int m = mp[cc];
        s = fmaf((float)m, vp[(size_t)cc * HDIM], s);
        scnt += m;
    }
    __shared__ float red[256];
    __shared__ int redc[4];
    red[threadIdx.x] = s;
    if (d == 0) redc[grp] = scnt;
    __syncthreads();
    if (threadIdx.x < 64)
        g_sv4[((size_t)bid * 4 + y) * HDIM + threadIdx.x] =
            red[threadIdx.x] + red[64 + threadIdx.x] + red[128 + threadIdx.x] + red[192 + threadIdx.x];
    if (threadIdx.x == 0)
        g_mcnt[bid * 4 + y] = (float)(redc[0] + redc[1] + redc[2] + redc[3]);
}

// ---------------------------------------------------------------------------
// Kernel 2: HMMA flash attention (identical to R12 except fp16 epilogue).
// ---------------------------------------------------------------------------
#define A_KS0 0
#define A_KS1 18432
#define A_VS0 36864
#define A_VS1 55296
#define A_SVR 73728
#define A_CNT 73984
#define A_TOTAL 74048

__global__ __launch_bounds__(128, 3) void attn_hmma()
{
    extern __shared__ char smc[];
    const uint32_t sb = smem_u32(smc);
    const int t = threadIdx.x;
    const int w = t >> 5, lane = t & 31;
    const int grow = lane >> 2, qr = lane & 3;
    const int wr = w * 32;
    const int n = blockIdx.z, h = blockIdx.y, q0 = blockIdx.x * 128;
    const size_t hb = (size_t)(n * NHEAD + h) * SEQ;
    const __nv_bfloat16* Qg = g_qbf + (hb + q0) * HDIM;
    const __nv_bfloat16* Kg = g_kbf + hb * HDIM;
    const __nv_bfloat16* Vg = g_vbf + hb * HDIM;

    for (int i = t; i < 1024; i += 128) {
        int r = i >> 3, ch = i & 7;
        uint32_t so = (uint32_t)((r * SKW + ch * 8) * 2);
        cp16(sb + A_KS1 + so, Qg + r * 64 + ch * 8);
        cp16(sb + A_KS0 + so, Kg + r * 64 + ch * 8);
        cp16(sb + A_VS0 + so, Vg + r * 64 + ch * 8);
    }
    if (t < 64) {
        const float* s4 = g_sv4 + (size_t)(n * NHEAD + h) * 4 * HDIM;
        ((float*)(smc + A_SVR))[t] = s4[t] + s4[64 + t] + s4[128 + t] + s4[192 + t];
    }
    if (t < 4) ((float*)(smc + A_CNT))[t] = g_mcnt[(n * NHEAD + h) * 4 + t];
    CP_COMMIT();
    CP_WAIT(0);
    __syncthreads();

    uint32_t qf0[4][4], qf1[4][4];
    {
        uint32_t qrow = (uint32_t)(wr + (lane & 7) + ((lane & 8) ? 8 : 0));
        uint32_t qcs = (lane & 16) ? 8u : 0u;
        #pragma unroll
        for (int kk = 0; kk < 4; kk++) {
            ldm4(qf0[kk][0], qf0[kk][1], qf0[kk][2], qf0[kk][3],
                 sb + A_KS1 + (qrow * SKW + kk * 16 + qcs) * 2);
            ldm4(qf1[kk][0], qf1[kk][1], qf1[kk][2], qf1[kk][3],
                 sb + A_KS1 + ((qrow + 16) * SKW + kk * 16 + qcs) * 2);
        }
    }
    __syncthreads();

    float of0[9][4], of1[9][4];
    #pragma unroll
    for (int i = 0; i < 9; i++)
        #pragma unroll
        for (int j = 0; j < 4; j++) { of0[i][j] = 0.0f; of1[i][j] = 0.0f; }

    const uint32_t krow_b = (uint32_t)(lane & 7);
    const uint32_t ke = ((uint32_t)(lane >> 3)) * 8;
    const uint32_t vrow_b = (uint32_t)(((lane & 8) ? 8 : 0) + (lane & 7));
    const uint32_t vcs = (lane & 16) ? 8u : 0u;
    const uint32_t bones = (lane < 4) ? 0x3F803F80u : 0u;

    const __nv_bfloat162 C24 = __float2bfloat162_rn(4.1666667e-2f);
    const __nv_bfloat162 C6  = __float2bfloat162_rn(1.6666667e-1f);
    const __nv_bfloat162 C2  = __float2bfloat162_rn(0.5f);
    const __nv_bfloat162 C1  = __float2bfloat162_rn(1.0f);

    for (int tile = 0; tile < 16; tile++) {
        if (tile) __syncthreads();

        if (tile < 15) {
            const int kn = tile * 128 + 128;
            const __nv_bfloat16* ks = Kg + (size_t)kn * HDIM;
            const __nv_bfloat16* vs = Vg + (size_t)kn * HDIM;
            uint32_t kbn = sb + ((tile + 1) & 1 ? A_KS1 : A_KS0);
            uint32_t vbn = sb + ((tile + 1) & 1 ? A_VS1 : A_VS0);
            for (int i = t; i < 1024; i += 128) {
                int r = i >> 3, ch = i & 7;
                uint32_t so = (uint32_t)((r * SKW + ch * 8) * 2);
                cp16(kbn + so, ks + r * 64 + ch * 8);
                cp16(vbn + so, vs + r * 64 + ch * 8);
            }
            CP_COMMIT();
            CP_WAIT(1);
        } else {
            CP_WAIT(0);
        }
        __syncthreads();

        const uint32_t kb = sb + (tile & 1 ? A_KS1 : A_KS0);
        const uint32_t vb = sb + (tile & 1 ? A_VS1 : A_VS0);

        #pragma unroll
        for (int kk = 0; kk < 8; kk++) {
            uint32_t p0[4], p1[4];
            #pragma unroll
            for (int half = 0; half < 2; half++) {
                const int ct = 2 * kk + half;
                float sa0[4] = {0.0f, 0.0f, 0.0f, 0.0f};
                float sa1[4] = {0.0f, 0.0f, 0.0f, 0.0f};
                uint32_t base = kb + ((ct * 8 + krow_b) * SKW + ke) * 2;
                uint32_t b0, b1, b2, b3, b4, b5, b6, b7;
                ldm4(b0, b1, b2, b3, base);
                ldm4(b4, b5, b6, b7, base + 64);
                mma_bf16(sa0, qf0[0][0], qf0[0][1], qf0[0][2], qf0[0][3], b0, b1);
                mma_bf16(sa1, qf1[0][0], qf1[0][1], qf1[0][2], qf1[0][3], b0, b1);
                mma_bf16(sa0, qf0[1][0], qf0[1][1], qf0[1][2], qf0[1][3], b2, b3);
                mma_bf16(sa1, qf1[1][0], qf1[1][1], qf1[1][2], qf1[1][3], b2, b3);
                mma_bf16(sa0, qf0[2][0], qf0[2][1], qf0[2][2], qf0[2][3], b4, b5);
                mma_bf16(sa1, qf1[2][0], qf1[2][1], qf1[2][2], qf1[2][3], b4, b5);
                mma_bf16(sa0, qf0[3][0], qf0[3][1], qf0[3][2], qf0[3][3], b6, b7);
                mma_bf16(sa1, qf1[3][0], qf1[3][1], qf1[3][2], qf1[3][3], b6, b7);

                __nv_bfloat162 x01, x23, y01, y23;
                *(uint32_t*)&x01 = f2bf2(sa0[0], sa0[1]);
                *(uint32_t*)&x23 = f2bf2(sa0[2], sa0[3]);
                *(uint32_t*)&y01 = f2bf2(sa1[0], sa1[1]);
                *(uint32_t*)&y23 = f2bf2(sa1[2], sa1[3]);
                __nv_bfloat162 d01 = __hmul2(x01, __hfma2(x01, __hfma2(x01, __hfma2(x01, C24, C6), C2), C1));
                __nv_bfloat162 d23 = __hmul2(x23, __hfma2(x23, __hfma2(x23, __hfma2(x23, C24, C6), C2), C1));
                __nv_bfloat162 e01 = __hmul2(y01, __hfma2(y01, __hfma2(y01, __hfma2(y01, C24, C6), C2), C1));
                __nv_bfloat162 e23 = __hmul2(y23, __hfma2(y23, __hfma2(y23, __hfma2(y23, C24, C6), C2), C1));
                p0[half * 2 + 0] = *(uint32_t*)&d01;
                p0[half * 2 + 1] = *(uint32_t*)&d23;
                p1[half * 2 + 0] = *(uint32_t*)&e01;
                p1[half * 2 + 1] = *(uint32_t*)&e23;
            }

            uint32_t rbase = vb + ((kk * 16 + vrow_b) * SKW + vcs) * 2;
            #pragma unroll
            for (int dg = 0; dg < 4; dg++) {
                uint32_t v0, v1, v2, v3;
                ldm4t(v0, v1, v2, v3, rbase + dg * 32);
                mma_bf16(of0[2 * dg],     p0[0], p0[1], p0[2], p0[3], v0, v1);
                mma_bf16(of1[2 * dg],     p1[0], p1[1], p1[2], p1[3], v0, v1);
                mma_bf16(of0[2 * dg + 1], p0[0], p0[1], p0[2], p0[3], v2, v3);
                mma_bf16(of1[2 * dg + 1], p1[0], p1[1], p1[2], p1[3], v2, v3);
            }
            mma_bf16(of0[8], p0[0], p0[1], p0[2], p0[3], bones, bones);
            mma_bf16(of1[8], p1[0], p1[1], p1[2], p1[3], bones, bones);
        }
    }

    const float* c4 = (const float*)(smc + A_CNT);
    const float cnt = c4[0] + c4[1] + c4[2] + c4[3];
    float sd00 = __shfl_sync(0xffffffffu, of0[8][0], lane & 28);
    float sd01 = __shfl_sync(0xffffffffu, of0[8][2], lane & 28);
    float sd10 = __shfl_sync(0xffffffffu, of1[8][0], lane & 28);
    float sd11 = __shfl_sync(0xffffffffu, of1[8][2], lane & 28);
    const float i00 = 1.0f / (cnt + sd00), i01 = 1.0f / (cnt + sd01);
    const float i10 = 1.0f / (cnt + sd10), i11 = 1.0f / (cnt + sd11);

    const float* sv = (const float*)(smc + A_SVR);
    const size_t rb = ((size_t)n * SEQ + q0 + wr + grow) * EMBD + h * HDIM;
    #pragma unroll
    for (int half = 0; half < 2; half++) {
        const float (*ofp)[4] = half ? of1 : of0;
        const float inv0 = half ? i10 : i00;
        const float inv1 = half ? i11 : i01;
        const size_t base0 = rb + (size_t)(half * 16) * EMBD;
        const size_t base1 = base0 + (size_t)8 * EMBD;
        #pragma unroll
        for (int dt = 0; dt < 8; dt++) {
            int j0 = dt * 8 + qr * 2;
            float o00 = (ofp[dt][0] + sv[j0]) * inv0;
            float o01 = (ofp[dt][1] + sv[j0 + 1]) * inv0;
            float o10 = (ofp[dt][2] + sv[j0]) * inv1;
            float o11 = (ofp[dt][3] + sv[j0 + 1]) * inv1;
            *(uint32_t*)(g_a16 + base0 + j0) = f2h2(o00, o01);
            *(uint32_t*)(g_a16 + base1 + j0) = f2h2(o10, o11);
        }
    }
}

// ---------------------------------------------------------------------------
// Kernel 3a: Wo -> fp16
// ---------------------------------------------------------------------------
__global__ __launch_bounds__(256) void wo_prep(const float* __restrict__ Wo)
{
    int i = (blockIdx.x * 256 + threadIdx.x) * 2;
    float2 wv = *(const float2*)(Wo + i);
    *(uint32_t*)(g_w16 + i) = f2h2(wv.x, wv.y);
}

// ---------------------------------------------------------------------------
// Kernel 3b: out = attn @ Wo^T + bo. SINGLE-pass fp16 MMA (fp32 accum),
// cp.async double buffer, 36.9KB/stage -> 2 CTAs/SM -> exactly 1 wave.
// ---------------------------------------------------------------------------
#define O_A 0
#define O_W 18432
#define O_STAGE 36864
#define O_TOTAL (2 * O_STAGE)

__global__ __launch_bounds__(256, 2) void out_hmma(const float* __restrict__ bo, float* __restrict__ out)
{
    extern __shared__ char smc[];
    const uint32_t sb = smem_u32(smc);
    const int t = threadIdx.x;
    const int w = t >> 5, lane = t & 31;
    const int grow = lane >> 2, qr = lane & 3;
    const int o0 = blockIdx.x * 128, m0 = blockIdx.y * 128;
    const int my = (w >> 2) * 64, ox = (w & 3) * 32;

    const __half* Ag = g_a16 + (size_t)m0 * EMBD;
    const __half* Wg = g_w16 + (size_t)o0 * EMBD;

    for (int i = t; i < 1024; i += 256) {
        int r = i >> 3, ch = i & 7;
        uint32_t so = (uint32_t)((r * SKW + ch * 8) * 2);
        size_t go = (size_t)r * EMBD + ch * 8;
        cp16(sb + O_A + so, Ag + go);
        cp16(sb + O_W + so, Wg + go);
    }
    CP_COMMIT();

    float cf[4][4][4];
    #pragma unroll
    for (int i = 0; i < 4; i++)
        #pragma unroll
        for (int j = 0; j < 4; j++)
            #pragma unroll
            for (int k = 0; k < 4; k++) cf[i][j][k] = 0.0f;

    const uint32_t arow = (uint32_t)(my + (lane & 7) + ((lane & 8) ? 8 : 0));
    const uint32_t acs = (lane & 16) ? 8u : 0u;
    const uint32_t brow = (uint32_t)(ox + ((lane & 16) ? 8 : 0) + (lane & 7));
    const uint32_t bcs = (lane & 8) ? 8u : 0u;

    for (int ec = 0; ec < 16; ec++) {
        if (ec) __syncthreads();

        if (ec < 15) {
            uint32_t stage = sb + ((ec + 1) & 1) * O_STAGE;
            size_t gb = (size_t)(ec + 1) * 64;
            for (int i = t; i < 1024; i += 256) {
                int r = i >> 3, ch = i & 7;
                uint32_t so = (uint32_t)((r * SKW + ch * 8) * 2);
                size_t go = (size_t)r * EMBD + gb + ch * 8;
                cp16(stage + O_A + so, Ag + go);
                cp16(stage + O_W + so, Wg + go);
            }
            CP_COMMIT();
            CP_WAIT(1);
        } else {
            CP_WAIT(0);
        }
        __syncthreads();

        const uint32_t st = sb + (ec & 1) * O_STAGE;
        #pragma unroll
        for (int kk = 0; kk < 4; kk++) {
            uint32_t ah[4][4], bh[4][2];
            #pragma unroll
            for (int mt = 0; mt < 4; mt++) {
                uint32_t off = (((arow + mt * 16) * SKW) + kk * 16 + acs) * 2;
                ldm4(ah[mt][0], ah[mt][1], ah[mt][2], ah[mt][3], st + O_A + off);
            }
            #pragma unroll
            for (int p = 0; p < 2; p++) {
                uint32_t off = (((brow + p * 16) * SKW) + kk * 16 + bcs) * 2;
                ldm4(bh[2 * p][0], bh[2 * p][1], bh[2 * p + 1][0], bh[2 * p + 1][1], st + O_W + off);
            }
            #pragma unroll
            for (int mt = 0; mt < 4; mt++)
                #pragma unroll
                for (int nt = 0; nt < 4; nt++)
                    mma_fp16(cf[mt][nt], ah[mt][0], ah[mt][1], ah[mt][2], ah[mt][3], bh[nt][0], bh[nt][1]);
        }
    }

    #pragma unroll
    for (int mt = 0; mt < 4; mt++) {
        int row = m0 + my + mt * 16 + grow;
        #pragma unroll
        for (int nt = 0; nt < 4; nt++) {
            int col = o0 + ox + nt * 8 + qr * 2;
            float b0 = bo[col], b1 = bo[col + 1];
            *(float2*)(out + (size_t)row * EMBD + col) =
                make_float2(cf[mt][nt][0] + b0, cf[mt][nt][1] + b1);
            *(float2*)(out + (size_t)(row + 8) * EMBD + col) =
                make_float2(cf[mt][nt][2] + b0, cf[mt][nt][3] + b1);
        }
    }
}

// ---------------------------------------------------------------------------
extern "C" void kernel_launch(void* const* d_in, const int* in_sizes, int n_in,
                              void* d_out, int out_size)
{
    const float* keys    = (const float*)d_in[0];
    const float* queries = (const float*)d_in[1];
    const int*   mask    = (const int*)d_in[3];
    const float* Wk      = (const float*)d_in[4];
    const float* Wq      = (const float*)d_in[5];
    const float* Wv      = (const float*)d_in[6];
    const float* Wo      = (const float*)d_in[7];
    const float* bo      = (const float*)d_in[8];
    float* out = (float*)d_out;

    cudaFuncSetAttribute(proj_hmma, cudaFuncAttributeMaxDynamicSharedMemorySize, P_TOTAL);
    cudaFuncSetAttribute(attn_hmma, cudaFuncAttributeMaxDynamicSharedMemorySize, A_TOTAL);
    cudaFuncSetAttribute(out_hmma, cudaFuncAttributeMaxDynamicSharedMemorySize, O_TOTAL);

    dim3 gp(SEQ / 128, NHEAD, NBATCH);
    proj_hmma<<<gp, 256, P_TOTAL>>>(keys, queries, Wk, Wq, Wv, mask);
    dim3 gc(NBATCH * NHEAD, 4);
    colsum_kernel<<<gc, 256>>>(mask);
    wo_prep<<<(EMBD * EMBD) / 512, 256>>>(Wo);
    dim3 ga(SEQ / 128, NHEAD, NBATCH);
    attn_hmma<<<ga, 128, A_TOTAL>>>();
    dim3 go(EMBD / 128, NBATCH * SEQ / 128);
    out_hmma<<<go, 256, O_TOTAL>>>(bo, out);
}

// round 14
// speedup vs baseline: 2.3321x; 1.2433x over previous
#include <cuda_runtime.h>
#include <cuda_bf16.h>
#include <cuda_fp16.h>
#include <math.h>
#include <stdint.h>

#define NBATCH 2
#define SEQ 2048
#define EMBD 1024
#define NHEAD 16
#define HDIM 64
#define ATT_SCALE 0.03125f
#define SKW 72                    // 16-bit smem row stride: 16B-aligned, ldmatrix conflict-free
#define KSTR (SEQ + 8)            // k/v per-head row stride; row SEQ is the zero pad row
#define CPAD (SEQ + 128)

// scratch
__device__ float g_v[(size_t)NBATCH * NHEAD * SEQ * HDIM];            // fp32 V (colsum source)
__device__ float g_sv4[(size_t)NBATCH * NHEAD * 4 * HDIM];            // partial masked colsums
__device__ float g_mcnt[(size_t)NBATCH * NHEAD * 4];                  // partial mask counts
__device__ int   g_cidx[(size_t)NBATCH * CPAD];                       // compacted unmasked key idx
__device__ int   g_ccnt[NBATCH];                                      // unmasked counts
__device__ __nv_bfloat16 g_qbf[(size_t)NBATCH * NHEAD * SEQ * HDIM];  // pre-scaled by 1/32
__device__ __nv_bfloat16 g_kbf[(size_t)NBATCH * NHEAD * KSTR * HDIM]; // pre-masked (k * mask)
__device__ __nv_bfloat16 g_vbf[(size_t)NBATCH * NHEAD * KSTR * HDIM];
__device__ __half g_a16[(size_t)NBATCH * SEQ * EMBD];                 // attn output, fp16
__device__ __half g_w16[(size_t)EMBD * EMBD];                         // Wo, fp16

// ===================== helpers =====================
__device__ __forceinline__ uint32_t smem_u32(const void* p) {
    uint32_t a;
    asm("{ .reg .u64 t; cvta.to.shared.u64 t, %1; cvt.u32.u64 %0, t; }" : "=r"(a) : "l"(p));
    return a;
}
__device__ __forceinline__ void cp16(uint32_t s, const void* g) {
    asm volatile("cp.async.ca.shared.global [%0], [%1], 16;" :: "r"(s), "l"(g));
}
#define CP_COMMIT() asm volatile("cp.async.commit_group;" ::: "memory")
#define CP_WAIT(n)  asm volatile("cp.async.wait_group %0;" :: "n"(n) : "memory")

__device__ __forceinline__ void mma_bf16(float* c, uint32_t a0, uint32_t a1, uint32_t a2, uint32_t a3,
                                         uint32_t b0, uint32_t b1) {
    asm volatile("mma.sync.aligned.m16n8k16.row.col.f32.bf16.bf16.f32 "
                 "{%0,%1,%2,%3}, {%4,%5,%6,%7}, {%8,%9}, {%0,%1,%2,%3};"
                 : "+f"(c[0]), "+f"(c[1]), "+f"(c[2]), "+f"(c[3])
                 : "r"(a0), "r"(a1), "r"(a2), "r"(a3), "r"(b0), "r"(b1));
}
__device__ __forceinline__ void mma_fp16(float* c, uint32_t a0, uint32_t a1, uint32_t a2, uint32_t a3,
                                         uint32_t b0, uint32_t b1) {
    asm volatile("mma.sync.aligned.m16n8k16.row.col.f32.f16.f16.f32 "
                 "{%0,%1,%2,%3}, {%4,%5,%6,%7}, {%8,%9}, {%0,%1,%2,%3};"
                 : "+f"(c[0]), "+f"(c[1]), "+f"(c[2]), "+f"(c[3])
                 : "r"(a0), "r"(a1), "r"(a2), "r"(a3), "r"(b0), "r"(b1));
}
__device__ __forceinline__ void ldm4(uint32_t& r0, uint32_t& r1, uint32_t& r2, uint32_t& r3, uint32_t a) {
    asm volatile("ldmatrix.sync.aligned.m8n8.x4.shared.b16 {%0,%1,%2,%3}, [%4];"
                 : "=r"(r0), "=r"(r1), "=r"(r2), "=r"(r3) : "r"(a));
}
__device__ __forceinline__ void ldm4t(uint32_t& r0, uint32_t& r1, uint32_t& r2, uint32_t& r3, uint32_t a) {
    asm volatile("ldmatrix.sync.aligned.m8n8.x4.trans.shared.b16 {%0,%1,%2,%3}, [%4];"
                 : "=r"(r0), "=r"(r1), "=r"(r2), "=r"(r3) : "r"(a));
}
__device__ __forceinline__ uint32_t f2bf2(float lo, float hi) {
    uint32_t u;
    asm("cvt.rn.bf16x2.f32 %0, %1, %2;" : "=r"(u) : "f"(hi), "f"(lo));
    return u;
}
__device__ __forceinline__ uint32_t f2h2(float lo, float hi) {
    uint32_t u;
    asm("cvt.rn.f16x2.f32 %0, %1, %2;" : "=r"(u) : "f"(hi), "f"(lo));
    return u;
}

// ---------------------------------------------------------------------------
// Kernel 0: build compacted unmasked-key index list per batch
// ---------------------------------------------------------------------------
__global__ __launch_bounds__(256) void compact_kernel(const int* __restrict__ mask)
{
    const int n = blockIdx.x, t = threadIdx.x;
    const int* m = mask + n * SEQ;
    int v[8];
    int c = 0;
    #pragma unroll
    for (int j = 0; j < 8; j++) { v[j] = m[t * 8 + j]; c += v[j]; }
    __shared__ int s[256];
    s[t] = c;
    __syncthreads();
    for (int off = 1; off < 256; off <<= 1) {
        int x = (t >= off) ? s[t - off] : 0;
        __syncthreads();
        s[t] += x;
        __syncthreads();
    }
    int pos = s[t] - c;
    #pragma unroll
    for (int j = 0; j < 8; j++)
        if (v[j]) g_cidx[n * CPAD + pos++] = t * 8 + j;
    __syncthreads();
    const int total = s[255];
    if (t == 0) g_ccnt[n] = total;
    const int padded = (total + 127) & ~127;
    for (int i = total + t; i < padded; i += 256)
        g_cidx[n * CPAD + i] = SEQ;                 // points at the zeroed pad row
}

// ---------------------------------------------------------------------------
// Kernel 1: projections via HMMA (3-way bf16 split). 128 rows x one head/block.
// ---------------------------------------------------------------------------
#define P_XH 0
#define P_XL 18432
#define P_WH 36864
#define P_WL 46080
#define P_TOTAL 55296

__device__ __forceinline__ void proj_load_x(char* smc, const float* __restrict__ x, int t) {
    for (int i = t; i < 2048; i += 256) {
        int r = i >> 4, c4 = (i & 15) * 4;
        float4 v = *(const float4*)(x + (size_t)r * EMBD + c4);
        uint32_t h01 = f2bf2(v.x, v.y), h23 = f2bf2(v.z, v.w);
        float r0 = v.x - __uint_as_float(h01 << 16);
        float r1 = v.y - __uint_as_float(h01 & 0xffff0000u);
        float r2 = v.z - __uint_as_float(h23 << 16);
        float r3 = v.w - __uint_as_float(h23 & 0xffff0000u);
        uint32_t so = (uint32_t)((r * SKW + c4) * 2);
        *(uint2*)(smc + P_XH + so) = make_uint2(h01, h23);
        *(uint2*)(smc + P_XL + so) = make_uint2(f2bf2(r0, r1), f2bf2(r2, r3));
    }
}
__device__ __forceinline__ void proj_load_w(char* smc, const float* __restrict__ W, int t) {
    for (int i = t; i < 1024; i += 256) {
        int r = i >> 4, c4 = (i & 15) * 4;
        float4 v = *(const float4*)(W + r * 64 + c4);
        uint32_t h01 = f2bf2(v.x, v.y), h23 = f2bf2(v.z, v.w);
        float r0 = v.x - __uint_as_float(h01 << 16);
        float r1 = v.y - __uint_as_float(h01 & 0xffff0000u);
        float r2 = v.z - __uint_as_float(h23 << 16);
        float r3 = v.w - __uint_as_float(h23 & 0xffff0000u);
        uint32_t so = (uint32_t)((r * SKW + c4) * 2);
        *(uint2*)(smc + P_WH + so) = make_uint2(h01, h23);
        *(uint2*)(smc + P_WL + so) = make_uint2(f2bf2(r0, r1), f2bf2(r2, r3));
    }
}
__device__ __forceinline__ void proj_mm(uint32_t sb, int wr, int lane, float (&c)[8][4]) {
    const uint32_t arow = (uint32_t)(wr + (lane & 7) + ((lane & 8) ? 8 : 0));
    const uint32_t acs = (lane & 16) ? 8u : 0u;
    const uint32_t brow = (uint32_t)(((lane & 16) ? 8 : 0) + (lane & 7));
    const uint32_t bcs = (lane & 8) ? 8u : 0u;
    #pragma unroll
    for (int kk = 0; kk < 4; kk++) {
        uint32_t xh[4], xl[4];
        ldm4(xh[0], xh[1], xh[2], xh[3], sb + P_XH + (arow * SKW + kk * 16 + acs) * 2);
        ldm4(xl[0], xl[1], xl[2], xl[3], sb + P_XL + (arow * SKW + kk * 16 + acs) * 2);
        #pragma unroll
        for (int p = 0; p < 4; p++) {
            uint32_t off = ((p * 16 + brow) * SKW + kk * 16 + bcs) * 2;
            uint32_t bh0, bh1, bh2, bh3, bl0, bl1, bl2, bl3;
            ldm4(bh0, bh1, bh2, bh3, sb + P_WH + off);
            ldm4(bl0, bl1, bl2, bl3, sb + P_WL + off);
            mma_bf16(c[2 * p],     xh[0], xh[1], xh[2], xh[3], bh0, bh1);
            mma_bf16(c[2 * p],     xh[0], xh[1], xh[2], xh[3], bl0, bl1);
            mma_bf16(c[2 * p],     xl[0], xl[1], xl[2], xl[3], bh0, bh1);
            mma_bf16(c[2 * p + 1], xh[0], xh[1], xh[2], xh[3], bh2, bh3);
            mma_bf16(c[2 * p + 1], xh[0], xh[1], xh[2], xh[3], bl2, bl3);
            mma_bf16(c[2 * p + 1], xl[0], xl[1], xl[2], xl[3], bh2, bh3);
        }
    }
}
__device__ __forceinline__ void proj_mm_regA(uint32_t sb, int lane,
                                             const uint32_t (&ah)[4][4], const uint32_t (&al)[4][4],
                                             float (&c)[8][4]) {
    const uint32_t brow = (uint32_t)(((lane & 16) ? 8 : 0) + (lane & 7));
    const uint32_t bcs = (lane & 8) ? 8u : 0u;
    #pragma unroll
    for (int kk = 0; kk < 4; kk++) {
        #pragma unroll
        for (int p = 0; p < 4; p++) {
            uint32_t off = ((p * 16 + brow) * SKW + kk * 16 + bcs) * 2;
            uint32_t bh0, bh1, bh2, bh3, bl0, bl1, bl2, bl3;
            ldm4(bh0, bh1, bh2, bh3, sb + P_WH + off);
            ldm4(bl0, bl1, bl2, bl3, sb + P_WL + off);
            mma_bf16(c[2 * p],     ah[kk][0], ah[kk][1], ah[kk][2], ah[kk][3], bh0, bh1);
            mma_bf16(c[2 * p],     ah[kk][0], ah[kk][1], ah[kk][2], ah[kk][3], bl0, bl1);
            mma_bf16(c[2 * p],     al[kk][0], al[kk][1], al[kk][2], al[kk][3], bh0, bh1);
            mma_bf16(c[2 * p + 1], ah[kk][0], ah[kk][1], ah[kk][2], ah[kk][3], bh2, bh3);
            mma_bf16(c[2 * p + 1], ah[kk][0], ah[kk][1], ah[kk][2], ah[kk][3], bl2, bl3);
            mma_bf16(c[2 * p + 1], al[kk][0], al[kk][1], al[kk][2], al[kk][3], bh2, bh3);
        }
    }
}

__global__ __launch_bounds__(256, 2) void proj_hmma(
    const float* __restrict__ keys, const float* __restrict__ queries,
    const float* __restrict__ Wk, const float* __restrict__ Wq, const float* __restrict__ Wv,
    const int* __restrict__ mask)
{
    extern __shared__ char smc[];
    const uint32_t sb = smem_u32(smc);
    const int t = threadIdx.x, w = t >> 5, lane = t & 31;
    const int grow = lane >> 2, qr = lane & 3;
    const int wr = w * 16;
    const int n = blockIdx.z, h = blockIdx.y, l0 = blockIdx.x * 128;
    const size_t hb = ((size_t)(n * NHEAD + h) * SEQ + l0) * HDIM;
    const size_t hbkv = ((size_t)(n * NHEAD + h) * KSTR + l0) * HDIM;
    const float* xq = queries + ((size_t)n * SEQ + l0) * EMBD + h * HDIM;
    const float* xk = keys    + ((size_t)n * SEQ + l0) * EMBD + h * HDIM;

    // ---- q ----
    proj_load_x(smc, xq, t);
    proj_load_w(smc, Wq, t);
    __syncthreads();
    float c[8][4];
    #pragma unroll
    for (int i = 0; i < 8; i++)
        #pragma unroll
        for (int j = 0; j < 4; j++) c[i][j] = 0.0f;
    proj_mm(sb, wr, lane, c);
    __syncthreads();

    uint32_t qh[4][4], ql[4][4];
    #pragma unroll
    for (int nt = 0; nt < 8; nt++) {
        uint32_t h0 = f2bf2(c[nt][0], c[nt][1]);
        uint32_t h1 = f2bf2(c[nt][2], c[nt][3]);
        float r0 = c[nt][0] - __uint_as_float(h0 << 16);
        float r1 = c[nt][1] - __uint_as_float(h0 & 0xffff0000u);
        float r2 = c[nt][2] - __uint_as_float(h1 << 16);
        float r3 = c[nt][3] - __uint_as_float(h1 & 0xffff0000u);
        qh[nt >> 1][(nt & 1) * 2 + 0] = h0;
        qh[nt >> 1][(nt & 1) * 2 + 1] = h1;
        ql[nt >> 1][(nt & 1) * 2 + 0] = f2bf2(r0, r1);
        ql[nt >> 1][(nt & 1) * 2 + 1] = f2bf2(r2, r3);
        int col = nt * 8 + qr * 2;
        *(uint32_t*)(g_qbf + hb + (size_t)(wr + grow) * HDIM + col) =
            f2bf2(c[nt][0] * ATT_SCALE, c[nt][1] * ATT_SCALE);
        *(uint32_t*)(g_qbf + hb + (size_t)(wr + grow + 8) * HDIM + col) =
            f2bf2(c[nt][2] * ATT_SCALE, c[nt][3] * ATT_SCALE);
    }

    // ---- k (pre-masked) ----
    proj_load_x(smc, xk, t);
    proj_load_w(smc, Wk, t);
    __syncthreads();
    #pragma unroll
    for (int i = 0; i < 8; i++)
        #pragma unroll
        for (int j = 0; j < 4; j++) c[i][j] = 0.0f;
    proj_mm(sb, wr, lane, c);
    __syncthreads();
    {
        const int* mrow = mask + n * SEQ + l0;
        const float mk0 = (float)mrow[wr + grow];
        const float mk1 = (float)mrow[wr + grow + 8];
        #pragma unroll
        for (int nt = 0; nt < 8; nt++) {
            int col = nt * 8 + qr * 2;
            *(uint32_t*)(g_kbf + hbkv + (size_t)(wr + grow) * HDIM + col) =
                f2bf2(c[nt][0] * mk0, c[nt][1] * mk0);
            *(uint32_t*)(g_kbf + hbkv + (size_t)(wr + grow + 8) * HDIM + col) =
                f2bf2(c[nt][2] * mk1, c[nt][3] * mk1);
        }
    }

    // ---- v = q Wv^T ----
    proj_load_w(smc, Wv, t);
    __syncthreads();
    #pragma unroll
    for (int i = 0; i < 8; i++)
        #pragma unroll
        for (int j = 0; j < 4; j++) c[i][j] = 0.0f;
    proj_mm_regA(sb, lane, qh, ql, c);
    #pragma unroll
    for (int nt = 0; nt < 8; nt++) {
        int col = nt * 8 + qr * 2;
        *(uint32_t*)(g_vbf + hbkv + (size_t)(wr + grow) * HDIM + col) = f2bf2(c[nt][0], c[nt][1]);
        *(uint32_t*)(g_vbf + hbkv + (size_t)(wr + grow + 8) * HDIM + col) = f2bf2(c[nt][2], c[nt][3]);
        *(float2*)(g_v + hb + (size_t)(wr + grow) * HDIM + col) = make_float2(c[nt][0], c[nt][1]);
        *(float2*)(g_v + hb + (size_t)(wr + grow + 8) * HDIM + col) = make_float2(c[nt][2], c[nt][3]);
    }
}

// ---------------------------------------------------------------------------
// Kernel 1b: masked V column sums + mask counts; also zeroes the k/v pad row
// ---------------------------------------------------------------------------
__global__ __launch_bounds__(256) void colsum_kernel(const int* __restrict__ mask)
{
    const int bid = blockIdx.x, y = blockIdx.y;
    if (y == 0 && threadIdx.x < 64) {
        size_t pz = ((size_t)bid * KSTR + SEQ) * HDIM + threadIdx.x;
        g_kbf[pz] = __float2bfloat16(0.0f);
        g_vbf[pz] = __float2bfloat16(0.0f);
    }
    const float* V = g_v + (size_t)bid * SEQ * HDIM + (size_t)y * 512 * HDIM;
    const int* mg = mask + (bid >> 4) * SEQ + y * 512;
    const int d = threadIdx.x & 63, grp = threadIdx.x >> 6;
    float s = 0.0f;
    int scnt = 0;
    const float* vp = V + (size_t)grp * 128 * HDIM + d;
    const int* mp = mg + grp * 128;
    #pragma unroll 8
    for (int cc = 0; cc < 128; cc++) {
        int m = mp[cc];
        s = fmaf((float)m, vp[(size_t)cc * HDIM], s);
        scnt += m;
    }
    __shared__ float red[256];
    __shared__ int redc[4];
    red[threadIdx.x] = s;
    if (d == 0) redc[grp] = scnt;
    __syncthreads();
    if (threadIdx.x < 64)
        g_sv4[((size_t)bid * 4 + y) * HDIM + threadIdx.x] =
            red[threadIdx.x] + red[64 + threadIdx.x] + red[128 + threadIdx.x] + red[192 + threadIdx.x];
    if (threadIdx.x == 0)
        g_mcnt[bid * 4 + y] = (float)(redc[0] + redc[1] + redc[2] + redc[3]);
}

// ---------------------------------------------------------------------------
// Kernel 2: HMMA flash attention over COMPACTED (unmasked-only) keys:
// ~half the tiles of the full sequence. Gathered K/V rows via cp.async.
// ---------------------------------------------------------------------------
#define A_KS0 0
#define A_KS1 18432
#define A_VS0 36864
#define A_VS1 55296
#define A_SVR 73728
#define A_CNT 73984
#define A_TOTAL 74048

__global__ __launch_bounds__(128, 3) void attn_hmma()
{
    extern __shared__ char smc[];
    const uint32_t sb = smem_u32(smc);
    const int t = threadIdx.x;
    const int w = t >> 5, lane = t & 31;
    const int grow = lane >> 2, qr = lane & 3;
    const int wr = w * 32;
    const int n = blockIdx.z, h = blockIdx.y, q0 = blockIdx.x * 128;
    const __nv_bfloat16* Qg = g_qbf + ((size_t)(n * NHEAD + h) * SEQ + q0) * HDIM;
    const __nv_bfloat16* Kg = g_kbf + (size_t)(n * NHEAD + h) * KSTR * HDIM;
    const __nv_bfloat16* Vg = g_vbf + (size_t)(n * NHEAD + h) * KSTR * HDIM;
    const int* cidx = g_cidx + n * CPAD;
    const int T = (g_ccnt[n] + 127) >> 7;

    for (int i = t; i < 1024; i += 128) {
        int r = i >> 3, ch = i & 7;
        int row = cidx[r];
        uint32_t so = (uint32_t)((r * SKW + ch * 8) * 2);
        cp16(sb + A_KS1 + so, Qg + r * 64 + ch * 8);
        cp16(sb + A_KS0 + so, Kg + (size_t)row * 64 + ch * 8);
        cp16(sb + A_VS0 + so, Vg + (size_t)row * 64 + ch * 8);
    }
    if (t < 64) {
        const float* s4 = g_sv4 + (size_t)(n * NHEAD + h) * 4 * HDIM;
        ((float*)(smc + A_SVR))[t] = s4[t] + s4[64 + t] + s4[128 + t] + s4[192 + t];
    }
    if (t < 4) ((float*)(smc + A_CNT))[t] = g_mcnt[(n * NHEAD + h) * 4 + t];
    CP_COMMIT();
    CP_WAIT(0);
    __syncthreads();

    uint32_t qf0[4][4], qf1[4][4];
    {
        uint32_t qrow = (uint32_t)(wr + (lane & 7) + ((lane & 8) ? 8 : 0));
        uint32_t qcs = (lane & 16) ? 8u : 0u;
        #pragma unroll
        for (int kk = 0; kk < 4; kk++) {
            ldm4(qf0[kk][0], qf0[kk][1], qf0[kk][2], qf0[kk][3],
                 sb + A_KS1 + (qrow * SKW + kk * 16 + qcs) * 2);
            ldm4(qf1[kk][0], qf1[kk][1], qf1[kk][2], qf1[kk][3],
                 sb + A_KS1 + ((qrow + 16) * SKW + kk * 16 + qcs) * 2);
        }
    }
    __syncthreads();

    float of0[9][4], of1[9][4];
    #pragma unroll
    for (int i = 0; i < 9; i++)
        #pragma unroll
        for (int j = 0; j < 4; j++) { of0[i][j] = 0.0f; of1[i][j] = 0.0f; }

    const uint32_t krow_b = (uint32_t)(lane & 7);
    const uint32_t ke = ((uint32_t)(lane >> 3)) * 8;
    const uint32_t vrow_b = (uint32_t)(((lane & 8) ? 8 : 0) + (lane & 7));
    const uint32_t vcs = (lane & 16) ? 8u : 0u;
    const uint32_t bones = (lane < 4) ? 0x3F803F80u : 0u;

    const __nv_bfloat162 C24 = __float2bfloat162_rn(4.1666667e-2f);
    const __nv_bfloat162 C6  = __float2bfloat162_rn(1.6666667e-1f);
    const __nv_bfloat162 C2  = __float2bfloat162_rn(0.5f);
    const __nv_bfloat162 C1  = __float2bfloat162_rn(1.0f);

    for (int tile = 0; tile < T; tile++) {
        if (tile) __syncthreads();

        if (tile + 1 < T) {
            const int kn = (tile + 1) * 128;
            uint32_t kbn = sb + ((tile + 1) & 1 ? A_KS1 : A_KS0);
            uint32_t vbn = sb + ((tile + 1) & 1 ? A_VS1 : A_VS0);
            for (int i = t; i < 1024; i += 128) {
                int r = i >> 3, ch = i & 7;
                int row = cidx[kn + r];
                uint32_t so = (uint32_t)((r * SKW + ch * 8) * 2);
                cp16(kbn + so, Kg + (size_t)row * 64 + ch * 8);
                cp16(vbn + so, Vg + (size_t)row * 64 + ch * 8);
            }
            CP_COMMIT();
            CP_WAIT(1);
        } else {
            CP_WAIT(0);
        }
        __syncthreads();

        const uint32_t kb = sb + (tile & 1 ? A_KS1 : A_KS0);
        const uint32_t vb = sb + (tile & 1 ? A_VS1 : A_VS0);

        #pragma unroll
        for (int kk = 0; kk < 8; kk++) {
            uint32_t p0[4], p1[4];
            #pragma unroll
            for (int half = 0; half < 2; half++) {
                const int ct = 2 * kk + half;
                float sa0[4] = {0.0f, 0.0f, 0.0f, 0.0f};
                float sa1[4] = {0.0f, 0.0f, 0.0f, 0.0f};
                uint32_t base = kb + ((ct * 8 + krow_b) * SKW + ke) * 2;
                uint32_t b0, b1, b2, b3, b4, b5, b6, b7;
                ldm4(b0, b1, b2, b3, base);
                ldm4(b4, b5, b6, b7, base + 64);
                mma_bf16(sa0, qf0[0][0], qf0[0][1], qf0[0][2], qf0[0][3], b0, b1);
                mma_bf16(sa1, qf1[0][0], qf1[0][1], qf1[0][2], qf1[0][3], b0, b1);
                mma_bf16(sa0, qf0[1][0], qf0[1][1], qf0[1][2], qf0[1][3], b2, b3);
                mma_bf16(sa1, qf1[1][0], qf1[1][1], qf1[1][2], qf1[1][3], b2, b3);
                mma_bf16(sa0, qf0[2][0], qf0[2][1], qf0[2][2], qf0[2][3], b4, b5);
                mma_bf16(sa1, qf1[2][0], qf1[2][1], qf1[2][2], qf1[2][3], b4, b5);
                mma_bf16(sa0, qf0[3][0], qf0[3][1], qf0[3][2], qf0[3][3], b6, b7);
                mma_bf16(sa1, qf1[3][0], qf1[3][1], qf1[3][2], qf1[3][3], b6, b7);

                __nv_bfloat162 x01, x23, y01, y23;
                *(uint32_t*)&x01 = f2bf2(sa0[0], sa0[1]);
                *(uint32_t*)&x23 = f2bf2(sa0[2], sa0[3]);
                *(uint32_t*)&y01 = f2bf2(sa1[0], sa1[1]);
                *(uint32_t*)&y23 = f2bf2(sa1[2], sa1[3]);
                __nv_bfloat162 d01 = __hmul2(x01, __hfma2(x01, __hfma2(x01, __hfma2(x01, C24, C6), C2), C1));
                __nv_bfloat162 d23 = __hmul2(x23, __hfma2(x23, __hfma2(x23, __hfma2(x23, C24, C6), C2), C1));
                __nv_bfloat162 e01 = __hmul2(y01, __hfma2(y01, __hfma2(y01, __hfma2(y01, C24, C6), C2), C1));
                __nv_bfloat162 e23 = __hmul2(y23, __hfma2(y23, __hfma2(y23, __hfma2(y23, C24, C6), C2), C1));
                p0[half * 2 + 0] = *(uint32_t*)&d01;
                p0[half * 2 + 1] = *(uint32_t*)&d23;
                p1[half * 2 + 0] = *(uint32_t*)&e01;
                p1[half * 2 + 1] = *(uint32_t*)&e23;
            }

            uint32_t rbase = vb + ((kk * 16 + vrow_b) * SKW + vcs) * 2;
            #pragma unroll
            for (int dg = 0; dg < 4; dg++) {
                uint32_t v0, v1, v2, v3;
                ldm4t(v0, v1, v2, v3, rbase + dg * 32);
                mma_bf16(of0[2 * dg],     p0[0], p0[1], p0[2], p0[3], v0, v1);
                mma_bf16(of1[2 * dg],     p1[0], p1[1], p1[2], p1[3], v0, v1);
                mma_bf16(of0[2 * dg + 1], p0[0], p0[1], p0[2], p0[3], v2, v3);
                mma_bf16(of1[2 * dg + 1], p1[0], p1[1], p1[2], p1[3], v2, v3);
            }
            mma_bf16(of0[8], p0[0], p0[1], p0[2], p0[3], bones, bones);
            mma_bf16(of1[8], p1[0], p1[1], p1[2], p1[3], bones, bones);
        }
    }

    const float* c4 = (const float*)(smc + A_CNT);
    const float cnt = c4[0] + c4[1] + c4[2] + c4[3];
    float sd00 = __shfl_sync(0xffffffffu, of0[8][0], lane & 28);
    float sd01 = __shfl_sync(0xffffffffu, of0[8][2], lane & 28);
    float sd10 = __shfl_sync(0xffffffffu, of1[8][0], lane & 28);
    float sd11 = __shfl_sync(0xffffffffu, of1[8][2], lane & 28);
    const float i00 = 1.0f / (cnt + sd00), i01 = 1.0f / (cnt + sd01);
    const float i10 = 1.0f / (cnt + sd10), i11 = 1.0f / (cnt + sd11);

    const float* sv = (const float*)(smc + A_SVR);
    const size_t rb = ((size_t)n * SEQ + q0 + wr + grow) * EMBD + h * HDIM;
    #pragma unroll
    for (int half = 0; half < 2; half++) {
        const float (*ofp)[4] = half ? of1 : of0;
        const float inv0 = half ? i10 : i00;
        const float inv1 = half ? i11 : i01;
        const size_t base0 = rb + (size_t)(half * 16) * EMBD;
        const size_t base1 = base0 + (size_t)8 * EMBD;
        #pragma unroll
        for (int dt = 0; dt < 8; dt++) {
            int j0 = dt * 8 + qr * 2;
            float o00 = (ofp[dt][0] + sv[j0]) * inv0;
            float o01 = (ofp[dt][1] + sv[j0 + 1]) * inv0;
            float o10 = (ofp[dt][2] + sv[j0]) * inv1;
            float o11 = (ofp[dt][3] + sv[j0 + 1]) * inv1;
            *(uint32_t*)(g_a16 + base0 + j0) = f2h2(o00, o01);
            *(uint32_t*)(g_a16 + base1 + j0) = f2h2(o10, o11);
        }
    }
}

// ---------------------------------------------------------------------------
// Kernel 3a: Wo -> fp16
// ---------------------------------------------------------------------------
__global__ __launch_bounds__(256) void wo_prep(const float* __restrict__ Wo)
{
    int i = (blockIdx.x * 256 + threadIdx.x) * 2;
    float2 wv = *(const float2*)(Wo + i);
    *(uint32_t*)(g_w16 + i) = f2h2(wv.x, wv.y);
}

// ---------------------------------------------------------------------------
// Kernel 3b: out = attn @ Wo^T + bo (single-pass fp16 MMA, 2 CTAs/SM, 1 wave)
// ---------------------------------------------------------------------------
#define O_A 0
#define O_W 18432
#define O_STAGE 36864
#define O_TOTAL (2 * O_STAGE)

__global__ __launch_bounds__(256, 2) void out_hmma(const float* __restrict__ bo, float* __restrict__ out)
{
    extern __shared__ char smc[];
    const uint32_t sb = smem_u32(smc);
    const int t = threadIdx.x;
    const int w = t >> 5, lane = t & 31;
    const int grow = lane >> 2, qr = lane & 3;
    const int o0 = blockIdx.x * 128, m0 = blockIdx.y * 128;
    const int my = (w >> 2) * 64, ox = (w & 3) * 32;

    const __half* Ag = g_a16 + (size_t)m0 * EMBD;
    const __half* Wg = g_w16 + (size_t)o0 * EMBD;

    for (int i = t; i < 1024; i += 256) {
        int r = i >> 3, ch = i & 7;
        uint32_t so = (uint32_t)((r * SKW + ch * 8) * 2);
        size_t go = (size_t)r * EMBD + ch * 8;
        cp16(sb + O_A + so, Ag + go);
        cp16(sb + O_W + so, Wg + go);
    }
    CP_COMMIT();

    float cf[4][4][4];
    #pragma unroll
    for (int i = 0; i < 4; i++)
        #pragma unroll
        for (int j = 0; j < 4; j++)
            #pragma unroll
            for (int k = 0; k < 4; k++) cf[i][j][k] = 0.0f;

    const uint32_t arow = (uint32_t)(my + (lane & 7) + ((lane & 8) ? 8 : 0));
    const uint32_t acs = (lane & 16) ? 8u : 0u;
    const uint32_t brow = (uint32_t)(ox + ((lane & 16) ? 8 : 0) + (lane & 7));
    const uint32_t bcs = (lane & 8) ? 8u : 0u;

    for (int ec = 0; ec < 16; ec++) {
        if (ec) __syncthreads();

        if (ec < 15) {
            uint32_t stage = sb + ((ec + 1) & 1) * O_STAGE;
            size_t gb = (size_t)(ec + 1) * 64;
            for (int i = t; i < 1024; i += 256) {
                int r = i >> 3, ch = i & 7;
                uint32_t so = (uint32_t)((r * SKW + ch * 8) * 2);
                size_t go = (size_t)r * EMBD + gb + ch * 8;
                cp16(stage + O_A + so, Ag + go);
                cp16(stage + O_W + so, Wg + go);
            }
            CP_COMMIT();
            CP_WAIT(1);
        } else {
            CP_WAIT(0);
        }
        __syncthreads();

        const uint32_t st = sb + (ec & 1) * O_STAGE;
        #pragma unroll
        for (int kk = 0; kk < 4; kk++) {
            uint32_t ah[4][4], bh[4][2];
            #pragma unroll
            for (int mt = 0; mt < 4; mt++) {
                uint32_t off = (((arow + mt * 16) * SKW) + kk * 16 + acs) * 2;
                ldm4(ah[mt][0], ah[mt][1], ah[mt][2], ah[mt][3], st + O_A + off);
            }
            #pragma unroll
            for (int p = 0; p < 2; p++) {
                uint32_t off = (((brow + p * 16) * SKW) + kk * 16 + bcs) * 2;
                ldm4(bh[2 * p][0], bh[2 * p][1], bh[2 * p + 1][0], bh[2 * p + 1][1], st + O_W + off);
            }
            #pragma unroll
            for (int mt = 0; mt < 4; mt++)
                #pragma unroll
                for (int nt = 0; nt < 4; nt++)
                    mma_fp16(cf[mt][nt], ah[mt][0], ah[mt][1], ah[mt][2], ah[mt][3], bh[nt][0], bh[nt][1]);
        }
    }

    #pragma unroll
    for (int mt = 0; mt < 4; mt++) {
        int row = m0 + my + mt * 16 + grow;
        #pragma unroll
        for (int nt = 0; nt < 4; nt++) {
            int col = o0 + ox + nt * 8 + qr * 2;
            float b0 = bo[col], b1 = bo[col + 1];
            *(float2*)(out + (size_t)row * EMBD + col) =
                make_float2(cf[mt][nt][0] + b0, cf[mt][nt][1] + b1);
            *(float2*)(out + (size_t)(row + 8) * EMBD + col) =
                make_float2(cf[mt][nt][2] + b0, cf[mt][nt][3] + b1);
        }
    }
}

// ---------------------------------------------------------------------------
extern "C" void kernel_launch(void* const* d_in, const int* in_sizes, int n_in,
                              void* d_out, int out_size)
{
    const float* keys    = (const float*)d_in[0];
    const float* queries = (const float*)d_in[1];
    const int*   mask    = (const int*)d_in[3];
    const float* Wk      = (const float*)d_in[4];
    const float* Wq      = (const float*)d_in[5];
    const float* Wv      = (const float*)d_in[6];
    const float* Wo      = (const float*)d_in[7];
    const float* bo      = (const float*)d_in[8];
    float* out = (float*)d_out;

    cudaFuncSetAttribute(proj_hmma, cudaFuncAttributeMaxDynamicSharedMemorySize, P_TOTAL);
    cudaFuncSetAttribute(attn_hmma, cudaFuncAttributeMaxDynamicSharedMemorySize, A_TOTAL);
    cudaFuncSetAttribute(out_hmma, cudaFuncAttributeMaxDynamicSharedMemorySize, O_TOTAL);

    compact_kernel<<<NBATCH, 256>>>(mask);
    dim3 gp(SEQ / 128, NHEAD, NBATCH);
    proj_hmma<<<gp, 256, P_TOTAL>>>(keys, queries, Wk, Wq, Wv, mask);
    dim3 gc(NBATCH * NHEAD, 4);
    colsum_kernel<<<gc, 256>>>(mask);
    wo_prep<<<(EMBD * EMBD) / 512, 256>>>(Wo);
    dim3 ga(SEQ / 128, NHEAD, NBATCH);
    attn_hmma<<<ga, 128, A_TOTAL>>>();
    dim3 go(EMBD / 128, NBATCH * SEQ / 128);
    out_hmma<<<go, 256, O_TOTAL>>>(bo, out);
}

// round 15
// speedup vs baseline: 2.4712x; 1.0596x over previous
#include <cuda_runtime.h>
#include <cuda_bf16.h>
#include <cuda_fp16.h>
#include <math.h>
#include <stdint.h>

#define NBATCH 2
#define SEQ 2048
#define EMBD 1024
#define NHEAD 16
#define HDIM 64
#define ATT_SCALE 0.03125f
#define SKW 72                    // 16-bit smem row stride: 16B-aligned, ldmatrix conflict-free
#define KSTR (SEQ + 8)            // k/v per-head row stride; row SEQ is the zero pad row
#define CPAD (SEQ + 128)

// scratch
__device__ float g_v[(size_t)NBATCH * NHEAD * SEQ * HDIM];            // fp32 V (colsum source)
__device__ float g_sv4[(size_t)NBATCH * NHEAD * 4 * HDIM];            // partial masked colsums
__device__ float g_mcnt[(size_t)NBATCH * NHEAD * 4];                  // partial mask counts
__device__ int   g_cidx[(size_t)NBATCH * CPAD];                       // compacted unmasked key idx
__device__ int   g_ccnt[NBATCH];                                      // unmasked counts
__device__ __half g_q16[(size_t)NBATCH * NHEAD * SEQ * HDIM];         // pre-scaled by 1/32
__device__ __half g_k16[(size_t)NBATCH * NHEAD * KSTR * HDIM];        // pre-masked (k * mask)
__device__ __half g_v16[(size_t)NBATCH * NHEAD * KSTR * HDIM];
__device__ __half g_a16[(size_t)NBATCH * SEQ * EMBD];                 // attn output, fp16
__device__ __half g_w16[(size_t)EMBD * EMBD];                         // Wo, fp16

// ===================== helpers =====================
__device__ __forceinline__ uint32_t smem_u32(const void* p) {
    uint32_t a;
    asm("{ .reg .u64 t; cvta.to.shared.u64 t, %1; cvt.u32.u64 %0, t; }" : "=r"(a) : "l"(p));
    return a;
}
__device__ __forceinline__ void cp16(uint32_t s, const void* g) {
    asm volatile("cp.async.ca.shared.global [%0], [%1], 16;" :: "r"(s), "l"(g));
}
#define CP_COMMIT() asm volatile("cp.async.commit_group;" ::: "memory")
#define CP_WAIT(n)  asm volatile("cp.async.wait_group %0;" :: "n"(n) : "memory")

__device__ __forceinline__ void mma_fp16(float* c, uint32_t a0, uint32_t a1, uint32_t a2, uint32_t a3,
                                         uint32_t b0, uint32_t b1) {
    asm volatile("mma.sync.aligned.m16n8k16.row.col.f32.f16.f16.f32 "
                 "{%0,%1,%2,%3}, {%4,%5,%6,%7}, {%8,%9}, {%0,%1,%2,%3};"
                 : "+f"(c[0]), "+f"(c[1]), "+f"(c[2]), "+f"(c[3])
                 : "r"(a0), "r"(a1), "r"(a2), "r"(a3), "r"(b0), "r"(b1));
}
__device__ __forceinline__ void ldm4(uint32_t& r0, uint32_t& r1, uint32_t& r2, uint32_t& r3, uint32_t a) {
    asm volatile("ldmatrix.sync.aligned.m8n8.x4.shared.b16 {%0,%1,%2,%3}, [%4];"
                 : "=r"(r0), "=r"(r1), "=r"(r2), "=r"(r3) : "r"(a));
}
__device__ __forceinline__ void ldm4t(uint32_t& r0, uint32_t& r1, uint32_t& r2, uint32_t& r3, uint32_t a) {
    asm volatile("ldmatrix.sync.aligned.m8n8.x4.trans.shared.b16 {%0,%1,%2,%3}, [%4];"
                 : "=r"(r0), "=r"(r1), "=r"(r2), "=r"(r3) : "r"(a));
}
__device__ __forceinline__ uint32_t f2h2(float lo, float hi) {
    uint32_t u;
    asm("cvt.rn.f16x2.f32 %0, %1, %2;" : "=r"(u) : "f"(hi), "f"(lo));
    return u;
}

// ---------------------------------------------------------------------------
// Kernel 0: build compacted unmasked-key index list per batch
// ---------------------------------------------------------------------------
__global__ __launch_bounds__(256) void compact_kernel(const int* __restrict__ mask)
{
    const int n = blockIdx.x, t = threadIdx.x;
    const int* m = mask + n * SEQ;
    int v[8];
    int c = 0;
    #pragma unroll
    for (int j = 0; j < 8; j++) { v[j] = m[t * 8 + j]; c += v[j]; }
    __shared__ int s[256];
    s[t] = c;
    __syncthreads();
    for (int off = 1; off < 256; off <<= 1) {
        int x = (t >= off) ? s[t - off] : 0;
        __syncthreads();
        s[t] += x;
        __syncthreads();
    }
    int pos = s[t] - c;
    #pragma unroll
    for (int j = 0; j < 8; j++)
        if (v[j]) g_cidx[n * CPAD + pos++] = t * 8 + j;
    __syncthreads();
    const int total = s[255];
    if (t == 0) g_ccnt[n] = total;
    const int padded = (total + 127) & ~127;
    for (int i = total + t; i < padded; i += 256)
        g_cidx[n * CPAD + i] = SEQ;                 // points at the zeroed pad row
}

// ---------------------------------------------------------------------------
// Kernel 1: projections via single-pass fp16 HMMA. 128 rows x one head/block.
// ---------------------------------------------------------------------------
#define P_X 0
#define P_W 18432
#define P_TOTAL 27648

__device__ __forceinline__ void proj_load_x16(char* smc, const float* __restrict__ x, int t) {
    for (int i = t; i < 2048; i += 256) {
        int r = i >> 4, c4 = (i & 15) * 4;
        float4 v = *(const float4*)(x + (size_t)r * EMBD + c4);
        uint32_t so = (uint32_t)((r * SKW + c4) * 2);
        *(uint2*)(smc + P_X + so) = make_uint2(f2h2(v.x, v.y), f2h2(v.z, v.w));
    }
}
__device__ __forceinline__ void proj_load_w16(char* smc, const float* __restrict__ W, int t) {
    for (int i = t; i < 1024; i += 256) {
        int r = i >> 4, c4 = (i & 15) * 4;
        float4 v = *(const float4*)(W + r * 64 + c4);
        uint32_t so = (uint32_t)((r * SKW + c4) * 2);
        *(uint2*)(smc + P_W + so) = make_uint2(f2h2(v.x, v.y), f2h2(v.z, v.w));
    }
}
__device__ __forceinline__ void proj_mm16(uint32_t sb, int wr, int lane, float (&c)[8][4]) {
    const uint32_t arow = (uint32_t)(wr + (lane & 7) + ((lane & 8) ? 8 : 0));
    const uint32_t acs = (lane & 16) ? 8u : 0u;
    const uint32_t brow = (uint32_t)(((lane & 16) ? 8 : 0) + (lane & 7));
    const uint32_t bcs = (lane & 8) ? 8u : 0u;
    #pragma unroll
    for (int kk = 0; kk < 4; kk++) {
        uint32_t xa[4];
        ldm4(xa[0], xa[1], xa[2], xa[3], sb + P_X + (arow * SKW + kk * 16 + acs) * 2);
        #pragma unroll
        for (int p = 0; p < 4; p++) {
            uint32_t off = ((p * 16 + brow) * SKW + kk * 16 + bcs) * 2;
            uint32_t b0, b1, b2, b3;
            ldm4(b0, b1, b2, b3, sb + P_W + off);
            mma_fp16(c[2 * p],     xa[0], xa[1], xa[2], xa[3], b0, b1);
            mma_fp16(c[2 * p + 1], xa[0], xa[1], xa[2], xa[3], b2, b3);
        }
    }
}
__device__ __forceinline__ void proj_mm16_regA(uint32_t sb, int lane,
                                               const uint32_t (&ah)[4][4], float (&c)[8][4]) {
    const uint32_t brow = (uint32_t)(((lane & 16) ? 8 : 0) + (lane & 7));
    const uint32_t bcs = (lane & 8) ? 8u : 0u;
    #pragma unroll
    for (int kk = 0; kk < 4; kk++) {
        #pragma unroll
        for (int p = 0; p < 4; p++) {
            uint32_t off = ((p * 16 + brow) * SKW + kk * 16 + bcs) * 2;
            uint32_t b0, b1, b2, b3;
            ldm4(b0, b1, b2, b3, sb + P_W + off);
            mma_fp16(c[2 * p],     ah[kk][0], ah[kk][1], ah[kk][2], ah[kk][3], b0, b1);
            mma_fp16(c[2 * p + 1], ah[kk][0], ah[kk][1], ah[kk][2], ah[kk][3], b2, b3);
        }
    }
}

__global__ __launch_bounds__(256, 2) void proj_hmma(
    const float* __restrict__ keys, const float* __restrict__ queries,
    const float* __restrict__ Wk, const float* __restrict__ Wq, const float* __restrict__ Wv,
    const int* __restrict__ mask)
{
    extern __shared__ char smc[];
    const uint32_t sb = smem_u32(smc);
    const int t = threadIdx.x, w = t >> 5, lane = t & 31;
    const int grow = lane >> 2, qr = lane & 3;
    const int wr = w * 16;
    const int n = blockIdx.z, h = blockIdx.y, l0 = blockIdx.x * 128;
    const size_t hb = ((size_t)(n * NHEAD + h) * SEQ + l0) * HDIM;
    const size_t hbkv = ((size_t)(n * NHEAD + h) * KSTR + l0) * HDIM;
    const float* xq = queries + ((size_t)n * SEQ + l0) * EMBD + h * HDIM;
    const float* xk = keys    + ((size_t)n * SEQ + l0) * EMBD + h * HDIM;

    // ---- q ----
    proj_load_x16(smc, xq, t);
    proj_load_w16(smc, Wq, t);
    __syncthreads();
    float c[8][4];
    #pragma unroll
    for (int i = 0; i < 8; i++)
        #pragma unroll
        for (int j = 0; j < 4; j++) c[i][j] = 0.0f;
    proj_mm16(sb, wr, lane, c);
    __syncthreads();

    uint32_t qh[4][4];
    #pragma unroll
    for (int nt = 0; nt < 8; nt++) {
        qh[nt >> 1][(nt & 1) * 2 + 0] = f2h2(c[nt][0], c[nt][1]);
        qh[nt >> 1][(nt & 1) * 2 + 1] = f2h2(c[nt][2], c[nt][3]);
        int col = nt * 8 + qr * 2;
        *(uint32_t*)(g_q16 + hb + (size_t)(wr + grow) * HDIM + col) =
            f2h2(c[nt][0] * ATT_SCALE, c[nt][1] * ATT_SCALE);
        *(uint32_t*)(g_q16 + hb + (size_t)(wr + grow + 8) * HDIM + col) =
            f2h2(c[nt][2] * ATT_SCALE, c[nt][3] * ATT_SCALE);
    }

    // ---- k (pre-masked) ----
    proj_load_x16(smc, xk, t);
    proj_load_w16(smc, Wk, t);
    __syncthreads();
    #pragma unroll
    for (int i = 0; i < 8; i++)
        #pragma unroll
        for (int j = 0; j < 4; j++) c[i][j] = 0.0f;
    proj_mm16(sb, wr, lane, c);
    __syncthreads();
    {
        const int* mrow = mask + n * SEQ + l0;
        const float mk0 = (float)mrow[wr + grow];
        const float mk1 = (float)mrow[wr + grow + 8];
        #pragma unroll
        for (int nt = 0; nt < 8; nt++) {
            int col = nt * 8 + qr * 2;
            *(uint32_t*)(g_k16 + hbkv + (size_t)(wr + grow) * HDIM + col) =
                f2h2(c[nt][0] * mk0, c[nt][1] * mk0);
            *(uint32_t*)(g_k16 + hbkv + (size_t)(wr + grow + 8) * HDIM + col) =
                f2h2(c[nt][2] * mk1, c[nt][3] * mk1);
        }
    }

    // ---- v = q Wv^T ----
    proj_load_w16(smc, Wv, t);
    __syncthreads();
    #pragma unroll
    for (int i = 0; i < 8; i++)
        #pragma unroll
        for (int j = 0; j < 4; j++) c[i][j] = 0.0f;
    proj_mm16_regA(sb, lane, qh, c);
    #pragma unroll
    for (int nt = 0; nt < 8; nt++) {
        int col = nt * 8 + qr * 2;
        *(uint32_t*)(g_v16 + hbkv + (size_t)(wr + grow) * HDIM + col) = f2h2(c[nt][0], c[nt][1]);
        *(uint32_t*)(g_v16 + hbkv + (size_t)(wr + grow + 8) * HDIM + col) = f2h2(c[nt][2], c[nt][3]);
        *(float2*)(g_v + hb + (size_t)(wr + grow) * HDIM + col) = make_float2(c[nt][0], c[nt][1]);
        *(float2*)(g_v + hb + (size_t)(wr + grow + 8) * HDIM + col) = make_float2(c[nt][2], c[nt][3]);
    }
}

// ---------------------------------------------------------------------------
// Kernel 1b: masked V column sums + mask counts; also zeroes the k/v pad row
// ---------------------------------------------------------------------------
__global__ __launch_bounds__(256) void colsum_kernel(const int* __restrict__ mask)
{
    const int bid = blockIdx.x, y = blockIdx.y;
    if (y == 0 && threadIdx.x < 64) {
        size_t pz = ((size_t)bid * KSTR + SEQ) * HDIM + threadIdx.x;
        g_k16[pz] = __float2half(0.0f);
        g_v16[pz] = __float2half(0.0f);
    }
    const float* V = g_v + (size_t)bid * SEQ * HDIM + (size_t)y * 512 * HDIM;
    const int* mg = mask + (bid >> 4) * SEQ + y * 512;
    const int d = threadIdx.x & 63, grp = threadIdx.x >> 6;
    float s = 0.0f;
    int scnt = 0;
    const float* vp = V + (size_t)grp * 128 * HDIM + d;
    const int* mp = mg + grp * 128;
    #pragma unroll 8
    for (int cc = 0; cc < 128; cc++) {
        int m = mp[cc];
        s = fmaf((float)m, vp[(size_t)cc * HDIM], s);
        scnt += m;
    }
    __shared__ float red[256];
    __shared__ int redc[4];
    red[threadIdx.x] = s;
    if (d == 0) redc[grp] = scnt;
    __syncthreads();
    if (threadIdx.x < 64)
        g_sv4[((size_t)bid * 4 + y) * HDIM + threadIdx.x] =
            red[threadIdx.x] + red[64 + threadIdx.x] + red[128 + threadIdx.x] + red[192 + threadIdx.x];
    if (threadIdx.x == 0)
        g_mcnt[bid * 4 + y] = (float)(redc[0] + redc[1] + redc[2] + redc[3]);
}

// ---------------------------------------------------------------------------
// Kernel 2: fp16 HMMA flash attention over COMPACTED keys.
// ---------------------------------------------------------------------------
#define A_KS0 0
#define A_KS1 18432
#define A_VS0 36864
#define A_VS1 55296
#define A_SVR 73728
#define A_CNT 73984
#define A_TOTAL 74048

__global__ __launch_bounds__(128, 3) void attn_hmma()
{
    extern __shared__ char smc[];
    const uint32_t sb = smem_u32(smc);
    const int t = threadIdx.x;
    const int w = t >> 5, lane = t & 31;
    const int grow = lane >> 2, qr = lane & 3;
    const int wr = w * 32;
    const int n = blockIdx.z, h = blockIdx.y, q0 = blockIdx.x * 128;
    const __half* Qg = g_q16 + ((size_t)(n * NHEAD + h) * SEQ + q0) * HDIM;
    const __half* Kg = g_k16 + (size_t)(n * NHEAD + h) * KSTR * HDIM;
    const __half* Vg = g_v16 + (size_t)(n * NHEAD + h) * KSTR * HDIM;
    const int* cidx = g_cidx + n * CPAD;
    const int T = (g_ccnt[n] + 127) >> 7;

    for (int i = t; i < 1024; i += 128) {
        int r = i >> 3, ch = i & 7;
        int row = cidx[r];
        uint32_t so = (uint32_t)((r * SKW + ch * 8) * 2);
        cp16(sb + A_KS1 + so, Qg + r * 64 + ch * 8);
        cp16(sb + A_KS0 + so, Kg + (size_t)row * 64 + ch * 8);
        cp16(sb + A_VS0 + so, Vg + (size_t)row * 64 + ch * 8);
    }
    if (t < 64) {
        const float* s4 = g_sv4 + (size_t)(n * NHEAD + h) * 4 * HDIM;
        ((float*)(smc + A_SVR))[t] = s4[t] + s4[64 + t] + s4[128 + t] + s4[192 + t];
    }
    if (t < 4) ((float*)(smc + A_CNT))[t] = g_mcnt[(n * NHEAD + h) * 4 + t];
    CP_COMMIT();
    CP_WAIT(0);
    __syncthreads();

    uint32_t qf0[4][4], qf1[4][4];
    {
        uint32_t qrow = (uint32_t)(wr + (lane & 7) + ((lane & 8) ? 8 : 0));
        uint32_t qcs = (lane & 16) ? 8u : 0u;
        #pragma unroll
        for (int kk = 0; kk < 4; kk++) {
            ldm4(qf0[kk][0], qf0[kk][1], qf0[kk][2], qf0[kk][3],
                 sb + A_KS1 + (qrow * SKW + kk * 16 + qcs) * 2);
            ldm4(qf1[kk][0], qf1[kk][1], qf1[kk][2], qf1[kk][3],
                 sb + A_KS1 + ((qrow + 16) * SKW + kk * 16 + qcs) * 2);
        }
    }
    __syncthreads();

    float of0[9][4], of1[9][4];
    #pragma unroll
    for (int i = 0; i < 9; i++)
        #pragma unroll
        for (int j = 0; j < 4; j++) { of0[i][j] = 0.0f; of1[i][j] = 0.0f; }

    const uint32_t krow_b = (uint32_t)(lane & 7);
    const uint32_t ke = ((uint32_t)(lane >> 3)) * 8;
    const uint32_t vrow_b = (uint32_t)(((lane & 8) ? 8 : 0) + (lane & 7));
    const uint32_t vcs = (lane & 16) ? 8u : 0u;
    const uint32_t bones = (lane < 4) ? 0x3C003C00u : 0u;   // fp16 ones in B column 0

    const __half2 C24 = __float2half2_rn(4.1666667e-2f);
    const __half2 C6  = __float2half2_rn(1.6666667e-1f);
    const __half2 C2  = __float2half2_rn(0.5f);
    const __half2 C1  = __float2half2_rn(1.0f);

    for (int tile = 0; tile < T; tile++) {
        if (tile) __syncthreads();

        if (tile + 1 < T) {
            const int kn = (tile + 1) * 128;
            uint32_t kbn = sb + ((tile + 1) & 1 ? A_KS1 : A_KS0);
            uint32_t vbn = sb + ((tile + 1) & 1 ? A_VS1 : A_VS0);
            for (int i = t; i < 1024; i += 128) {
                int r = i >> 3, ch = i & 7;
                int row = cidx[kn + r];
                uint32_t so = (uint32_t)((r * SKW + ch * 8) * 2);
                cp16(kbn + so, Kg + (size_t)row * 64 + ch * 8);
                cp16(vbn + so, Vg + (size_t)row * 64 + ch * 8);
            }
            CP_COMMIT();
            CP_WAIT(1);
        } else {
            CP_WAIT(0);
        }
        __syncthreads();

        const uint32_t kb = sb + (tile & 1 ? A_KS1 : A_KS0);
        const uint32_t vb = sb + (tile & 1 ? A_VS1 : A_VS0);

        #pragma unroll
        for (int kk = 0; kk < 8; kk++) {
            uint32_t p0[4], p1[4];
            #pragma unroll
            for (int half = 0; half < 2; half++) {
                const int ct = 2 * kk + half;
                float sa0[4] = {0.0f, 0.0f, 0.0f, 0.0f};
                float sa1[4] = {0.0f, 0.0f, 0.0f, 0.0f};
                uint32_t base = kb + ((ct * 8 + krow_b) * SKW + ke) * 2;
                uint32_t b0, b1, b2, b3, b4, b5, b6, b7;
                ldm4(b0, b1, b2, b3, base);
                ldm4(b4, b5, b6, b7, base + 64);
                mma_fp16(sa0, qf0[0][0], qf0[0][1], qf0[0][2], qf0[0][3], b0, b1);
                mma_fp16(sa1, qf1[0][0], qf1[0][1], qf1[0][2], qf1[0][3], b0, b1);
                mma_fp16(sa0, qf0[1][0], qf0[1][1], qf0[1][2], qf0[1][3], b2, b3);
                mma_fp16(sa1, qf1[1][0], qf1[1][1], qf1[1][2], qf1[1][3], b2, b3);
                mma_fp16(sa0, qf0[2][0], qf0[2][1], qf0[2][2], qf0[2][3], b4, b5);
                mma_fp16(sa1, qf1[2][0], qf1[2][1], qf1[2][2], qf1[2][3], b4, b5);
                mma_fp16(sa0, qf0[3][0], qf0[3][1], qf0[3][2], qf0[3][3], b6, b7);
                mma_fp16(sa1, qf1[3][0], qf1[3][1], qf1[3][2], qf1[3][3], b6, b7);

                __half2 x01, x23, y01, y23;
                *(uint32_t*)&x01 = f2h2(sa0[0], sa0[1]);
                *(uint32_t*)&x23 = f2h2(sa0[2], sa0[3]);
                *(uint32_t*)&y01 = f2h2(sa1[0], sa1[1]);
                *(uint32_t*)&y23 = f2h2(sa1[2], sa1[3]);
                __half2 d01 = __hmul2(x01, __hfma2(x01, __hfma2(x01, __hfma2(x01, C24, C6), C2), C1));
                __half2 d23 = __hmul2(x23, __hfma2(x23, __hfma2(x23, __hfma2(x23, C24, C6), C2), C1));
                __half2 e01 = __hmul2(y01, __hfma2(y01, __hfma2(y01, __hfma2(y01, C24, C6), C2), C1));
                __half2 e23 = __hmul2(y23, __hfma2(y23, __hfma2(y23, __hfma2(y23, C24, C6), C2), C1));
                p0[half * 2 + 0] = *(uint32_t*)&d01;
                p0[half * 2 + 1] = *(uint32_t*)&d23;
                p1[half * 2 + 0] = *(uint32_t*)&e01;
                p1[half * 2 + 1] = *(uint32_t*)&e23;
            }

            uint32_t rbase = vb + ((kk * 16 + vrow_b) * SKW + vcs) * 2;
            #pragma unroll
            for (int dg = 0; dg < 4; dg++) {
                uint32_t v0, v1, v2, v3;
                ldm4t(v0, v1, v2, v3, rbase + dg * 32);
                mma_fp16(of0[2 * dg],     p0[0], p0[1], p0[2], p0[3], v0, v1);
                mma_fp16(of1[2 * dg],     p1[0], p1[1], p1[2], p1[3], v0, v1);
                mma_fp16(of0[2 * dg + 1], p0[0], p0[1], p0[2], p0[3], v2, v3);
                mma_fp16(of1[2 * dg + 1], p1[0], p1[1], p1[2], p1[3], v2, v3);
            }
            mma_fp16(of0[8], p0[0], p0[1], p0[2], p0[3], bones, bones);
            mma_fp16(of1[8], p1[0], p1[1], p1[2], p1[3], bones, bones);
        }
    }

    const float* c4 = (const float*)(smc + A_CNT);
    const float cnt = c4[0] + c4[1] + c4[2] + c4[3];
    float sd00 = __shfl_sync(0xffffffffu, of0[8][0], lane & 28);
    float sd01 = __shfl_sync(0xffffffffu, of0[8][2], lane & 28);
    float sd10 = __shfl_sync(0xffffffffu, of1[8][0], lane & 28);
    float sd11 = __shfl_sync(0xffffffffu, of1[8][2], lane & 28);
    const float i00 = 1.0f / (cnt + sd00), i01 = 1.0f / (cnt + sd01);
    const float i10 = 1.0f / (cnt + sd10), i11 = 1.0f / (cnt + sd11);

    const float* sv = (const float*)(smc + A_SVR);
    const size_t rb = ((size_t)n * SEQ + q0 + wr + grow) * EMBD + h * HDIM;
    #pragma unroll
    for (int half = 0; half < 2; half++) {
        const float (*ofp)[4] = half ? of1 : of0;
        const float inv0 = half ? i10 : i00;
        const float inv1 = half ? i11 : i01;
        const size_t base0 = rb + (size_t)(half * 16) * EMBD;
        const size_t base1 = base0 + (size_t)8 * EMBD;
        #pragma unroll
        for (int dt = 0; dt < 8; dt++) {
            int j0 = dt * 8 + qr * 2;
            float o00 = (ofp[dt][0] + sv[j0]) * inv0;
            float o01 = (ofp[dt][1] + sv[j0 + 1]) * inv0;
            float o10 = (ofp[dt][2] + sv[j0]) * inv1;
            float o11 = (ofp[dt][3] + sv[j0 + 1]) * inv1;
            *(uint32_t*)(g_a16 + base0 + j0) = f2h2(o00, o01);
            *(uint32_t*)(g_a16 + base1 + j0) = f2h2(o10, o11);
        }
    }
}

// ---------------------------------------------------------------------------
// Kernel 3a: Wo -> fp16
// ---------------------------------------------------------------------------
__global__ __launch_bounds__(256) void wo_prep(const float* __restrict__ Wo)
{
    int i = (blockIdx.x * 256 + threadIdx.x) * 2;
    float2 wv = *(const float2*)(Wo + i);
    *(uint32_t*)(g_w16 + i) = f2h2(wv.x, wv.y);
}

// ---------------------------------------------------------------------------
// Kernel 3b: out = attn @ Wo^T + bo (single-pass fp16 MMA, 2 CTAs/SM, 1 wave)
// ---------------------------------------------------------------------------
#define O_A 0
#define O_W 18432
#define O_STAGE 36864
#define O_TOTAL (2 * O_STAGE)

__global__ __launch_bounds__(256, 2) void out_hmma(const float* __restrict__ bo, float* __restrict__ out)
{
    extern __shared__ char smc[];
    const uint32_t sb = smem_u32(smc);
    const int t = threadIdx.x;
    const int w = t >> 5, lane = t & 31;
    const int grow = lane >> 2, qr = lane & 3;
    const int o0 = blockIdx.x * 128, m0 = blockIdx.y * 128;
    const int my = (w >> 2) * 64, ox = (w & 3) * 32;

    const __half* Ag = g_a16 + (size_t)m0 * EMBD;
    const __half* Wg = g_w16 + (size_t)o0 * EMBD;

    for (int i = t; i < 1024; i += 256) {
        int r = i >> 3, ch = i & 7;
        uint32_t so = (uint32_t)((r * SKW + ch * 8) * 2);
        size_t go = (size_t)r * EMBD + ch * 8;
        cp16(sb + O_A + so, Ag + go);
        cp16(sb + O_W + so, Wg + go);
    }
    CP_COMMIT();

    float cf[4][4][4];
    #pragma unroll
    for (int i = 0; i < 4; i++)
        #pragma unroll
        for (int j = 0; j < 4; j++)
            #pragma unroll
            for (int k = 0; k < 4; k++) cf[i][j][k] = 0.0f;

    const uint32_t arow = (uint32_t)(my + (lane & 7) + ((lane & 8) ? 8 : 0));
    const uint32_t acs = (lane & 16) ? 8u : 0u;
    const uint32_t brow = (uint32_t)(ox + ((lane & 16) ? 8 : 0) + (lane & 7));
    const uint32_t bcs = (lane & 8) ? 8u : 0u;

    for (int ec = 0; ec < 16; ec++) {
        if (ec) __syncthreads();

        if (ec < 15) {
            uint32_t stage = sb + ((ec + 1) & 1) * O_STAGE;
            size_t gb = (size_t)(ec + 1) * 64;
            for (int i = t; i < 1024; i += 256) {
                int r = i >> 3, ch = i & 7;
                uint32_t so = (uint32_t)((r * SKW + ch * 8) * 2);
                size_t go = (size_t)r * EMBD + gb + ch * 8;
                cp16(stage + O_A + so, Ag + go);
                cp16(stage + O_W + so, Wg + go);
            }
            CP_COMMIT();
            CP_WAIT(1);
        } else {
            CP_WAIT(0);
        }
        __syncthreads();

        const uint32_t st = sb + (ec & 1) * O_STAGE;
        #pragma unroll
        for (int kk = 0; kk < 4; kk++) {
            uint32_t ah[4][4], bh[4][2];
            #pragma unroll
            for (int mt = 0; mt < 4; mt++) {
                uint32_t off = (((arow + mt * 16) * SKW) + kk * 16 + acs) * 2;
                ldm4(ah[mt][0], ah[mt][1], ah[mt][2], ah[mt][3], st + O_A + off);
            }
            #pragma unroll
            for (int p = 0; p < 2; p++) {
                uint32_t off = (((brow + p * 16) * SKW) + kk * 16 + bcs) * 2;
                ldm4(bh[2 * p][0], bh[2 * p][1], bh[2 * p + 1][0], bh[2 * p + 1][1], st + O_W + off);
            }
            #pragma unroll
            for (int mt = 0; mt < 4; mt++)
                #pragma unroll
                for (int nt = 0; nt < 4; nt++)
                    mma_fp16(cf[mt][nt], ah[mt][0], ah[mt][1], ah[mt][2], ah[mt][3], bh[nt][0], bh[nt][1]);
        }
    }

    #pragma unroll
    for (int mt = 0; mt < 4; mt++) {
        int row = m0 + my + mt * 16 + grow;
        #pragma unroll
        for (int nt = 0; nt < 4; nt++) {
            int col = o0 + ox + nt * 8 + qr * 2;
            float b0 = bo[col], b1 = bo[col + 1];
            *(float2*)(out + (size_t)row * EMBD + col) =
                make_float2(cf[mt][nt][0] + b0, cf[mt][nt][1] + b1);
            *(float2*)(out + (size_t)(row + 8) * EMBD + col) =
                make_float2(cf[mt][nt][2] + b0, cf[mt][nt][3] + b1);
        }
    }
}

// ---------------------------------------------------------------------------
extern "C" void kernel_launch(void* const* d_in, const int* in_sizes, int n_in,
                              void* d_out, int out_size)
{
    const float* keys    = (const float*)d_in[0];
    const float* queries = (const float*)d_in[1];
    const int*   mask    = (const int*)d_in[3];
    const float* Wk      = (const float*)d_in[4];
    const float* Wq      = (const float*)d_in[5];
    const float* Wv      = (const float*)d_in[6];
    const float* Wo      = (const float*)d_in[7];
    const float* bo      = (const float*)d_in[8];
    float* out = (float*)d_out;

    cudaFuncSetAttribute(proj_hmma, cudaFuncAttributeMaxDynamicSharedMemorySize, P_TOTAL);
    cudaFuncSetAttribute(attn_hmma, cudaFuncAttributeMaxDynamicSharedMemorySize, A_TOTAL);
    cudaFuncSetAttribute(out_hmma, cudaFuncAttributeMaxDynamicSharedMemorySize, O_TOTAL);

    compact_kernel<<<NBATCH, 256>>>(mask);
    dim3 gp(SEQ / 128, NHEAD, NBATCH);
    proj_hmma<<<gp, 256, P_TOTAL>>>(keys, queries, Wk, Wq, Wv, mask);
    dim3 gc(NBATCH * NHEAD, 4);
    colsum_kernel<<<gc, 256>>>(mask);
    wo_prep<<<(EMBD * EMBD) / 512, 256>>>(Wo);
    dim3 ga(SEQ / 128, NHEAD, NBATCH);
    attn_hmma<<<ga, 128, A_TOTAL>>>();
    dim3 go(EMBD / 128, NBATCH * SEQ / 128);
    out_hmma<<<go, 256, O_TOTAL>>>(bo, out);
}

// round 16
// speedup vs baseline: 2.4733x; 1.0009x over previous
#include <cuda_runtime.h>
#include <cuda_bf16.h>
#include <cuda_fp16.h>
#include <math.h>
#include <stdint.h>

#define NBATCH 2
#define SEQ 2048
#define EMBD 1024
#define NHEAD 16
#define HDIM 64
#define ATT_SCALE 0.03125f
#define SKW 72                    // 16-bit smem row stride: 16B-aligned, ldmatrix conflict-free
#define KSTR (SEQ + 8)            // k/v per-head row stride; row SEQ is the zero pad row
#define CPAD (SEQ + 128)

// scratch
__device__ float g_v[(size_t)NBATCH * NHEAD * SEQ * HDIM];            // fp32 V (colsum source)
__device__ float g_sv4[(size_t)NBATCH * NHEAD * 4 * HDIM];            // partial masked colsums
__device__ float g_mcnt[(size_t)NBATCH * NHEAD * 4];                  // partial mask counts
__device__ int   g_cidx[(size_t)NBATCH * CPAD];                       // compacted unmasked key idx
__device__ int   g_ccnt[NBATCH];                                      // unmasked counts
__device__ __half g_q16[(size_t)NBATCH * NHEAD * SEQ * HDIM];         // pre-scaled by 1/32
__device__ __half g_k16[(size_t)NBATCH * NHEAD * KSTR * HDIM];        // pre-masked (k * mask)
__device__ __half g_v16[(size_t)NBATCH * NHEAD * KSTR * HDIM];
__device__ __half g_a16[(size_t)NBATCH * SEQ * EMBD];                 // attn output, fp16
__device__ __half g_w16[(size_t)EMBD * EMBD];                         // Wo, fp16

// ===================== helpers =====================
__device__ __forceinline__ uint32_t smem_u32(const void* p) {
    uint32_t a;
    asm("{ .reg .u64 t; cvta.to.shared.u64 t, %1; cvt.u32.u64 %0, t; }" : "=r"(a) : "l"(p));
    return a;
}
__device__ __forceinline__ void cp16(uint32_t s, const void* g) {
    asm volatile("cp.async.ca.shared.global [%0], [%1], 16;" :: "r"(s), "l"(g));
}
#define CP_COMMIT() asm volatile("cp.async.commit_group;" ::: "memory")
#define CP_WAIT(n)  asm volatile("cp.async.wait_group %0;" :: "n"(n) : "memory")

__device__ __forceinline__ void mma_fp16(float* c, uint32_t a0, uint32_t a1, uint32_t a2, uint32_t a3,
                                         uint32_t b0, uint32_t b1) {
    asm volatile("mma.sync.aligned.m16n8k16.row.col.f32.f16.f16.f32 "
                 "{%0,%1,%2,%3}, {%4,%5,%6,%7}, {%8,%9}, {%0,%1,%2,%3};"
                 : "+f"(c[0]), "+f"(c[1]), "+f"(c[2]), "+f"(c[3])
                 : "r"(a0), "r"(a1), "r"(a2), "r"(a3), "r"(b0), "r"(b1));
}
__device__ __forceinline__ void ldm4(uint32_t& r0, uint32_t& r1, uint32_t& r2, uint32_t& r3, uint32_t a) {
    asm volatile("ldmatrix.sync.aligned.m8n8.x4.shared.b16 {%0,%1,%2,%3}, [%4];"
                 : "=r"(r0), "=r"(r1), "=r"(r2), "=r"(r3) : "r"(a));
}
__device__ __forceinline__ void ldm4t(uint32_t& r0, uint32_t& r1, uint32_t& r2, uint32_t& r3, uint32_t a) {
    asm volatile("ldmatrix.sync.aligned.m8n8.x4.trans.shared.b16 {%0,%1,%2,%3}, [%4];"
                 : "=r"(r0), "=r"(r1), "=r"(r2), "=r"(r3) : "r"(a));
}
__device__ __forceinline__ uint32_t f2h2(float lo, float hi) {
    uint32_t u;
    asm("cvt.rn.f16x2.f32 %0, %1, %2;" : "=r"(u) : "f"(hi), "f"(lo));
    return u;
}

// ---------------------------------------------------------------------------
// Kernel 0: compact unmasked-key indices (blocks [0,NBATCH)) + Wo->fp16
// (blocks [NBATCH, ...)) fused into one launch.
// ---------------------------------------------------------------------------
__global__ __launch_bounds__(256) void compact_kernel(const int* __restrict__ mask,
                                                      const float* __restrict__ Wo)
{
    const int t = threadIdx.x;
    if (blockIdx.x >= NBATCH) {
        int i = ((blockIdx.x - NBATCH) * 256 + t) * 2;
        float2 wv = *(const float2*)(Wo + i);
        *(uint32_t*)(g_w16 + i) = f2h2(wv.x, wv.y);
        return;
    }
    const int n = blockIdx.x;
    const int* m = mask + n * SEQ;
    int v[8];
    int c = 0;
    #pragma unroll
    for (int j = 0; j < 8; j++) { v[j] = m[t * 8 + j]; c += v[j]; }
    __shared__ int s[256];
    s[t] = c;
    __syncthreads();
    for (int off = 1; off < 256; off <<= 1) {
        int x = (t >= off) ? s[t - off] : 0;
        __syncthreads();
        s[t] += x;
        __syncthreads();
    }
    int pos = s[t] - c;
    #pragma unroll
    for (int j = 0; j < 8; j++)
        if (v[j]) g_cidx[n * CPAD + pos++] = t * 8 + j;
    __syncthreads();
    const int total = s[255];
    if (t == 0) g_ccnt[n] = total;
    const int padded = (total + 127) & ~127;
    for (int i = total + t; i < padded; i += 256)
        g_cidx[n * CPAD + i] = SEQ;                 // points at the zeroed pad row
}

// ---------------------------------------------------------------------------
// Kernel 1: projections, fp16 HMMA. ALL inputs loaded up front, ONE barrier,
// then q / k / v GEMMs back-to-back (v uses q A-fragments from registers).
// ---------------------------------------------------------------------------
#define P_XQ 0
#define P_XK 18432
#define P_WQ 36864
#define P_WK 46080
#define P_WV 55296
#define P_TOTAL 64512

__device__ __forceinline__ void proj_load_x16(char* smc, int base, const float* __restrict__ x, int t) {
    for (int i = t; i < 2048; i += 256) {
        int r = i >> 4, c4 = (i & 15) * 4;
        float4 v = *(const float4*)(x + (size_t)r * EMBD + c4);
        uint32_t so = (uint32_t)((r * SKW + c4) * 2);
        *(uint2*)(smc + base + so) = make_uint2(f2h2(v.x, v.y), f2h2(v.z, v.w));
    }
}
__device__ __forceinline__ void proj_load_w16(char* smc, int base, const float* __restrict__ W, int t) {
    for (int i = t; i < 1024; i += 256) {
        int r = i >> 4, c4 = (i & 15) * 4;
        float4 v = *(const float4*)(W + r * 64 + c4);
        uint32_t so = (uint32_t)((r * SKW + c4) * 2);
        *(uint2*)(smc + base + so) = make_uint2(f2h2(v.x, v.y), f2h2(v.z, v.w));
    }
}
__device__ __forceinline__ void proj_mm16(uint32_t sb, int xbase, int wbase,
                                          int wr, int lane, float (&c)[8][4]) {
    const uint32_t arow = (uint32_t)(wr + (lane & 7) + ((lane & 8) ? 8 : 0));
    const uint32_t acs = (lane & 16) ? 8u : 0u;
    const uint32_t brow = (uint32_t)(((lane & 16) ? 8 : 0) + (lane & 7));
    const uint32_t bcs = (lane & 8) ? 8u : 0u;
    #pragma unroll
    for (int kk = 0; kk < 4; kk++) {
        uint32_t xa[4];
        ldm4(xa[0], xa[1], xa[2], xa[3], sb + xbase + (arow * SKW + kk * 16 + acs) * 2);
        #pragma unroll
        for (int p = 0; p < 4; p++) {
            uint32_t off = ((p * 16 + brow) * SKW + kk * 16 + bcs) * 2;
            uint32_t b0, b1, b2, b3;
            ldm4(b0, b1, b2, b3, sb + wbase + off);
            mma_fp16(c[2 * p],     xa[0], xa[1], xa[2], xa[3], b0, b1);
            mma_fp16(c[2 * p + 1], xa[0], xa[1], xa[2], xa[3], b2, b3);
        }
    }
}
__device__ __forceinline__ void proj_mm16_regA(uint32_t sb, int wbase, int lane,
                                               const uint32_t (&ah)[4][4], float (&c)[8][4]) {
    const uint32_t brow = (uint32_t)(((lane & 16) ? 8 : 0) + (lane & 7));
    const uint32_t bcs = (lane & 8) ? 8u : 0u;
    #pragma unroll
    for (int kk = 0; kk < 4; kk++) {
        #pragma unroll
        for (int p = 0; p < 4; p++) {
            uint32_t off = ((p * 16 + brow) * SKW + kk * 16 + bcs) * 2;
            uint32_t b0, b1, b2, b3;
            ldm4(b0, b1, b2, b3, sb + wbase + off);
            mma_fp16(c[2 * p],     ah[kk][0], ah[kk][1], ah[kk][2], ah[kk][3], b0, b1);
            mma_fp16(c[2 * p + 1], ah[kk][0], ah[kk][1], ah[kk][2], ah[kk][3], b2, b3);
        }
    }
}

__global__ __launch_bounds__(256, 2) void proj_hmma(
    const float* __restrict__ keys, const float* __restrict__ queries,
    const float* __restrict__ Wk, const float* __restrict__ Wq, const float* __restrict__ Wv,
    const int* __restrict__ mask)
{
    extern __shared__ char smc[];
    const uint32_t sb = smem_u32(smc);
    const int t = threadIdx.x, w = t >> 5, lane = t & 31;
    const int grow = lane >> 2, qr = lane & 3;
    const int wr = w * 16;
    const int n = blockIdx.z, h = blockIdx.y, l0 = blockIdx.x * 128;
    const size_t hb = ((size_t)(n * NHEAD + h) * SEQ + l0) * HDIM;
    const size_t hbkv = ((size_t)(n * NHEAD + h) * KSTR + l0) * HDIM;
    const float* xq = queries + ((size_t)n * SEQ + l0) * EMBD + h * HDIM;
    const float* xk = keys    + ((size_t)n * SEQ + l0) * EMBD + h * HDIM;

    // one massive independent load burst, then a single barrier
    proj_load_x16(smc, P_XQ, xq, t);
    proj_load_x16(smc, P_XK, xk, t);
    proj_load_w16(smc, P_WQ, Wq, t);
    proj_load_w16(smc, P_WK, Wk, t);
    proj_load_w16(smc, P_WV, Wv, t);
    __syncthreads();

    // ---- q ----
    float c[8][4];
    #pragma unroll
    for (int i = 0; i < 8; i++)
        #pragma unroll
        for (int j = 0; j < 4; j++) c[i][j] = 0.0f;
    proj_mm16(sb, P_XQ, P_WQ, wr, lane, c);

    uint32_t qh[4][4];
    #pragma unroll
    for (int nt = 0; nt < 8; nt++) {
        qh[nt >> 1][(nt & 1) * 2 + 0] = f2h2(c[nt][0], c[nt][1]);
        qh[nt >> 1][(nt & 1) * 2 + 1] = f2h2(c[nt][2], c[nt][3]);
        int col = nt * 8 + qr * 2;
        *(uint32_t*)(g_q16 + hb + (size_t)(wr + grow) * HDIM + col) =
            f2h2(c[nt][0] * ATT_SCALE, c[nt][1] * ATT_SCALE);
        *(uint32_t*)(g_q16 + hb + (size_t)(wr + grow + 8) * HDIM + col) =
            f2h2(c[nt][2] * ATT_SCALE, c[nt][3] * ATT_SCALE);
    }

    // ---- k (pre-masked) ----
    #pragma unroll
    for (int i = 0; i < 8; i++)
        #pragma unroll
        for (int j = 0; j < 4; j++) c[i][j] = 0.0f;
    proj_mm16(sb, P_XK, P_WK, wr, lane, c);
    {
        const int* mrow = mask + n * SEQ + l0;
        const float mk0 = (float)mrow[wr + grow];
        const float mk1 = (float)mrow[wr + grow + 8];
        #pragma unroll
        for (int nt = 0; nt < 8; nt++) {
            int col = nt * 8 + qr * 2;
            *(uint32_t*)(g_k16 + hbkv + (size_t)(wr + grow) * HDIM + col) =
                f2h2(c[nt][0] * mk0, c[nt][1] * mk0);
            *(uint32_t*)(g_k16 + hbkv + (size_t)(wr + grow + 8) * HDIM + col) =
                f2h2(c[nt][2] * mk1, c[nt][3] * mk1);
        }
    }

    // ---- v = q Wv^T (A from registers) ----
    #pragma unroll
    for (int i = 0; i < 8; i++)
        #pragma unroll
        for (int j = 0; j < 4; j++) c[i][j] = 0.0f;
    proj_mm16_regA(sb, P_WV, lane, qh, c);
    #pragma unroll
    for (int nt = 0; nt < 8; nt++) {
        int col = nt * 8 + qr * 2;
        *(uint32_t*)(g_v16 + hbkv + (size_t)(wr + grow) * HDIM + col) = f2h2(c[nt][0], c[nt][1]);
        *(uint32_t*)(g_v16 + hbkv + (size_t)(wr + grow + 8) * HDIM + col) = f2h2(c[nt][2], c[nt][3]);
        *(float2*)(g_v + hb + (size_t)(wr + grow) * HDIM + col) = make_float2(c[nt][0], c[nt][1]);
        *(float2*)(g_v + hb + (size_t)(wr + grow + 8) * HDIM + col) = make_float2(c[nt][2], c[nt][3]);
    }
}

// ---------------------------------------------------------------------------
// Kernel 1b: masked V column sums + mask counts; also zeroes the k/v pad row
// ---------------------------------------------------------------------------
__global__ __launch_bounds__(256) void colsum_kernel(const int* __restrict__ mask)
{
    const int bid = blockIdx.x, y = blockIdx.y;
    if (y == 0 && threadIdx.x < 64) {
        size_t pz = ((size_t)bid * KSTR + SEQ) * HDIM + threadIdx.x;
        g_k16[pz] = __float2half(0.0f);
        g_v16[pz] = __float2half(0.0f);
    }
    const float* V = g_v + (size_t)bid * SEQ * HDIM + (size_t)y * 512 * HDIM;
    const int* mg = mask + (bid >> 4) * SEQ + y * 512;
    const int d = threadIdx.x & 63, grp = threadIdx.x >> 6;
    float s = 0.0f;
    int scnt = 0;
    const float* vp = V + (size_t)grp * 128 * HDIM + d;
    const int* mp = mg + grp * 128;
    #pragma unroll 8
    for (int cc = 0; cc < 128; cc++) {
        int m = mp[cc];
        s = fmaf((float)m, vp[(size_t)cc * HDIM], s);
        scnt += m;
    }
    __shared__ float red[256];
    __shared__ int redc[4];
    red[threadIdx.x] = s;
    if (d == 0) redc[grp] = scnt;
    __syncthreads();
    if (threadIdx.x < 64)
        g_sv4[((size_t)bid * 4 + y) * HDIM + threadIdx.x] =
            red[threadIdx.x] + red[64 + threadIdx.x] + red[128 + threadIdx.x] + red[192 + threadIdx.x];
    if (threadIdx.x == 0)
        g_mcnt[bid * 4 + y] = (float)(redc[0] + redc[1] + redc[2] + redc[3]);
}

// ---------------------------------------------------------------------------
// Kernel 2: fp16 HMMA flash attention over COMPACTED keys.
// ---------------------------------------------------------------------------
#define A_KS0 0
#define A_KS1 18432
#define A_VS0 36864
#define A_VS1 55296
#define A_SVR 73728
#define A_CNT 73984
#define A_TOTAL 74048

__global__ __launch_bounds__(128, 3) void attn_hmma()
{
    extern __shared__ char smc[];
    const uint32_t sb = smem_u32(smc);
    const int t = threadIdx.x;
    const int w = t >> 5, lane = t & 31;
    const int grow = lane >> 2, qr = lane & 3;
    const int wr = w * 32;
    const int n = blockIdx.z, h = blockIdx.y, q0 = blockIdx.x * 128;
    const __half* Qg = g_q16 + ((size_t)(n * NHEAD + h) * SEQ + q0) * HDIM;
    const __half* Kg = g_k16 + (size_t)(n * NHEAD + h) * KSTR * HDIM;
    const __half* Vg = g_v16 + (size_t)(n * NHEAD + h) * KSTR * HDIM;
    const int* cidx = g_cidx + n * CPAD;
    const int T = (g_ccnt[n] + 127) >> 7;

    for (int i = t; i < 1024; i += 128) {
        int r = i >> 3, ch = i & 7;
        int row = cidx[r];
        uint32_t so = (uint32_t)((r * SKW + ch * 8) * 2);
        cp16(sb + A_KS1 + so, Qg + r * 64 + ch * 8);
        cp16(sb + A_KS0 + so, Kg + (size_t)row * 64 + ch * 8);
        cp16(sb + A_VS0 + so, Vg + (size_t)row * 64 + ch * 8);
    }
    if (t < 64) {
        const float* s4 = g_sv4 + (size_t)(n * NHEAD + h) * 4 * HDIM;
        ((float*)(smc + A_SVR))[t] = s4[t] + s4[64 + t] + s4[128 + t] + s4[192 + t];
    }
    if (t < 4) ((float*)(smc + A_CNT))[t] = g_mcnt[(n * NHEAD + h) * 4 + t];
    CP_COMMIT();
    CP_WAIT(0);
    __syncthreads();

    uint32_t qf0[4][4], qf1[4][4];
    {
        uint32_t qrow = (uint32_t)(wr + (lane & 7) + ((lane & 8) ? 8 : 0));
        uint32_t qcs = (lane & 16) ? 8u : 0u;
        #pragma unroll
        for (int kk = 0; kk < 4; kk++) {
            ldm4(qf0[kk][0], qf0[kk][1], qf0[kk][2], qf0[kk][3],
                 sb + A_KS1 + (qrow * SKW + kk * 16 + qcs) * 2);
            ldm4(qf1[kk][0], qf1[kk][1], qf1[kk][2], qf1[kk][3],
                 sb + A_KS1 + ((qrow + 16) * SKW + kk * 16 + qcs) * 2);
        }
    }
    __syncthreads();

    float of0[9][4], of1[9][4];
    #pragma unroll
    for (int i = 0; i < 9; i++)
        #pragma unroll
        for (int j = 0; j < 4; j++) { of0[i][j] = 0.0f; of1[i][j] = 0.0f; }

    const uint32_t krow_b = (uint32_t)(lane & 7);
    const uint32_t ke = ((uint32_t)(lane >> 3)) * 8;
    const uint32_t vrow_b = (uint32_t)(((lane & 8) ? 8 : 0) + (lane & 7));
    const uint32_t vcs = (lane & 16) ? 8u : 0u;
    const uint32_t bones = (lane < 4) ? 0x3C003C00u : 0u;   // fp16 ones in B column 0

    const __half2 C24 = __float2half2_rn(4.1666667e-2f);
    const __half2 C6  = __float2half2_rn(1.6666667e-1f);
    const __half2 C2  = __float2half2_rn(0.5f);
    const __half2 C1  = __float2half2_rn(1.0f);

    for (int tile = 0; tile < T; tile++) {
        if (tile) __syncthreads();

        if (tile + 1 < T) {
            const int kn = (tile + 1) * 128;
            uint32_t kbn = sb + ((tile + 1) & 1 ? A_KS1 : A_KS0);
            uint32_t vbn = sb + ((tile + 1) & 1 ? A_VS1 : A_VS0);
            for (int i = t; i < 1024; i += 128) {
                int r = i >> 3, ch = i & 7;
                int row = cidx[kn + r];
                uint32_t so = (uint32_t)((r * SKW + ch * 8) * 2);
                cp16(kbn + so, Kg + (size_t)row * 64 + ch * 8);
                cp16(vbn + so, Vg + (size_t)row * 64 + ch * 8);
            }
            CP_COMMIT();
            CP_WAIT(1);
        } else {
            CP_WAIT(0);
        }
        __syncthreads();

        const uint32_t kb = sb + (tile & 1 ? A_KS1 : A_KS0);
        const uint32_t vb = sb + (tile & 1 ? A_VS1 : A_VS0);

        #pragma unroll
        for (int kk = 0; kk < 8; kk++) {
            uint32_t p0[4], p1[4];
            #pragma unroll
            for (int half = 0; half < 2; half++) {
                const int ct = 2 * kk + half;
                float sa0[4] = {0.0f, 0.0f, 0.0f, 0.0f};
                float sa1[4] = {0.0f, 0.0f, 0.0f, 0.0f};
                uint32_t base = kb + ((ct * 8 + krow_b) * SKW + ke) * 2;
                uint32_t b0, b1, b2, b3, b4, b5, b6, b7;
                ldm4(b0, b1, b2, b3, base);
                ldm4(b4, b5, b6, b7, base + 64);
                mma_fp16(sa0, qf0[0][0], qf0[0][1], qf0[0][2], qf0[0][3], b0, b1);
                mma_fp16(sa1, qf1[0][0], qf1[0][1], qf1[0][2], qf1[0][3], b0, b1);
                mma_fp16(sa0, qf0[1][0], qf0[1][1], qf0[1][2], qf0[1][3], b2, b3);
                mma_fp16(sa1, qf1[1][0], qf1[1][1], qf1[1][2], qf1[1][3], b2, b3);
                mma_fp16(sa0, qf0[2][0], qf0[2][1], qf0[2][2], qf0[2][3], b4, b5);
                mma_fp16(sa1, qf1[2][0], qf1[2][1], qf1[2][2], qf1[2][3], b4, b5);
                mma_fp16(sa0, qf0[3][0], qf0[3][1], qf0[3][2], qf0[3][3], b6, b7);
                mma_fp16(sa1, qf1[3][0], qf1[3][1], qf1[3][2], qf1[3][3], b6, b7);

                __half2 x01, x23, y01, y23;
                *(uint32_t*)&x01 = f2h2(sa0[0], sa0[1]);
                *(uint32_t*)&x23 = f2h2(sa0[2], sa0[3]);
                *(uint32_t*)&y01 = f2h2(sa1[0], sa1[1]);
                *(uint32_t*)&y23 = f2h2(sa1[2], sa1[3]);
                __half2 d01 = __hmul2(x01, __hfma2(x01, __hfma2(x01, __hfma2(x01, C24, C6), C2), C1));
                __half2 d23 = __hmul2(x23, __hfma2(x23, __hfma2(x23, __hfma2(x23, C24, C6), C2), C1));
                __half2 e01 = __hmul2(y01, __hfma2(y01, __hfma2(y01, __hfma2(y01, C24, C6), C2), C1));
                __half2 e23 = __hmul2(y23, __hfma2(y23, __hfma2(y23, __hfma2(y23, C24, C6), C2), C1));
                p0[half * 2 + 0] = *(uint32_t*)&d01;
                p0[half * 2 + 1] = *(uint32_t*)&d23;
                p1[half * 2 + 0] = *(uint32_t*)&e01;
                p1[half * 2 + 1] = *(uint32_t*)&e23;
            }

            uint32_t rbase = vb + ((kk * 16 + vrow_b) * SKW + vcs) * 2;
            #pragma unroll
            for (int dg = 0; dg < 4; dg++) {
                uint32_t v0, v1, v2, v3;
                ldm4t(v0, v1, v2, v3, rbase + dg * 32);
                mma_fp16(of0[2 * dg],     p0[0], p0[1], p0[2], p0[3], v0, v1);
                mma_fp16(of1[2 * dg],     p1[0], p1[1], p1[2], p1[3], v0, v1);
                mma_fp16(of0[2 * dg + 1], p0[0], p0[1], p0[2], p0[3], v2, v3);
                mma_fp16(of1[2 * dg + 1], p1[0], p1[1], p1[2], p1[3], v2, v3);
            }
            mma_fp16(of0[8], p0[0], p0[1], p0[2], p0[3], bones, bones);
            mma_fp16(of1[8], p1[0], p1[1], p1[2], p1[3], bones, bones);
        }
    }

    const float* c4 = (const float*)(smc + A_CNT);
    const float cnt = c4[0] + c4[1] + c4[2] + c4[3];
    float sd00 = __shfl_sync(0xffffffffu, of0[8][0], lane & 28);
    float sd01 = __shfl_sync(0xffffffffu, of0[8][2], lane & 28);
    float sd10 = __shfl_sync(0xffffffffu, of1[8][0], lane & 28);
    float sd11 = __shfl_sync(0xffffffffu, of1[8][2], lane & 28);
    const float i00 = 1.0f / (cnt + sd00), i01 = 1.0f / (cnt + sd01);
    const float i10 = 1.0f / (cnt + sd10), i11 = 1.0f / (cnt + sd11);

    const float* sv = (const float*)(smc + A_SVR);
    const size_t rb = ((size_t)n * SEQ + q0 + wr + grow) * EMBD + h * HDIM;
    #pragma unroll
    for (int half = 0; half < 2; half++) {
        const float (*ofp)[4] = half ? of1 : of0;
        const float inv0 = half ? i10 : i00;
        const float inv1 = half ? i11 : i01;
        const size_t base0 = rb + (size_t)(half * 16) * EMBD;
        const size_t base1 = base0 + (size_t)8 * EMBD;
        #pragma unroll
        for (int dt = 0; dt < 8; dt++) {
            int j0 = dt * 8 + qr * 2;
            float o00 = (ofp[dt][0] + sv[j0]) * inv0;
            float o01 = (ofp[dt][1] + sv[j0 + 1]) * inv0;
            float o10 = (ofp[dt][2] + sv[j0]) * inv1;
            float o11 = (ofp[dt][3] + sv[j0 + 1]) * inv1;
            *(uint32_t*)(g_a16 + base0 + j0) = f2h2(o00, o01);
            *(uint32_t*)(g_a16 + base1 + j0) = f2h2(o10, o11);
        }
    }
}

// ---------------------------------------------------------------------------
// Kernel 3: out = attn @ Wo^T + bo (single-pass fp16 MMA, 2 CTAs/SM, 1 wave)
// ---------------------------------------------------------------------------
#define O_A 0
#define O_W 18432
#define O_STAGE 36864
#define O_TOTAL (2 * O_STAGE)

__global__ __launch_bounds__(256, 2) void out_hmma(const float* __restrict__ bo, float* __restrict__ out)
{
    extern __shared__ char smc[];
    const uint32_t sb = smem_u32(smc);
    const int t = threadIdx.x;
    const int w = t >> 5, lane = t & 31;
    const int grow = lane >> 2, qr = lane & 3;
    const int o0 = blockIdx.x * 128, m0 = blockIdx.y * 128;
    const int my = (w >> 2) * 64, ox = (w & 3) * 32;

    const __half* Ag = g_a16 + (size_t)m0 * EMBD;
    const __half* Wg = g_w16 + (size_t)o0 * EMBD;

    for (int i = t; i < 1024; i += 256) {
        int r = i >> 3, ch = i & 7;
        uint32_t so = (uint32_t)((r * SKW + ch * 8) * 2);
        size_t go = (size_t)r * EMBD + ch * 8;
        cp16(sb + O_A + so, Ag + go);
        cp16(sb + O_W + so, Wg + go);
    }
    CP_COMMIT();

    float cf[4][4][4];
    #pragma unroll
    for (int i = 0; i < 4; i++)
        #pragma unroll
        for (int j = 0; j < 4; j++)
            #pragma unroll
            for (int k = 0; k < 4; k++) cf[i][j][k] = 0.0f;

    const uint32_t arow = (uint32_t)(my + (lane & 7) + ((lane & 8) ? 8 : 0));
    const uint32_t acs = (lane & 16) ? 8u : 0u;
    const uint32_t brow = (uint32_t)(ox + ((lane & 16) ? 8 : 0) + (lane & 7));
    const uint32_t bcs = (lane & 8) ? 8u : 0u;

    for (int ec = 0; ec < 16; ec++) {
        if (ec) __syncthreads();

        if (ec < 15) {
            uint32_t stage = sb + ((ec + 1) & 1) * O_STAGE;
            size_t gb = (size_t)(ec + 1) * 64;
            for (int i = t; i < 1024; i += 256) {
                int r = i >> 3, ch = i & 7;
                uint32_t so = (uint32_t)((r * SKW + ch * 8) * 2);
                size_t go = (size_t)r * EMBD + gb + ch * 8;
                cp16(stage + O_A + so, Ag + go);
                cp16(stage + O_W + so, Wg + go);
            }
            CP_COMMIT();
            CP_WAIT(1);
        } else {
            CP_WAIT(0);
        }
        __syncthreads();

        const uint32_t st = sb + (ec & 1) * O_STAGE;
        #pragma unroll
        for (int kk = 0; kk < 4; kk++) {
            uint32_t ah[4][4], bh[4][2];
            #pragma unroll
            for (int mt = 0; mt < 4; mt++) {
                uint32_t off = (((arow + mt * 16) * SKW) + kk * 16 + acs) * 2;
                ldm4(ah[mt][0], ah[mt][1], ah[mt][2], ah[mt][3], st + O_A + off);
            }
            #pragma unroll
            for (int p = 0; p < 2; p++) {
                uint32_t off = (((brow + p * 16) * SKW) + kk * 16 + bcs) * 2;
                ldm4(bh[2 * p][0], bh[2 * p][1], bh[2 * p + 1][0], bh[2 * p + 1][1], st + O_W + off);
            }
            #pragma unroll
            for (int mt = 0; mt < 4; mt++)
                #pragma unroll
                for (int nt = 0; nt < 4; nt++)
                    mma_fp16(cf[mt][nt], ah[mt][0], ah[mt][1], ah[mt][2], ah[mt][3], bh[nt][0], bh[nt][1]);
        }
    }

    #pragma unroll
    for (int mt = 0; mt < 4; mt++) {
        int row = m0 + my + mt * 16 + grow;
        #pragma unroll
        for (int nt = 0; nt < 4; nt++) {
            int col = o0 + ox + nt * 8 + qr * 2;
            float b0 = bo[col], b1 = bo[col + 1];
            *(float2*)(out + (size_t)row * EMBD + col) =
                make_float2(cf[mt][nt][0] + b0, cf[mt][nt][1] + b1);
            *(float2*)(out + (size_t)(row + 8) * EMBD + col) =
                make_float2(cf[mt][nt][2] + b0, cf[mt][nt][3] + b1);
        }
    }
}

// ---------------------------------------------------------------------------
extern "C" void kernel_launch(void* const* d_in, const int* in_sizes, int n_in,
                              void* d_out, int out_size)
{
    const float* keys    = (const float*)d_in[0];
    const float* queries = (const float*)d_in[1];
    const int*   mask    = (const int*)d_in[3];
    const float* Wk      = (const float*)d_in[4];
    const float* Wq      = (const float*)d_in[5];
    const float* Wv      = (const float*)d_in[6];
    const float* Wo      = (const float*)d_in[7];
    const float* bo      = (const float*)d_in[8];
    float* out = (float*)d_out;

    cudaFuncSetAttribute(proj_hmma, cudaFuncAttributeMaxDynamicSharedMemorySize, P_TOTAL);
    cudaFuncSetAttribute(attn_hmma, cudaFuncAttributeMaxDynamicSharedMemorySize, A_TOTAL);
    cudaFuncSetAttribute(out_hmma, cudaFuncAttributeMaxDynamicSharedMemorySize, O_TOTAL);

    compact_kernel<<<NBATCH + (EMBD * EMBD) / 512, 256>>>(mask, Wo);
    dim3 gp(SEQ / 128, NHEAD, NBATCH);
    proj_hmma<<<gp, 256, P_TOTAL>>>(keys, queries, Wk, Wq, Wv, mask);
    dim3 gc(NBATCH * NHEAD, 4);
    colsum_kernel<<<gc, 256>>>(mask);
    dim3 ga(SEQ / 128, NHEAD, NBATCH);
    attn_hmma<<<ga, 128, A_TOTAL>>>();
    dim3 go(EMBD / 128, NBATCH * SEQ / 128);
    out_hmma<<<go, 256, O_TOTAL>>>(bo, out);
}

// round 17
// speedup vs baseline: 2.9074x; 1.1755x over previous
#include <cuda_runtime.h>
#include <cuda_bf16.h>
#include <cuda_fp16.h>
#include <math.h>
#include <stdint.h>

#define NBATCH 2
#define SEQ 2048
#define EMBD 1024
#define NHEAD 16
#define HDIM 64
#define ATT_SCALE 0.03125f
#define SKW 72                    // 16-bit smem row stride: 16B-aligned, ldmatrix conflict-free
#define KSTR (SEQ + 8)            // k/v per-head row stride; row SEQ is the zero pad row
#define CPAD (SEQ + 128)

// scratch
__device__ float g_svp[(size_t)NBATCH * NHEAD * 16 * HDIM];           // per-qtile masked V colsum partials
__device__ int   g_cidx[(size_t)NBATCH * CPAD];                       // compacted unmasked key idx
__device__ int   g_ccnt[NBATCH];                                      // unmasked counts
__device__ __half g_q16[(size_t)NBATCH * NHEAD * SEQ * HDIM];         // pre-scaled by 1/32
__device__ __half g_k16[(size_t)NBATCH * NHEAD * KSTR * HDIM];        // pre-masked (k * mask)
__device__ __half g_v16[(size_t)NBATCH * NHEAD * KSTR * HDIM];
__device__ __half g_a16[(size_t)NBATCH * SEQ * EMBD];                 // attn output, fp16
__device__ __half g_w16[(size_t)EMBD * EMBD];                         // Wo, fp16

// ===================== helpers =====================
__device__ __forceinline__ uint32_t smem_u32(const void* p) {
    uint32_t a;
    asm("{ .reg .u64 t; cvta.to.shared.u64 t, %1; cvt.u32.u64 %0, t; }" : "=r"(a) : "l"(p));
    return a;
}
__device__ __forceinline__ void cp16(uint32_t s, const void* g) {
    asm volatile("cp.async.ca.shared.global [%0], [%1], 16;" :: "r"(s), "l"(g));
}
#define CP_COMMIT() asm volatile("cp.async.commit_group;" ::: "memory")
#define CP_WAIT(n)  asm volatile("cp.async.wait_group %0;" :: "n"(n) : "memory")

__device__ __forceinline__ void mma_fp16(float* c, uint32_t a0, uint32_t a1, uint32_t a2, uint32_t a3,
                                         uint32_t b0, uint32_t b1) {
    asm volatile("mma.sync.aligned.m16n8k16.row.col.f32.f16.f16.f32 "
                 "{%0,%1,%2,%3}, {%4,%5,%6,%7}, {%8,%9}, {%0,%1,%2,%3};"
                 : "+f"(c[0]), "+f"(c[1]), "+f"(c[2]), "+f"(c[3])
                 : "r"(a0), "r"(a1), "r"(a2), "r"(a3), "r"(b0), "r"(b1));
}
__device__ __forceinline__ void ldm4(uint32_t& r0, uint32_t& r1, uint32_t& r2, uint32_t& r3, uint32_t a) {
    asm volatile("ldmatrix.sync.aligned.m8n8.x4.shared.b16 {%0,%1,%2,%3}, [%4];"
                 : "=r"(r0), "=r"(r1), "=r"(r2), "=r"(r3) : "r"(a));
}
__device__ __forceinline__ void ldm4t(uint32_t& r0, uint32_t& r1, uint32_t& r2, uint32_t& r3, uint32_t a) {
    asm volatile("ldmatrix.sync.aligned.m8n8.x4.trans.shared.b16 {%0,%1,%2,%3}, [%4];"
                 : "=r"(r0), "=r"(r1), "=r"(r2), "=r"(r3) : "r"(a));
}
__device__ __forceinline__ uint32_t f2h2(float lo, float hi) {
    uint32_t u;
    asm("cvt.rn.f16x2.f32 %0, %1, %2;" : "=r"(u) : "f"(hi), "f"(lo));
    return u;
}

// ---------------------------------------------------------------------------
// Kernel 0: compact unmasked-key indices + zero pad rows (blocks [0,NBATCH))
// and Wo->fp16 (blocks [NBATCH, ...)) fused.
// ---------------------------------------------------------------------------
__global__ __launch_bounds__(256) void compact_kernel(const int* __restrict__ mask,
                                                      const float* __restrict__ Wo)
{
    const int t = threadIdx.x;
    if (blockIdx.x >= NBATCH) {
        int i = ((blockIdx.x - NBATCH) * 256 + t) * 2;
        float2 wv = *(const float2*)(Wo + i);
        *(uint32_t*)(g_w16 + i) = f2h2(wv.x, wv.y);
        return;
    }
    const int n = blockIdx.x;
    // zero this batch's k/v pad rows (one per head)
    for (int i = t; i < NHEAD * HDIM; i += 256) {
        int hh = i >> 6, d = i & 63;
        size_t pz = ((size_t)(n * NHEAD + hh) * KSTR + SEQ) * HDIM + d;
        g_k16[pz] = __float2half(0.0f);
        g_v16[pz] = __float2half(0.0f);
    }
    const int* m = mask + n * SEQ;
    int v[8];
    int c = 0;
    #pragma unroll
    for (int j = 0; j < 8; j++) { v[j] = m[t * 8 + j]; c += v[j]; }
    __shared__ int s[256];
    s[t] = c;
    __syncthreads();
    for (int off = 1; off < 256; off <<= 1) {
        int x = (t >= off) ? s[t - off] : 0;
        __syncthreads();
        s[t] += x;
        __syncthreads();
    }
    int pos = s[t] - c;
    #pragma unroll
    for (int j = 0; j < 8; j++)
        if (v[j]) g_cidx[n * CPAD + pos++] = t * 8 + j;
    __syncthreads();
    const int total = s[255];
    if (t == 0) g_ccnt[n] = total;
    const int padded = (total + 127) & ~127;
    for (int i = total + t; i < padded; i += 256)
        g_cidx[n * CPAD + i] = SEQ;                 // points at the zeroed pad row
}

// ---------------------------------------------------------------------------
// Kernel 1: projections, fp16 HMMA; also emits this block's masked V colsum
// partial (fp32, deterministic shfl+smem tree) -> no separate colsum kernel.
// ---------------------------------------------------------------------------
#define P_XQ 0
#define P_XK 18432
#define P_WQ 36864
#define P_WK 46080
#define P_WV 55296
#define P_TOTAL 64512

__device__ __forceinline__ void proj_load_x16(char* smc, int base, const float* __restrict__ x, int t) {
    for (int i = t; i < 2048; i += 256) {
        int r = i >> 4, c4 = (i & 15) * 4;
        float4 v = *(const float4*)(x + (size_t)r * EMBD + c4);
        uint32_t so = (uint32_t)((r * SKW + c4) * 2);
        *(uint2*)(smc + base + so) = make_uint2(f2h2(v.x, v.y), f2h2(v.z, v.w));
    }
}
__device__ __forceinline__ void proj_load_w16(char* smc, int base, const float* __restrict__ W, int t) {
    for (int i = t; i < 1024; i += 256) {
        int r = i >> 4, c4 = (i & 15) * 4;
        float4 v = *(const float4*)(W + r * 64 + c4);
        uint32_t so = (uint32_t)((r * SKW + c4) * 2);
        *(uint2*)(smc + base + so) = make_uint2(f2h2(v.x, v.y), f2h2(v.z, v.w));
    }
}
__device__ __forceinline__ void proj_mm16(uint32_t sb, int xbase, int wbase,
                                          int wr, int lane, float (&c)[8][4]) {
    const uint32_t arow = (uint32_t)(wr + (lane & 7) + ((lane & 8) ? 8 : 0));
    const uint32_t acs = (lane & 16) ? 8u : 0u;
    const uint32_t brow = (uint32_t)(((lane & 16) ? 8 : 0) + (lane & 7));
    const uint32_t bcs = (lane & 8) ? 8u : 0u;
    #pragma unroll
    for (int kk = 0; kk < 4; kk++) {
        uint32_t xa[4];
        ldm4(xa[0], xa[1], xa[2], xa[3], sb + xbase + (arow * SKW + kk * 16 + acs) * 2);
        #pragma unroll
        for (int p = 0; p < 4; p++) {
            uint32_t off = ((p * 16 + brow) * SKW + kk * 16 + bcs) * 2;
            uint32_t b0, b1, b2, b3;
            ldm4(b0, b1, b2, b3, sb + wbase + off);
            mma_fp16(c[2 * p],     xa[0], xa[1], xa[2], xa[3], b0, b1);
            mma_fp16(c[2 * p + 1], xa[0], xa[1], xa[2], xa[3], b2, b3);
        }
    }
}
__device__ __forceinline__ void proj_mm16_regA(uint32_t sb, int wbase, int lane,
                                               const uint32_t (&ah)[4][4], float (&c)[8][4]) {
    const uint32_t brow = (uint32_t)(((lane & 16) ? 8 : 0) + (lane & 7));
    const uint32_t bcs = (lane & 8) ? 8u : 0u;
    #pragma unroll
    for (int kk = 0; kk < 4; kk++) {
        #pragma unroll
        for (int p = 0; p < 4; p++) {
            uint32_t off = ((p * 16 + brow) * SKW + kk * 16 + bcs) * 2;
            uint32_t b0, b1, b2, b3;
            ldm4(b0, b1, b2, b3, sb + wbase + off);
            mma_fp16(c[2 * p],     ah[kk][0], ah[kk][1], ah[kk][2], ah[kk][3], b0, b1);
            mma_fp16(c[2 * p + 1], ah[kk][0], ah[kk][1], ah[kk][2], ah[kk][3], b2, b3);
        }
    }
}

__global__ __launch_bounds__(256, 2) void proj_hmma(
    const float* __restrict__ keys, const float* __restrict__ queries,
    const float* __restrict__ Wk, const float* __restrict__ Wq, const float* __restrict__ Wv,
    const int* __restrict__ mask)
{
    extern __shared__ char smc[];
    const uint32_t sb = smem_u32(smc);
    const int t = threadIdx.x, w = t >> 5, lane = t & 31;
    const int grow = lane >> 2, qr = lane & 3;
    const int wr = w * 16;
    const int n = blockIdx.z, h = blockIdx.y, l0 = blockIdx.x * 128;
    const size_t hb = ((size_t)(n * NHEAD + h) * SEQ + l0) * HDIM;
    const size_t hbkv = ((size_t)(n * NHEAD + h) * KSTR + l0) * HDIM;
    const float* xq = queries + ((size_t)n * SEQ + l0) * EMBD + h * HDIM;
    const float* xk = keys    + ((size_t)n * SEQ + l0) * EMBD + h * HDIM;

    proj_load_x16(smc, P_XQ, xq, t);
    proj_load_x16(smc, P_XK, xk, t);
    proj_load_w16(smc, P_WQ, Wq, t);
    proj_load_w16(smc, P_WK, Wk, t);
    proj_load_w16(smc, P_WV, Wv, t);
    __syncthreads();

    // ---- q ----
    float c[8][4];
    #pragma unroll
    for (int i = 0; i < 8; i++)
        #pragma unroll
        for (int j = 0; j < 4; j++) c[i][j] = 0.0f;
    proj_mm16(sb, P_XQ, P_WQ, wr, lane, c);

    uint32_t qh[4][4];
    #pragma unroll
    for (int nt = 0; nt < 8; nt++) {
        qh[nt >> 1][(nt & 1) * 2 + 0] = f2h2(c[nt][0], c[nt][1]);
        qh[nt >> 1][(nt & 1) * 2 + 1] = f2h2(c[nt][2], c[nt][3]);
        int col = nt * 8 + qr * 2;
        *(uint32_t*)(g_q16 + hb + (size_t)(wr + grow) * HDIM + col) =
            f2h2(c[nt][0] * ATT_SCALE, c[nt][1] * ATT_SCALE);
        *(uint32_t*)(g_q16 + hb + (size_t)(wr + grow + 8) * HDIM + col) =
            f2h2(c[nt][2] * ATT_SCALE, c[nt][3] * ATT_SCALE);
    }

    // ---- k (pre-masked) ----
    #pragma unroll
    for (int i = 0; i < 8; i++)
        #pragma unroll
        for (int j = 0; j < 4; j++) c[i][j] = 0.0f;
    proj_mm16(sb, P_XK, P_WK, wr, lane, c);
    const int* mrow = mask + n * SEQ + l0;
    const float mk0 = (float)mrow[wr + grow];
    const float mk1 = (float)mrow[wr + grow + 8];
    #pragma unroll
    for (int nt = 0; nt < 8; nt++) {
        int col = nt * 8 + qr * 2;
        *(uint32_t*)(g_k16 + hbkv + (size_t)(wr + grow) * HDIM + col) =
            f2h2(c[nt][0] * mk0, c[nt][1] * mk0);
        *(uint32_t*)(g_k16 + hbkv + (size_t)(wr + grow + 8) * HDIM + col) =
            f2h2(c[nt][2] * mk1, c[nt][3] * mk1);
    }

    // ---- v = q Wv^T (A from registers) ----
    #pragma unroll
    for (int i = 0; i < 8; i++)
        #pragma unroll
        for (int j = 0; j < 4; j++) c[i][j] = 0.0f;
    proj_mm16_regA(sb, P_WV, lane, qh, c);
    #pragma unroll
    for (int nt = 0; nt < 8; nt++) {
        int col = nt * 8 + qr * 2;
        *(uint32_t*)(g_v16 + hbkv + (size_t)(wr + grow) * HDIM + col) = f2h2(c[nt][0], c[nt][1]);
        *(uint32_t*)(g_v16 + hbkv + (size_t)(wr + grow + 8) * HDIM + col) = f2h2(c[nt][2], c[nt][3]);
    }

    // ---- masked V colsum partial for this 128-row tile (fp32, fixed order) ----
    float sp[16];
    #pragma unroll
    for (int nt = 0; nt < 8; nt++) {
        sp[2 * nt]     = mk0 * c[nt][0] + mk1 * c[nt][2];
        sp[2 * nt + 1] = mk0 * c[nt][1] + mk1 * c[nt][3];
    }
    #pragma unroll
    for (int i = 0; i < 16; i++) {
        sp[i] += __shfl_xor_sync(0xffffffffu, sp[i], 4);
        sp[i] += __shfl_xor_sync(0xffffffffu, sp[i], 8);
        sp[i] += __shfl_xor_sync(0xffffffffu, sp[i], 16);
    }
    __syncthreads();                                 // all smem reads (MMA) complete
    float* red = (float*)smc;                        // [8 warps][64 cols]
    if (grow == 0) {
        #pragma unroll
        for (int nt = 0; nt < 8; nt++) {
            red[w * 64 + nt * 8 + qr * 2]     = sp[2 * nt];
            red[w * 64 + nt * 8 + qr * 2 + 1] = sp[2 * nt + 1];
        }
    }
    __syncthreads();
    if (t < 64) {
        float s = 0.0f;
        #pragma unroll
        for (int ww = 0; ww < 8; ww++) s += red[ww * 64 + t];
        g_svp[(((size_t)(n * NHEAD + h)) * 16 + blockIdx.x) * HDIM + t] = s;
    }
}

// ---------------------------------------------------------------------------
// Kernel 2: fp16 HMMA flash attention over COMPACTED keys.
// ---------------------------------------------------------------------------
#define A_KS0 0
#define A_KS1 18432
#define A_VS0 36864
#define A_VS1 55296
#define A_SVR 73728
#define A_TOTAL 73984

__global__ __launch_bounds__(128, 3) void attn_hmma()
{
    extern __shared__ char smc[];
    const uint32_t sb = smem_u32(smc);
    const int t = threadIdx.x;
    const int w = t >> 5, lane = t & 31;
    const int grow = lane >> 2, qr = lane & 3;
    const int wr = w * 32;
    const int n = blockIdx.z, h = blockIdx.y, q0 = blockIdx.x * 128;
    const __half* Qg = g_q16 + ((size_t)(n * NHEAD + h) * SEQ + q0) * HDIM;
    const __half* Kg = g_k16 + (size_t)(n * NHEAD + h) * KSTR * HDIM;
    const __half* Vg = g_v16 + (size_t)(n * NHEAD + h) * KSTR * HDIM;
    const int* cidx = g_cidx + n * CPAD;
    const int ccnt = g_ccnt[n];
    const int T = (ccnt + 127) >> 7;

    for (int i = t; i < 1024; i += 128) {
        int r = i >> 3, ch = i & 7;
        int row = cidx[r];
        uint32_t so = (uint32_t)((r * SKW + ch * 8) * 2);
        cp16(sb + A_KS1 + so, Qg + r * 64 + ch * 8);
        cp16(sb + A_KS0 + so, Kg + (size_t)row * 64 + ch * 8);
        cp16(sb + A_VS0 + so, Vg + (size_t)row * 64 + ch * 8);
    }
    if (t < 64) {
        const float* s16 = g_svp + (size_t)(n * NHEAD + h) * 16 * HDIM;
        float s = 0.0f;
        #pragma unroll
        for (int i = 0; i < 16; i++) s += s16[i * HDIM + t];
        ((float*)(smc + A_SVR))[t] = s;
    }
    CP_COMMIT();
    CP_WAIT(0);
    __syncthreads();

    uint32_t qf0[4][4], qf1[4][4];
    {
        uint32_t qrow = (uint32_t)(wr + (lane & 7) + ((lane & 8) ? 8 : 0));
        uint32_t qcs = (lane & 16) ? 8u : 0u;
        #pragma unroll
        for (int kk = 0; kk < 4; kk++) {
            ldm4(qf0[kk][0], qf0[kk][1], qf0[kk][2], qf0[kk][3],
                 sb + A_KS1 + (qrow * SKW + kk * 16 + qcs) * 2);
            ldm4(qf1[kk][0], qf1[kk][1], qf1[kk][2], qf1[kk][3],
                 sb + A_KS1 + ((qrow + 16) * SKW + kk * 16 + qcs) * 2);
        }
    }
    __syncthreads();

    float of0[9][4], of1[9][4];
    #pragma unroll
    for (int i = 0; i < 9; i++)
        #pragma unroll
        for (int j = 0; j < 4; j++) { of0[i][j] = 0.0f; of1[i][j] = 0.0f; }

    const uint32_t krow_b = (uint32_t)(lane & 7);
    const uint32_t ke = ((uint32_t)(lane >> 3)) * 8;
    const uint32_t vrow_b = (uint32_t)(((lane & 8) ? 8 : 0) + (lane & 7));
    const uint32_t vcs = (lane & 16) ? 8u : 0u;
    const uint32_t bones = (lane < 4) ? 0x3C003C00u : 0u;   // fp16 ones in B column 0

    const __half2 C24 = __float2half2_rn(4.1666667e-2f);
    const __half2 C6  = __float2half2_rn(1.6666667e-1f);
    const __half2 C2  = __float2half2_rn(0.5f);
    const __half2 C1  = __float2half2_rn(1.0f);

    for (int tile = 0; tile < T; tile++) {
        if (tile) __syncthreads();

        if (tile + 1 < T) {
            const int kn = (tile + 1) * 128;
            uint32_t kbn = sb + ((tile + 1) & 1 ? A_KS1 : A_KS0);
            uint32_t vbn = sb + ((tile + 1) & 1 ? A_VS1 : A_VS0);
            for (int i = t; i < 1024; i += 128) {
                int r = i >> 3, ch = i & 7;
                int row = cidx[kn + r];
                uint32_t so = (uint32_t)((r * SKW + ch * 8) * 2);
                cp16(kbn + so, Kg + (size_t)row * 64 + ch * 8);
                cp16(vbn + so, Vg + (size_t)row * 64 + ch * 8);
            }
            CP_COMMIT();
            CP_WAIT(1);
        } else {
            CP_WAIT(0);
        }
        __syncthreads();

        const uint32_t kb = sb + (tile & 1 ? A_KS1 : A_KS0);
        const uint32_t vb = sb + (tile & 1 ? A_VS1 : A_VS0);

        #pragma unroll
        for (int kk = 0; kk < 8; kk++) {
            uint32_t p0[4], p1[4];
            #pragma unroll
            for (int half = 0; half < 2; half++) {
                const int ct = 2 * kk + half;
                float sa0[4] = {0.0f, 0.0f, 0.0f, 0.0f};
                float sa1[4] = {0.0f, 0.0f, 0.0f, 0.0f};
                uint32_t base = kb + ((ct * 8 + krow_b) * SKW + ke) * 2;
                uint32_t b0, b1, b2, b3, b4, b5, b6, b7;
                ldm4(b0, b1, b2, b3, base);
                ldm4(b4, b5, b6, b7, base + 64);
                mma_fp16(sa0, qf0[0][0], qf0[0][1], qf0[0][2], qf0[0][3], b0, b1);
                mma_fp16(sa1, qf1[0][0], qf1[0][1], qf1[0][2], qf1[0][3], b0, b1);
                mma_fp16(sa0, qf0[1][0], qf0[1][1], qf0[1][2], qf0[1][3], b2, b3);
                mma_fp16(sa1, qf1[1][0], qf1[1][1], qf1[1][2], qf1[1][3], b2, b3);
                mma_fp16(sa0, qf0[2][0], qf0[2][1], qf0[2][2], qf0[2][3], b4, b5);
                mma_fp16(sa1, qf1[2][0], qf1[2][1], qf1[2][2], qf1[2][3], b4, b5);
                mma_fp16(sa0, qf0[3][0], qf0[3][1], qf0[3][2], qf0[3][3], b6, b7);
                mma_fp16(sa1, qf1[3][0], qf1[3][1], qf1[3][2], qf1[3][3], b6, b7);

                __half2 x01, x23, y01, y23;
                *(uint32_t*)&x01 = f2h2(sa0[0], sa0[1]);
                *(uint32_t*)&x23 = f2h2(sa0[2], sa0[3]);
                *(uint32_t*)&y01 = f2h2(sa1[0], sa1[1]);
                *(uint32_t*)&y23 = f2h2(sa1[2], sa1[3]);
                __half2 d01 = __hmul2(x01, __hfma2(x01, __hfma2(x01, __hfma2(x01, C24, C6), C2), C1));
                __half2 d23 = __hmul2(x23, __hfma2(x23, __hfma2(x23, __hfma2(x23, C24, C6), C2), C1));
                __half2 e01 = __hmul2(y01, __hfma2(y01, __hfma2(y01, __hfma2(y01, C24, C6), C2), C1));
                __half2 e23 = __hmul2(y23, __hfma2(y23, __hfma2(y23, __hfma2(y23, C24, C6), C2), C1));
                p0[half * 2 + 0] = *(uint32_t*)&d01;
                p0[half * 2 + 1] = *(uint32_t*)&d23;
                p1[half * 2 + 0] = *(uint32_t*)&e01;
                p1[half * 2 + 1] = *(uint32_t*)&e23;
            }

            uint32_t rbase = vb + ((kk * 16 + vrow_b) * SKW + vcs) * 2;
            #pragma unroll
            for (int dg = 0; dg < 4; dg++) {
                uint32_t v0, v1, v2, v3;
                ldm4t(v0, v1, v2, v3, rbase + dg * 32);
                mma_fp16(of0[2 * dg],     p0[0], p0[1], p0[2], p0[3], v0, v1);
                mma_fp16(of1[2 * dg],     p1[0], p1[1], p1[2], p1[3], v0, v1);
                mma_fp16(of0[2 * dg + 1], p0[0], p0[1], p0[2], p0[3], v2, v3);
                mma_fp16(of1[2 * dg + 1], p1[0], p1[1], p1[2], p1[3], v2, v3);
            }
            mma_fp16(of0[8], p0[0], p0[1], p0[2], p0[3], bones, bones);
            mma_fp16(of1[8], p1[0], p1[1], p1[2], p1[3], bones, bones);
        }
    }

    const float cnt = (float)ccnt;
    float sd00 = __shfl_sync(0xffffffffu, of0[8][0], lane & 28);
    float sd01 = __shfl_sync(0xffffffffu, of0[8][2], lane & 28);
    float sd10 = __shfl_sync(0xffffffffu, of1[8][0], lane & 28);
    float sd11 = __shfl_sync(0xffffffffu, of1[8][2], lane & 28);
    const float i00 = 1.0f / (cnt + sd00), i01 = 1.0f / (cnt + sd01);
    const float i10 = 1.0f / (cnt + sd10), i11 = 1.0f / (cnt + sd11);

    const float* sv = (const float*)(smc + A_SVR);
    const size_t rb = ((size_t)n * SEQ + q0 + wr + grow) * EMBD + h * HDIM;
    #pragma unroll
    for (int half = 0; half < 2; half++) {
        const float (*ofp)[4] = half ? of1 : of0;
        const float inv0 = half ? i10 : i00;
        const float inv1 = half ? i11 : i01;
        const size_t base0 = rb + (size_t)(half * 16) * EMBD;
        const size_t base1 = base0 + (size_t)8 * EMBD;
        #pragma unroll
        for (int dt = 0; dt < 8; dt++) {
            int j0 = dt * 8 + qr * 2;
            float o00 = (ofp[dt][0] + sv[j0]) * inv0;
            float o01 = (ofp[dt][1] + sv[j0 + 1]) * inv0;
            float o10 = (ofp[dt][2] + sv[j0]) * inv1;
            float o11 = (ofp[dt][3] + sv[j0 + 1]) * inv1;
            *(uint32_t*)(g_a16 + base0 + j0) = f2h2(o00, o01);
            *(uint32_t*)(g_a16 + base1 + j0) = f2h2(o10, o11);
        }
    }
}

// ---------------------------------------------------------------------------
// Kernel 3: out = attn @ Wo^T + bo (single-pass fp16 MMA, 2 CTAs/SM, 1 wave)
// ---------------------------------------------------------------------------
#define O_A 0
#define O_W 18432
#define O_STAGE 36864
#define O_TOTAL (2 * O_STAGE)

__global__ __launch_bounds__(256, 2) void out_hmma(const float* __restrict__ bo, float* __restrict__ out)
{
    extern __shared__ char smc[];
    const uint32_t sb = smem_u32(smc);
    const int t = threadIdx.x;
    const int w = t >> 5, lane = t & 31;
    const int grow = lane >> 2, qr = lane & 3;
    const int o0 = blockIdx.x * 128, m0 = blockIdx.y * 128;
    const int my = (w >> 2) * 64, ox = (w & 3) * 32;

    const __half* Ag = g_a16 + (size_t)m0 * EMBD;
    const __half* Wg = g_w16 + (size_t)o0 * EMBD;

    for (int i = t; i < 1024; i += 256) {
        int r = i >> 3, ch = i & 7;
        uint32_t so = (uint32_t)((r * SKW + ch * 8) * 2);
        size_t go = (size_t)r * EMBD + ch * 8;
        cp16(sb + O_A + so, Ag + go);
        cp16(sb + O_W + so, Wg + go);
    }
    CP_COMMIT();

    float cf[4][4][4];
    #pragma unroll
    for (int i = 0; i < 4; i++)
        #pragma unroll
        for (int j = 0; j < 4; j++)
            #pragma unroll
            for (int k = 0; k < 4; k++) cf[i][j][k] = 0.0f;

    const uint32_t arow = (uint32_t)(my + (lane & 7) + ((lane & 8) ? 8 : 0));
    const uint32_t acs = (lane & 16) ? 8u : 0u;
    const uint32_t brow = (uint32_t)(ox + ((lane & 16) ? 8 : 0) + (lane & 7));
    const uint32_t bcs = (lane & 8) ? 8u : 0u;

    for (int ec = 0; ec < 16; ec++) {
        if (ec) __syncthreads();

        if (ec < 15) {
            uint32_t stage = sb + ((ec + 1) & 1) * O_STAGE;
            size_t gb = (size_t)(ec + 1) * 64;
            for (int i = t; i < 1024; i += 256) {
                int r = i >> 3, ch = i & 7;
                uint32_t so = (uint32_t)((r * SKW + ch * 8) * 2);
                size_t go = (size_t)r * EMBD + gb + ch * 8;
                cp16(stage + O_A + so, Ag + go);
                cp16(stage + O_W + so, Wg + go);
            }
            CP_COMMIT();
            CP_WAIT(1);
        } else {
            CP_WAIT(0);
        }
        __syncthreads();

        const uint32_t st = sb + (ec & 1) * O_STAGE;
        #pragma unroll
        for (int kk = 0; kk < 4; kk++) {
            uint32_t ah[4][4], bh[4][2];
            #pragma unroll
            for (int mt = 0; mt < 4; mt++) {
                uint32_t off = (((arow + mt * 16) * SKW) + kk * 16 + acs) * 2;
                ldm4(ah[mt][0], ah[mt][1], ah[mt][2], ah[mt][3], st + O_A + off);
            }
            #pragma unroll
            for (int p = 0; p < 2; p++) {
                uint32_t off = (((brow + p * 16) * SKW) + kk * 16 + bcs) * 2;
                ldm4(bh[2 * p][0], bh[2 * p][1], bh[2 * p + 1][0], bh[2 * p + 1][1], st + O_W + off);
            }
            #pragma unroll
            for (int mt = 0; mt < 4; mt++)
                #pragma unroll
                for (int nt = 0; nt < 4; nt++)
                    mma_fp16(cf[mt][nt], ah[mt][0], ah[mt][1], ah[mt][2], ah[mt][3], bh[nt][0], bh[nt][1]);
        }
    }

    #pragma unroll
    for (int mt = 0; mt < 4; mt++) {
        int row = m0 + my + mt * 16 + grow;
        #pragma unroll
        for (int nt = 0; nt < 4; nt++) {
            int col = o0 + ox + nt * 8 + qr * 2;
            float b0 = bo[col], b1 = bo[col + 1];
            *(float2*)(out + (size_t)row * EMBD + col) =
                make_float2(cf[mt][nt][0] + b0, cf[mt][nt][1] + b1);
            *(float2*)(out + (size_t)(row + 8) * EMBD + col) =
                make_float2(cf[mt][nt][2] + b0, cf[mt][nt][3] + b1);
        }
    }
}

// ---------------------------------------------------------------------------
extern "C" void kernel_launch(void* const* d_in, const int* in_sizes, int n_in,
                              void* d_out, int out_size)
{
    const float* keys    = (const float*)d_in[0];
    const float* queries = (const float*)d_in[1];
    const int*   mask    = (const int*)d_in[3];
    const float* Wk      = (const float*)d_in[4];
    const float* Wq      = (const float*)d_in[5];
    const float* Wv      = (const float*)d_in[6];
    const float* Wo      = (const float*)d_in[7];
    const float* bo      = (const float*)d_in[8];
    float* out = (float*)d_out;

    cudaFuncSetAttribute(proj_hmma, cudaFuncAttributeMaxDynamicSharedMemorySize, P_TOTAL);
    cudaFuncSetAttribute(attn_hmma, cudaFuncAttributeMaxDynamicSharedMemorySize, A_TOTAL);
    cudaFuncSetAttribute(out_hmma, cudaFuncAttributeMaxDynamicSharedMemorySize, O_TOTAL);

    compact_kernel<<<NBATCH + (EMBD * EMBD) / 512, 256>>>(mask, Wo);
    dim3 gp(SEQ / 128, NHEAD, NBATCH);
    proj_hmma<<<gp, 256, P_TOTAL>>>(keys, queries, Wk, Wq, Wv, mask);
    dim3 ga(SEQ / 128, NHEAD, NBATCH);
    attn_hmma<<<ga, 128, A_TOTAL>>>();
    dim3 go(EMBD / 128, NBATCH * SEQ / 128);
    out_hmma<<<go, 256, O_TOTAL>>>(bo, out);
}